// round 3
// baseline (speedup 1.0000x reference)
#include <cuda_runtime.h>
#include <cstdint>

#define BATCH 8
#define SEQ   2048
#define CIN   512
#define DH    64
#define COUT  512
#define MROWS (BATCH*SEQ)   // 16384

// scratch (allocation-free rule: __device__ globals)
__device__ float g_Q[(size_t)MROWS * DH];
__device__ float g_K[(size_t)MROWS * DH];
__device__ float g_V[(size_t)MROWS * COUT];

// ---------------------------------------------------------------------------
// Fused QKV projection: Y[M, 640] = X[M,512] @ [Wq(512x64) | Wk(512x64) | Wv(512x512)]
// 128x128 block tile, Ktile=8, 256 threads, 8x8 microtile.
// ---------------------------------------------------------------------------
__global__ __launch_bounds__(256) void qkv_kernel(
    const float* __restrict__ X,
    const float* __restrict__ Wq,
    const float* __restrict__ Wk,
    const float* __restrict__ Wv)
{
    __shared__ float As[8][128];
    __shared__ float Bs[8][128];

    const int tid = threadIdx.x;
    const int tx = tid & 15;
    const int ty = tid >> 4;
    const int m0 = blockIdx.x * 128;
    const int n0 = blockIdx.y * 128;

    // A load mapping: 2 threads per row, 4 consecutive k each
    const int a_row = tid >> 1;
    const int a_k   = (tid & 1) * 4;
    // B load mapping: 32 threads per k-row, 4 consecutive n each
    const int b_k = tid >> 5;
    const int b_n = (tid & 31) * 4;
    const int ng  = n0 + b_n;

    // per-thread constant source pointer for the B float4 (regions never split a
    // 4-aligned group: boundaries 64 and 128 are multiples of 4)
    const float* bsrc;
    int bld;
    if (ng < 64)       { bsrc = Wq + ng;         bld = 64;  }
    else if (ng < 128) { bsrc = Wk + (ng - 64);  bld = 64;  }
    else               { bsrc = Wv + (ng - 128); bld = 512; }

    float acc[8][8];
#pragma unroll
    for (int i = 0; i < 8; i++)
#pragma unroll
        for (int j = 0; j < 8; j++) acc[i][j] = 0.f;

    for (int k0 = 0; k0 < CIN; k0 += 8) {
        float4 av = *reinterpret_cast<const float4*>(
            &X[(size_t)(m0 + a_row) * CIN + k0 + a_k]);
        As[a_k + 0][a_row] = av.x;
        As[a_k + 1][a_row] = av.y;
        As[a_k + 2][a_row] = av.z;
        As[a_k + 3][a_row] = av.w;
        *reinterpret_cast<float4*>(&Bs[b_k][b_n]) =
            *reinterpret_cast<const float4*>(&bsrc[(size_t)(k0 + b_k) * bld]);
        __syncthreads();

#pragma unroll
        for (int kk = 0; kk < 8; kk++) {
            float4 a0 = *reinterpret_cast<const float4*>(&As[kk][ty * 8]);
            float4 a1 = *reinterpret_cast<const float4*>(&As[kk][ty * 8 + 4]);
            float4 b0 = *reinterpret_cast<const float4*>(&Bs[kk][tx * 8]);
            float4 b1 = *reinterpret_cast<const float4*>(&Bs[kk][tx * 8 + 4]);
            float a[8] = {a0.x, a0.y, a0.z, a0.w, a1.x, a1.y, a1.z, a1.w};
            float b[8] = {b0.x, b0.y, b0.z, b0.w, b1.x, b1.y, b1.z, b1.w};
#pragma unroll
            for (int i = 0; i < 8; i++)
#pragma unroll
                for (int j = 0; j < 8; j++)
                    acc[i][j] += a[i] * b[j];
        }
        __syncthreads();
    }

    // epilogue: route columns to Q / K / V scratch
#pragma unroll
    for (int i = 0; i < 8; i++) {
        const int row = m0 + ty * 8 + i;
#pragma unroll
        for (int j = 0; j < 8; j++) {
            const int n = n0 + tx * 8 + j;
            const float v = acc[i][j];
            if (n < 64)       g_Q[(size_t)row * DH + n] = v;
            else if (n < 128) g_K[(size_t)row * DH + (n - 64)] = v;
            else              g_V[(size_t)row * COUT + (n - 128)] = v;
        }
    }
}

// ---------------------------------------------------------------------------
// Flash attention, fp32. One CTA per (batch, 64-query tile), 512 threads.
// Warp w owns output rows w*4..w*4+3 (full-warp shuffle softmax reductions).
// Per thread: 4 rows x 16 cols of O (cols = lane*4 + q*128 + u).
// smem: Qt[64][68] (K-transposed, pre-scaled), Kt[64][68], Ps[64][68], Vs[64][512]
// ---------------------------------------------------------------------------
#define BM 64
#define BN 64
#define QTILES (SEQ / BM)       // 32
#define QT_STRIDE 68
#define SM_QT 0
#define SM_KT (64 * QT_STRIDE)              // 4352
#define SM_PS (2 * 64 * QT_STRIDE)          // 8704
#define SM_VS (3 * 64 * QT_STRIDE)          // 13056
#define SMEM_FLOATS (3 * 64 * QT_STRIDE + 64 * 512)   // 45824
#define SMEM_BYTES  (SMEM_FLOATS * 4)                 // 183296

__global__ __launch_bounds__(512, 1) void attn_kernel(float* __restrict__ out)
{
    extern __shared__ float sm[];
    float* Qt = sm + SM_QT;
    float* Kt = sm + SM_KT;
    float* Ps = sm + SM_PS;
    float* Vs = sm + SM_VS;

    const int tid  = threadIdx.x;
    const int warp = tid >> 5;
    const int lane = tid & 31;
    const int b    = blockIdx.y;
    const int qt   = (int)gridDim.x - 1 - (int)blockIdx.x;  // heavy tiles first
    const int q0   = qt * BM;
    const int r0   = warp * 4;

    // load Q tile transposed into Qt[d][row], pre-scaled by 1/sqrt(64)
#pragma unroll
    for (int j = 0; j < 2; j++) {
        int id4 = tid + j * 512;        // 1024 float4 total
        int r   = id4 >> 4;             // 16 float4 per row
        int d   = (id4 & 15) * 4;
        float4 v = *reinterpret_cast<const float4*>(
            &g_Q[(size_t)(b * SEQ + q0 + r) * DH + d]);
        Qt[(d + 0) * QT_STRIDE + r] = v.x * 0.125f;
        Qt[(d + 1) * QT_STRIDE + r] = v.y * 0.125f;
        Qt[(d + 2) * QT_STRIDE + r] = v.z * 0.125f;
        Qt[(d + 3) * QT_STRIDE + r] = v.w * 0.125f;
    }

    float O[4][16];
#pragma unroll
    for (int i = 0; i < 4; i++)
#pragma unroll
        for (int c = 0; c < 16; c++) O[i][c] = 0.f;
    float m_i[4], l_i[4];
#pragma unroll
    for (int i = 0; i < 4; i++) { m_i[i] = -1e30f; l_i[i] = 0.f; }

    for (int kt = 0; kt <= qt; kt++) {
        const int k0 = kt * BN;
        // load K tile transposed
#pragma unroll
        for (int j = 0; j < 2; j++) {
            int id4 = tid + j * 512;
            int r   = id4 >> 4;
            int d   = (id4 & 15) * 4;
            float4 v = *reinterpret_cast<const float4*>(
                &g_K[(size_t)(b * SEQ + k0 + r) * DH + d]);
            Kt[(d + 0) * QT_STRIDE + r] = v.x;
            Kt[(d + 1) * QT_STRIDE + r] = v.y;
            Kt[(d + 2) * QT_STRIDE + r] = v.z;
            Kt[(d + 3) * QT_STRIDE + r] = v.w;
        }
        // load V tile [64][512]
#pragma unroll
        for (int j = 0; j < 16; j++) {
            int id4 = tid + j * 512;        // 8192 float4
            int kk  = id4 >> 7;             // 128 float4 per row
            int c   = (id4 & 127) * 4;
            *reinterpret_cast<float4*>(&Vs[kk * 512 + c]) =
                *reinterpret_cast<const float4*>(
                    &g_V[(size_t)(b * SEQ + k0 + kk) * COUT + c]);
        }
        __syncthreads();

        // S = Q K^T  (4 rows x 2 cols per thread; cols = lane*2 + j)
        float s00 = 0.f, s01 = 0.f, s10 = 0.f, s11 = 0.f,
              s20 = 0.f, s21 = 0.f, s30 = 0.f, s31 = 0.f;
#pragma unroll 8
        for (int d = 0; d < DH; d++) {
            float4 a  = *reinterpret_cast<const float4*>(&Qt[d * QT_STRIDE + r0]);
            float2 bb = *reinterpret_cast<const float2*>(&Kt[d * QT_STRIDE + lane * 2]);
            s00 += a.x * bb.x; s01 += a.x * bb.y;
            s10 += a.y * bb.x; s11 += a.y * bb.y;
            s20 += a.z * bb.x; s21 += a.z * bb.y;
            s30 += a.w * bb.x; s31 += a.w * bb.y;
        }
        float s[4][2] = {{s00, s01}, {s10, s11}, {s20, s21}, {s30, s31}};

        // causal mask on the diagonal tile (k0 == q0)
        if (kt == qt) {
            const int c0 = lane * 2;
#pragma unroll
            for (int i = 0; i < 4; i++) {
                if (c0     > r0 + i) s[i][0] = -1e30f;
                if (c0 + 1 > r0 + i) s[i][1] = -1e30f;
            }
        }

        // online softmax per row (rows are warp-local)
#pragma unroll
        for (int i = 0; i < 4; i++) {
            float mx = fmaxf(s[i][0], s[i][1]);
#pragma unroll
            for (int off = 16; off > 0; off >>= 1)
                mx = fmaxf(mx, __shfl_xor_sync(0xffffffffu, mx, off));
            float mn    = fmaxf(m_i[i], mx);
            float alpha = __expf(m_i[i] - mn);
            float p0 = __expf(s[i][0] - mn);
            float p1 = __expf(s[i][1] - mn);
            float rs = p0 + p1;
#pragma unroll
            for (int off = 16; off > 0; off >>= 1)
                rs += __shfl_xor_sync(0xffffffffu, rs, off);
            l_i[i] = l_i[i] * alpha + rs;
            m_i[i] = mn;
            Ps[(r0 + i) * QT_STRIDE + lane * 2]     = p0;
            Ps[(r0 + i) * QT_STRIDE + lane * 2 + 1] = p1;
#pragma unroll
            for (int c = 0; c < 16; c++) O[i][c] *= alpha;
        }
        __syncwarp();   // Ps rows are private to this warp

        // O += P @ V  (cols: lane*4 + q*128 + u)
#pragma unroll 4
        for (int k = 0; k < BN; k++) {
            float4 b0 = *reinterpret_cast<const float4*>(&Vs[k * 512 + lane * 4]);
            float4 b1 = *reinterpret_cast<const float4*>(&Vs[k * 512 + lane * 4 + 128]);
            float4 b2 = *reinterpret_cast<const float4*>(&Vs[k * 512 + lane * 4 + 256]);
            float4 b3 = *reinterpret_cast<const float4*>(&Vs[k * 512 + lane * 4 + 384]);
#pragma unroll
            for (int i = 0; i < 4; i++) {
                float p = Ps[(r0 + i) * QT_STRIDE + k];
                O[i][0]  += p * b0.x; O[i][1]  += p * b0.y;
                O[i][2]  += p * b0.z; O[i][3]  += p * b0.w;
                O[i][4]  += p * b1.x; O[i][5]  += p * b1.y;
                O[i][6]  += p * b1.z; O[i][7]  += p * b1.w;
                O[i][8]  += p * b2.x; O[i][9]  += p * b2.y;
                O[i][10] += p * b2.z; O[i][11] += p * b2.w;
                O[i][12] += p * b3.x; O[i][13] += p * b3.y;
                O[i][14] += p * b3.z; O[i][15] += p * b3.w;
            }
        }
        __syncthreads();   // protect Kt/Vs before next tile's loads
    }

    // epilogue: normalize and store
#pragma unroll
    for (int i = 0; i < 4; i++) {
        const float inv = 1.f / l_i[i];
        const size_t base = (size_t)(b * SEQ + q0 + r0 + i) * COUT;
#pragma unroll
        for (int q = 0; q < 4; q++) {
            float4 v;
            v.x = O[i][q * 4 + 0] * inv;
            v.y = O[i][q * 4 + 1] * inv;
            v.z = O[i][q * 4 + 2] * inv;
            v.w = O[i][q * 4 + 3] * inv;
            *reinterpret_cast<float4*>(&out[base + lane * 4 + q * 128]) = v;
        }
    }
}

// ---------------------------------------------------------------------------
extern "C" void kernel_launch(void* const* d_in, const int* in_sizes, int n_in,
                              void* d_out, int out_size)
{
    const float* x  = (const float*)d_in[0];
    const float* Wq = (const float*)d_in[1];
    const float* Wk = (const float*)d_in[2];
    const float* Wv = (const float*)d_in[3];
    float* out = (float*)d_out;

    dim3 g1(MROWS / 128, (64 + 64 + COUT) / 128);   // 128 x 5
    qkv_kernel<<<g1, 256>>>(x, Wq, Wk, Wv);

    cudaFuncSetAttribute(attn_kernel,
                         cudaFuncAttributeMaxDynamicSharedMemorySize, SMEM_BYTES);
    attn_kernel<<<dim3(QTILES, BATCH), 512, SMEM_BYTES>>>(out);
}

// round 6
// speedup vs baseline: 3.1127x; 3.1127x over previous
#include <cuda_runtime.h>
#include <cuda_bf16.h>
#include <cstdint>

#define BATCH 8
#define SEQ   2048
#define CIN   512
#define DH    64
#define COUT  512
#define MROWS (BATCH*SEQ)   // 16384
#define NTOT  640
#define SCALE_Q 0.18033688011112042f   // (1/8) * log2(e)

typedef unsigned short u16;
typedef uint32_t u32;
typedef uint64_t u64;

// ---- scratch (bf16 halves stored as u16) ----
__device__ __align__(16) u16 g_Xh[(size_t)MROWS*CIN];
__device__ __align__(16) u16 g_Xl[(size_t)MROWS*CIN];
__device__ __align__(16) u16 g_Wth[(size_t)NTOT*CIN];
__device__ __align__(16) u16 g_Wtl[(size_t)NTOT*CIN];
__device__ __align__(16) u16 g_Qh[(size_t)MROWS*DH];
__device__ __align__(16) u16 g_Ql[(size_t)MROWS*DH];
__device__ __align__(16) u16 g_Kh[(size_t)MROWS*DH];
__device__ __align__(16) u16 g_Kl[(size_t)MROWS*DH];
__device__ __align__(16) u16 g_Vth[(size_t)BATCH*COUT*SEQ];  // [b][feat][token]
__device__ __align__(16) u16 g_Vtl[(size_t)BATCH*COUT*SEQ];

// ---- helpers ----
__device__ __forceinline__ u32 smem_u32(const void* p){
    u32 a; asm("{ .reg .u64 t; cvta.to.shared.u64 t, %1; cvt.u32.u64 %0, t; }" : "=r"(a) : "l"(p));
    return a;
}
__device__ __forceinline__ void mma16816(float* c, const u32* a, u32 b0, u32 b1){
    asm volatile("mma.sync.aligned.m16n8k16.row.col.f32.bf16.bf16.f32 "
        "{%0,%1,%2,%3}, {%4,%5,%6,%7}, {%8,%9}, {%0,%1,%2,%3};"
        : "+f"(c[0]), "+f"(c[1]), "+f"(c[2]), "+f"(c[3])
        : "r"(a[0]), "r"(a[1]), "r"(a[2]), "r"(a[3]), "r"(b0), "r"(b1));
}
__device__ __forceinline__ void ldm4(u32* r, u32 addr){
    asm volatile("ldmatrix.sync.aligned.m8n8.x4.shared.b16 {%0,%1,%2,%3}, [%4];"
        : "=r"(r[0]), "=r"(r[1]), "=r"(r[2]), "=r"(r[3]) : "r"(addr));
}
// pack two floats -> bf16x2 (lo = first arg)
__device__ __forceinline__ u32 packbf(float lo, float hi){
    u32 d; asm("cvt.rn.bf16x2.f32 %0, %1, %2;" : "=r"(d) : "f"(hi), "f"(lo)); return d;
}
__device__ __forceinline__ u16 f2bf(float x){ return __bfloat16_as_ushort(__float2bfloat16(x)); }
__device__ __forceinline__ float bf2f(u16 u){ return __bfloat162float(__ushort_as_bfloat16(u)); }
__device__ __forceinline__ void split2(float x, u16& h, u16& l){
    h = f2bf(x); l = f2bf(x - bf2f(h));
}
__device__ __forceinline__ float bfhi(float x){ return bf2f(f2bf(x)); }

// A-operand ldmatrix address (row-major 16x16 tile, row stride S bytes)
__device__ __forceinline__ u32 addrA(u32 base, int lane, int S){
    return base + (u32)((lane & 15) * S + (lane >> 4) * 16);
}
// B-operand ldmatrix address from B^T rows ([n][k] row-major, stride S bytes) -> 2 n-tiles
__device__ __forceinline__ u32 addrB(u32 base, int lane, int S){
    int n = ((lane >> 4) << 3) | (lane & 7);
    return base + (u32)(n * S + ((lane >> 3) & 1) * 16);
}

// ---------------------------------------------------------------------------
// split X into bf16 hi/lo
// ---------------------------------------------------------------------------
__global__ __launch_bounds__(256) void k_split_x(const float* __restrict__ X){
    size_t i = (size_t)blockIdx.x * 256 + threadIdx.x;     // float4 index
    float4 v = reinterpret_cast<const float4*>(X)[i];
    u16 h[4], l[4];
    split2(v.x, h[0], l[0]); split2(v.y, h[1], l[1]);
    split2(v.z, h[2], l[2]); split2(v.w, h[3], l[3]);
    uint2 ph, pl;
    ph.x = (u32)h[0] | ((u32)h[1] << 16); ph.y = (u32)h[2] | ((u32)h[3] << 16);
    pl.x = (u32)l[0] | ((u32)l[1] << 16); pl.y = (u32)l[2] | ((u32)l[3] << 16);
    reinterpret_cast<uint2*>(g_Xh)[i] = ph;
    reinterpret_cast<uint2*>(g_Xl)[i] = pl;
}

// ---------------------------------------------------------------------------
// build transposed concatenated weight [640 out][512 in], split bf16 hi/lo
// ---------------------------------------------------------------------------
__global__ __launch_bounds__(256) void k_split_w(const float* __restrict__ Wq,
                                                 const float* __restrict__ Wk,
                                                 const float* __restrict__ Wv){
    int idx = blockIdx.x * 256 + threadIdx.x;   // [0, 640*512)
    int n = idx % NTOT, k = idx / NTOT;
    float v;
    if (n < 64)       v = Wq[k*64 + n];
    else if (n < 128) v = Wk[k*64 + (n-64)];
    else              v = Wv[k*512 + (n-128)];
    u16 h, l; split2(v, h, l);
    g_Wth[(size_t)n*CIN + k] = h;
    g_Wtl[(size_t)n*CIN + k] = l;
}

// ---------------------------------------------------------------------------
// projection GEMM: C[16384,640] = X @ Wt^T  (bf16x3, mma.sync)
// CTA tile 128x128, 256 thr (8 warps 2x4), warp tile 64x32, k-step 64.
// smem stages: Ah,Al,Bh,Bl each [128][72] bf16 (stride 144B)
// ---------------------------------------------------------------------------
#define GS 144                       // row stride bytes
#define G_AH 0
#define G_AL 18432
#define G_BH 36864
#define G_BL 55296
#define G_SMEM 73728

__global__ __launch_bounds__(256) void k_gemm(){
    extern __shared__ unsigned char smem[];
    const u32 sb = smem_u32(smem);
    float* smemT = reinterpret_cast<float*>(smem);
    const int tid = threadIdx.x, lane = tid & 31, w = tid >> 5;
    const int wm = w >> 2, wn = w & 3;
    const int m0 = blockIdx.x * 128, n0 = blockIdx.y * 128;

    float c[4][4][4];
#pragma unroll
    for (int i = 0; i < 4; i++)
#pragma unroll
        for (int j = 0; j < 4; j++)
#pragma unroll
            for (int r = 0; r < 4; r++) c[i][j][r] = 0.f;

    for (int s = 0; s < 8; s++){
        __syncthreads();
        // stage loads: 128 rows x 64 cols bf16 per buffer (8 uint4/row)
#pragma unroll
        for (int it = 0; it < 4; it++){
            int idx = tid + it*256, r = idx >> 3, cc = idx & 7;
            size_t ga = ((size_t)(m0 + r)*CIN + s*64)*2 + cc*16;
            size_t gb = ((size_t)(n0 + r)*CIN + s*64)*2 + cc*16;
            u32 so = (u32)(r*GS + cc*16);
            *reinterpret_cast<uint4*>(smem + G_AH + so) = *reinterpret_cast<const uint4*>((const char*)g_Xh  + ga);
            *reinterpret_cast<uint4*>(smem + G_AL + so) = *reinterpret_cast<const uint4*>((const char*)g_Xl  + ga);
            *reinterpret_cast<uint4*>(smem + G_BH + so) = *reinterpret_cast<const uint4*>((const char*)g_Wth + gb);
            *reinterpret_cast<uint4*>(smem + G_BL + so) = *reinterpret_cast<const uint4*>((const char*)g_Wtl + gb);
        }
        __syncthreads();

#pragma unroll
        for (int kc = 0; kc < 4; kc++){
            u32 ah[4][4], al[4][4];
#pragma unroll
            for (int mt = 0; mt < 4; mt++){
                u32 ro = (u32)((wm*64 + mt*16) * GS + kc*32);
                ldm4(ah[mt], addrA(sb + G_AH + ro, lane, GS));
                ldm4(al[mt], addrA(sb + G_AL + ro, lane, GS));
            }
            u32 bh[2][4], bl[2][4];
#pragma unroll
            for (int np = 0; np < 2; np++){
                u32 ro = (u32)((wn*32 + np*16) * GS + kc*32);
                ldm4(bh[np], addrB(sb + G_BH + ro, lane, GS));
                ldm4(bl[np], addrB(sb + G_BL + ro, lane, GS));
            }
#pragma unroll
            for (int mt = 0; mt < 4; mt++)
#pragma unroll
                for (int np = 0; np < 2; np++)
#pragma unroll
                    for (int hh = 0; hh < 2; hh++){
                        int nt = np*2 + hh;
                        u32 b0 = bh[np][hh*2], b1 = bh[np][hh*2+1];
                        mma16816(c[mt][nt], ah[mt], b0, b1);
                        mma16816(c[mt][nt], al[mt], b0, b1);
                        mma16816(c[mt][nt], ah[mt], bl[np][hh*2], bl[np][hh*2+1]);
                    }
        }
    }
    __syncthreads();

    if (n0 == 0){
        // Q (cols 0..63, scaled) and K (cols 64..127): direct register stores
#pragma unroll
        for (int mt = 0; mt < 4; mt++){
            int row = m0 + wm*64 + mt*16 + (lane >> 2);
#pragma unroll
            for (int nt = 0; nt < 4; nt++){
                int cg = wn*32 + nt*8 + ((lane & 3) << 1);
                bool isQ = (cg < 64);
                float sc = isQ ? SCALE_Q : 1.f;
                int col = isQ ? cg : cg - 64;
#pragma unroll
                for (int hh = 0; hh < 2; hh++){
                    int r = row + hh*8;
                    float v0 = c[mt][nt][hh*2]   * sc;
                    float v1 = c[mt][nt][hh*2+1] * sc;
                    u16 h0,l0,h1,l1; split2(v0,h0,l0); split2(v1,h1,l1);
                    u32 ph = (u32)h0 | ((u32)h1 << 16);
                    u32 pl = (u32)l0 | ((u32)l1 << 16);
                    size_t off = ((size_t)r*DH + col)*2;
                    if (isQ){
                        *reinterpret_cast<u32*>((char*)g_Qh + off) = ph;
                        *reinterpret_cast<u32*>((char*)g_Ql + off) = pl;
                    } else {
                        *reinterpret_cast<u32*>((char*)g_Kh + off) = ph;
                        *reinterpret_cast<u32*>((char*)g_Kl + off) = pl;
                    }
                }
            }
        }
    } else {
        // V: bounce through smem fp32 [128 tok][132], then store [feat][tok] split
#pragma unroll
        for (int mt = 0; mt < 4; mt++){
            int rl = wm*64 + mt*16 + (lane >> 2);
#pragma unroll
            for (int nt = 0; nt < 4; nt++){
                int cl = wn*32 + nt*8 + ((lane & 3) << 1);
                *reinterpret_cast<float2*>(&smemT[rl*132 + cl]) =
                    make_float2(c[mt][nt][0], c[mt][nt][1]);
                *reinterpret_cast<float2*>(&smemT[(rl+8)*132 + cl]) =
                    make_float2(c[mt][nt][2], c[mt][nt][3]);
            }
        }
        __syncthreads();
        const int b = m0 >> 11, t0 = m0 & 2047;
#pragma unroll
        for (int fi = 0; fi < 16; fi++){
            int fl = w*16 + fi;
            int gf = (n0 - 128) + fl;
            float v0 = smemT[(lane*4+0)*132 + fl];
            float v1 = smemT[(lane*4+1)*132 + fl];
            float v2 = smemT[(lane*4+2)*132 + fl];
            float v3 = smemT[(lane*4+3)*132 + fl];
            u16 h0,l0,h1,l1,h2,l2,h3,l3;
            split2(v0,h0,l0); split2(v1,h1,l1); split2(v2,h2,l2); split2(v3,h3,l3);
            uint2 H = make_uint2((u32)h0 | ((u32)h1<<16), (u32)h2 | ((u32)h3<<16));
            uint2 L = make_uint2((u32)l0 | ((u32)l1<<16), (u32)l2 | ((u32)l3<<16));
            size_t off = ((size_t)(b*COUT + gf)*SEQ + t0 + lane*4)*2;
            *reinterpret_cast<uint2*>((char*)g_Vth + off) = H;
            *reinterpret_cast<uint2*>((char*)g_Vtl + off) = L;
        }
    }
}

// ---------------------------------------------------------------------------
// attention: CTA = (128-query tile, 128-feat quarter, batch), 256 thr, 8 warps.
// Warp w owns q-rows w*16..w*16+15 and all 128 feats of its quarter.
// smem: Kh,Kl [64][72]; Vh,Vl [128][72]; Qh,Ql [128][72]   (stride 144B)
// ---------------------------------------------------------------------------
#define A_KH 0
#define A_KL 9216
#define A_VH 18432
#define A_VL 36864
#define A_QH 55296
#define A_QL 73728
#define A_SMEM 92160

__global__ __launch_bounds__(256) void k_attn(float* __restrict__ out){
    extern __shared__ unsigned char smem[];
    const u32 sb = smem_u32(smem);
    const int tid = threadIdx.x, lane = tid & 31, w = tid >> 5;

    const int bi = blockIdx.x;
    const int qt = 15 - (bi >> 5);        // heavy q-tiles first
    const int sub = bi & 31;
    const int b  = sub >> 2;
    const int h0 = (sub & 3) * 128;
    const int q0 = qt * 128;
    const int nkt = 2*qt + 2;

    // load Q tile (128 rows x 64 d, h/l) into smem
#pragma unroll
    for (int it = 0; it < 4; it++){
        int idx = tid + it*256, r = idx >> 3, cc = idx & 7;
        size_t gq = ((size_t)(b*SEQ + q0 + r)*DH)*2 + cc*16;
        u32 so = (u32)(r*GS + cc*16);
        *reinterpret_cast<uint4*>(smem + A_QH + so) = *reinterpret_cast<const uint4*>((const char*)g_Qh + gq);
        *reinterpret_cast<uint4*>(smem + A_QL + so) = *reinterpret_cast<const uint4*>((const char*)g_Ql + gq);
    }
    __syncthreads();

    // extract per-warp Q fragments (kept in regs for whole kernel)
    u32 qh[4][4], ql[4][4];
#pragma unroll
    for (int kc = 0; kc < 4; kc++){
        u32 ro = (u32)((w*16) * GS + kc*32);
        ldm4(qh[kc], addrA(sb + A_QH + ro, lane, GS));
        ldm4(ql[kc], addrA(sb + A_QL + ro, lane, GS));
    }

    float o[16][4];
#pragma unroll
    for (int nt = 0; nt < 16; nt++)
#pragma unroll
        for (int r = 0; r < 4; r++) o[nt][r] = 0.f;
    float l0 = 0.f, l1 = 0.f;
    const int row0 = q0 + w*16 + (lane >> 2);
    const int row1 = row0 + 8;

    for (int kt = 0; kt < nkt; kt++){
        const int k0 = kt * 64;
        __syncthreads();   // protect K/V smem from previous iteration's readers

        // load K tile [64 tok][64 d] and V tile [128 feat][64 tok], h/l
#pragma unroll
        for (int it = 0; it < 2; it++){
            int idx = tid + it*256, r = idx >> 3, cc = idx & 7;
            size_t gk = ((size_t)(b*SEQ + k0 + r)*DH)*2 + cc*16;
            u32 so = (u32)(r*GS + cc*16);
            *reinterpret_cast<uint4*>(smem + A_KH + so) = *reinterpret_cast<const uint4*>((const char*)g_Kh + gk);
            *reinterpret_cast<uint4*>(smem + A_KL + so) = *reinterpret_cast<const uint4*>((const char*)g_Kl + gk);
        }
#pragma unroll
        for (int it = 0; it < 4; it++){
            int idx = tid + it*256, r = idx >> 3, cc = idx & 7;
            size_t gv = ((size_t)(b*COUT + h0 + r)*SEQ + k0)*2 + cc*16;
            u32 so = (u32)(r*GS + cc*16);
            *reinterpret_cast<uint4*>(smem + A_VH + so) = *reinterpret_cast<const uint4*>((const char*)g_Vth + gv);
            *reinterpret_cast<uint4*>(smem + A_VL + so) = *reinterpret_cast<const uint4*>((const char*)g_Vtl + gv);
        }
        __syncthreads();

        // ---- S = Q K^T (bf16x3), 16 rows x 64 keys per warp ----
        float s[8][4];
#pragma unroll
        for (int nt = 0; nt < 8; nt++)
#pragma unroll
            for (int r = 0; r < 4; r++) s[nt][r] = 0.f;

#pragma unroll
        for (int kc = 0; kc < 4; kc++){
#pragma unroll
            for (int np = 0; np < 4; np++){
                u32 ro = (u32)((np*16) * GS + kc*32);
                u32 kh[4], kl[4];
                ldm4(kh, addrB(sb + A_KH + ro, lane, GS));
                ldm4(kl, addrB(sb + A_KL + ro, lane, GS));
#pragma unroll
                for (int hh = 0; hh < 2; hh++){
                    int nt = np*2 + hh;
                    mma16816(s[nt], qh[kc], kh[hh*2], kh[hh*2+1]);
                    mma16816(s[nt], ql[kc], kh[hh*2], kh[hh*2+1]);
                    mma16816(s[nt], qh[kc], kl[hh*2], kl[hh*2+1]);
                }
            }
        }

        // ---- mask + exp2 + rowsum; build P fragments in place ----
        float pv[8][4];
#pragma unroll
        for (int nt = 0; nt < 8; nt++){
            int col = k0 + nt*8 + ((lane & 3) << 1);
            pv[nt][0] = (col     <= row0) ? exp2f(s[nt][0]) : 0.f;
            pv[nt][1] = (col + 1 <= row0) ? exp2f(s[nt][1]) : 0.f;
            pv[nt][2] = (col     <= row1) ? exp2f(s[nt][2]) : 0.f;
            pv[nt][3] = (col + 1 <= row1) ? exp2f(s[nt][3]) : 0.f;
            l0 += pv[nt][0] + pv[nt][1];
            l1 += pv[nt][2] + pv[nt][3];
        }
        u32 pah[4][4], pal[4][4];
#pragma unroll
        for (int kc = 0; kc < 4; kc++){
            const float* e = pv[2*kc];
            const float* f = pv[2*kc+1];
            pah[kc][0] = packbf(bfhi(e[0]), bfhi(e[1]));
            pah[kc][1] = packbf(bfhi(e[2]), bfhi(e[3]));
            pah[kc][2] = packbf(bfhi(f[0]), bfhi(f[1]));
            pah[kc][3] = packbf(bfhi(f[2]), bfhi(f[3]));
            pal[kc][0] = packbf(e[0]-bfhi(e[0]), e[1]-bfhi(e[1]));
            pal[kc][1] = packbf(e[2]-bfhi(e[2]), e[3]-bfhi(e[3]));
            pal[kc][2] = packbf(f[0]-bfhi(f[0]), f[1]-bfhi(f[1]));
            pal[kc][3] = packbf(f[2]-bfhi(f[2]), f[3]-bfhi(f[3]));
        }

        // ---- O += P V (bf16x3), 16 rows x 128 feats per warp ----
#pragma unroll
        for (int kc = 0; kc < 4; kc++){
#pragma unroll
            for (int np = 0; np < 8; np++){
                u32 ro = (u32)((np*16) * GS + kc*32);
                u32 vh[4], vl[4];
                ldm4(vh, addrB(sb + A_VH + ro, lane, GS));
                ldm4(vl, addrB(sb + A_VL + ro, lane, GS));
#pragma unroll
                for (int hh = 0; hh < 2; hh++){
                    int nt = np*2 + hh;
                    mma16816(o[nt], pah[kc], vh[hh*2], vh[hh*2+1]);
                    mma16816(o[nt], pal[kc], vh[hh*2], vh[hh*2+1]);
                    mma16816(o[nt], pah[kc], vl[hh*2], vl[hh*2+1]);
                }
            }
        }
    }

    // row-sum reduce across the 4 lanes of each row group
    l0 += __shfl_xor_sync(0xffffffffu, l0, 1);
    l0 += __shfl_xor_sync(0xffffffffu, l0, 2);
    l1 += __shfl_xor_sync(0xffffffffu, l1, 1);
    l1 += __shfl_xor_sync(0xffffffffu, l1, 2);
    const float inv0 = 1.f / l0, inv1 = 1.f / l1;

    // epilogue
    const size_t ob0 = (size_t)(b*SEQ + row0)*COUT + h0;
    const size_t ob1 = (size_t)(b*SEQ + row1)*COUT + h0;
#pragma unroll
    for (int nt = 0; nt < 16; nt++){
        int cg = nt*8 + ((lane & 3) << 1);
        *reinterpret_cast<float2*>(&out[ob0 + cg]) = make_float2(o[nt][0]*inv0, o[nt][1]*inv0);
        *reinterpret_cast<float2*>(&out[ob1 + cg]) = make_float2(o[nt][2]*inv1, o[nt][3]*inv1);
    }
}

// ---------------------------------------------------------------------------
extern "C" void kernel_launch(void* const* d_in, const int* in_sizes, int n_in,
                              void* d_out, int out_size)
{
    const float* x  = (const float*)d_in[0];
    const float* Wq = (const float*)d_in[1];
    const float* Wk = (const float*)d_in[2];
    const float* Wv = (const float*)d_in[3];
    float* out = (float*)d_out;

    k_split_x<<<(MROWS*CIN/4)/256, 256>>>(x);
    k_split_w<<<(NTOT*CIN)/256, 256>>>(Wq, Wk, Wv);

    cudaFuncSetAttribute(k_gemm, cudaFuncAttributeMaxDynamicSharedMemorySize, G_SMEM);
    k_gemm<<<dim3(128, 5), 256, G_SMEM>>>();

    cudaFuncSetAttribute(k_attn, cudaFuncAttributeMaxDynamicSharedMemorySize, A_SMEM);
    k_attn<<<512, 256, A_SMEM>>>(out);
}

// round 9
// speedup vs baseline: 3.3324x; 1.0706x over previous
#include <cuda_runtime.h>
#include <cuda_bf16.h>
#include <cstdint>

#define BATCH 8
#define SEQ   2048
#define CIN   512
#define DH    64
#define COUT  512
#define MROWS (BATCH*SEQ)   // 16384
#define NTOT  640
#define SCALE_Q 0.18033688011112042f   // (1/8) * log2(e)

typedef unsigned short u16;
typedef uint32_t u32;
typedef uint64_t u64;

// ---- scratch (bf16 halves stored as u16) ----
__device__ __align__(16) u16 g_Xh[(size_t)MROWS*CIN];
__device__ __align__(16) u16 g_Xl[(size_t)MROWS*CIN];
__device__ __align__(16) u16 g_Wth[(size_t)NTOT*CIN];
__device__ __align__(16) u16 g_Wtl[(size_t)NTOT*CIN];
__device__ __align__(16) u16 g_Qh[(size_t)MROWS*DH];
__device__ __align__(16) u16 g_Ql[(size_t)MROWS*DH];
__device__ __align__(16) u16 g_Kh[(size_t)MROWS*DH];
__device__ __align__(16) u16 g_Kl[(size_t)MROWS*DH];
__device__ __align__(16) u16 g_Vth[(size_t)BATCH*COUT*SEQ];  // [b][feat][token]
__device__ __align__(16) u16 g_Vtl[(size_t)BATCH*COUT*SEQ];

// ---- helpers ----
__device__ __forceinline__ u32 smem_u32(const void* p){
    u32 a; asm("{ .reg .u64 t; cvta.to.shared.u64 t, %1; cvt.u32.u64 %0, t; }" : "=r"(a) : "l"(p));
    return a;
}
__device__ __forceinline__ void mma16816(float* c, const u32* a, u32 b0, u32 b1){
    asm volatile("mma.sync.aligned.m16n8k16.row.col.f32.bf16.bf16.f32 "
        "{%0,%1,%2,%3}, {%4,%5,%6,%7}, {%8,%9}, {%0,%1,%2,%3};"
        : "+f"(c[0]), "+f"(c[1]), "+f"(c[2]), "+f"(c[3])
        : "r"(a[0]), "r"(a[1]), "r"(a[2]), "r"(a[3]), "r"(b0), "r"(b1));
}
__device__ __forceinline__ void ldm4(u32* r, u32 addr){
    asm volatile("ldmatrix.sync.aligned.m8n8.x4.shared.b16 {%0,%1,%2,%3}, [%4];"
        : "=r"(r[0]), "=r"(r[1]), "=r"(r[2]), "=r"(r[3]) : "r"(addr));
}
__device__ __forceinline__ u32 packbf(float lo, float hi){
    u32 d; asm("cvt.rn.bf16x2.f32 %0, %1, %2;" : "=r"(d) : "f"(hi), "f"(lo)); return d;
}
__device__ __forceinline__ u16 f2bf(float x){ return __bfloat16_as_ushort(__float2bfloat16(x)); }
__device__ __forceinline__ float bf2f(u16 u){ return __bfloat162float(__ushort_as_bfloat16(u)); }
__device__ __forceinline__ void split2(float x, u16& h, u16& l){
    h = f2bf(x); l = f2bf(x - bf2f(h));
}
__device__ __forceinline__ float bfhi(float x){ return bf2f(f2bf(x)); }

__device__ __forceinline__ void cpa16(u32 dst, const void* src){
    asm volatile("cp.async.cg.shared.global [%0], [%1], 16;" :: "r"(dst), "l"(src));
}
__device__ __forceinline__ void cp_commit(){ asm volatile("cp.async.commit_group;" ::: "memory"); }
__device__ __forceinline__ void cp_wait1(){ asm volatile("cp.async.wait_group 1;" ::: "memory"); }
__device__ __forceinline__ void cp_wait0(){ asm volatile("cp.async.wait_group 0;" ::: "memory"); }

// A-operand ldmatrix address (row-major 16x16 tile, row stride S bytes)
__device__ __forceinline__ u32 addrA(u32 base, int lane, int S){
    return base + (u32)((lane & 15) * S + (lane >> 4) * 16);
}
// B-operand ldmatrix address from B^T rows ([n][k] row-major, stride S bytes)
__device__ __forceinline__ u32 addrB(u32 base, int lane, int S){
    int n = ((lane >> 4) << 3) | (lane & 7);
    return base + (u32)(n * S + ((lane >> 3) & 1) * 16);
}

// ---------------------------------------------------------------------------
__global__ __launch_bounds__(256) void k_split_x(const float* __restrict__ X){
    size_t i = (size_t)blockIdx.x * 256 + threadIdx.x;
    float4 v = reinterpret_cast<const float4*>(X)[i];
    u16 h[4], l[4];
    split2(v.x, h[0], l[0]); split2(v.y, h[1], l[1]);
    split2(v.z, h[2], l[2]); split2(v.w, h[3], l[3]);
    uint2 ph, pl;
    ph.x = (u32)h[0] | ((u32)h[1] << 16); ph.y = (u32)h[2] | ((u32)h[3] << 16);
    pl.x = (u32)l[0] | ((u32)l[1] << 16); pl.y = (u32)l[2] | ((u32)l[3] << 16);
    reinterpret_cast<uint2*>(g_Xh)[i] = ph;
    reinterpret_cast<uint2*>(g_Xl)[i] = pl;
}

__global__ __launch_bounds__(256) void k_split_w(const float* __restrict__ Wq,
                                                 const float* __restrict__ Wk,
                                                 const float* __restrict__ Wv){
    int idx = blockIdx.x * 256 + threadIdx.x;
    int n = idx % NTOT, k = idx / NTOT;
    float v;
    if (n < 64)       v = Wq[k*64 + n];
    else if (n < 128) v = Wk[k*64 + (n-64)];
    else              v = Wv[k*512 + (n-128)];
    u16 h, l; split2(v, h, l);
    g_Wth[(size_t)n*CIN + k] = h;
    g_Wtl[(size_t)n*CIN + k] = l;
}

// ---------------------------------------------------------------------------
// projection GEMM, 2-stage cp.async pipeline.
// stage layout (73728 B): Ah@0 Al@18432 Bh@36864 Bl@55296 ; rows stride 144B
// ---------------------------------------------------------------------------
#define GS 144
#define GST 73728
#define G_SMEM (2*GST)

__global__ __launch_bounds__(256) void k_gemm(){
    extern __shared__ unsigned char smem[];
    const u32 sb = smem_u32(smem);
    float* smemT = reinterpret_cast<float*>(smem);
    const int tid = threadIdx.x, lane = tid & 31, w = tid >> 5;
    const int wm = w >> 2, wn = w & 3;
    const int m0 = blockIdx.x * 128, n0 = blockIdx.y * 128;

    float c[4][4][4];
#pragma unroll
    for (int i = 0; i < 4; i++)
#pragma unroll
        for (int j = 0; j < 4; j++)
#pragma unroll
            for (int r = 0; r < 4; r++) c[i][j][r] = 0.f;

    auto issue = [&](int s, int stg){
        const u32 SB = sb + (u32)stg * GST;
#pragma unroll
        for (int it = 0; it < 4; it++){
            int idx = tid + it*256, r = idx >> 3, cc = idx & 7;
            size_t ga = ((size_t)(m0 + r)*CIN + s*64)*2 + cc*16;
            size_t gb = ((size_t)(n0 + r)*CIN + s*64)*2 + cc*16;
            u32 so = (u32)(r*GS + cc*16);
            cpa16(SB +     0 + so, (const char*)g_Xh  + ga);
            cpa16(SB + 18432 + so, (const char*)g_Xl  + ga);
            cpa16(SB + 36864 + so, (const char*)g_Wth + gb);
            cpa16(SB + 55296 + so, (const char*)g_Wtl + gb);
        }
        cp_commit();
    };

    issue(0, 0);
    for (int s = 0; s < 8; s++){
        if (s + 1 < 8){ issue(s + 1, (s + 1) & 1); cp_wait1(); }
        else          { cp_wait0(); }
        __syncthreads();
        const u32 SB = sb + (u32)(s & 1) * GST;

#pragma unroll
        for (int kc = 0; kc < 4; kc++){
            u32 ah[4][4], al[4][4];
#pragma unroll
            for (int mt = 0; mt < 4; mt++){
                u32 ro = (u32)((wm*64 + mt*16) * GS + kc*32);
                ldm4(ah[mt], addrA(SB +     0 + ro, lane, GS));
                ldm4(al[mt], addrA(SB + 18432 + ro, lane, GS));
            }
            u32 bh[2][4], bl[2][4];
#pragma unroll
            for (int np = 0; np < 2; np++){
                u32 ro = (u32)((wn*32 + np*16) * GS + kc*32);
                ldm4(bh[np], addrB(SB + 36864 + ro, lane, GS));
                ldm4(bl[np], addrB(SB + 55296 + ro, lane, GS));
            }
#pragma unroll
            for (int mt = 0; mt < 4; mt++)
#pragma unroll
                for (int np = 0; np < 2; np++)
#pragma unroll
                    for (int hh = 0; hh < 2; hh++){
                        int nt = np*2 + hh;
                        mma16816(c[mt][nt], ah[mt], bh[np][hh*2], bh[np][hh*2+1]);
                        mma16816(c[mt][nt], al[mt], bh[np][hh*2], bh[np][hh*2+1]);
                        mma16816(c[mt][nt], ah[mt], bl[np][hh*2], bl[np][hh*2+1]);
                    }
        }
        __syncthreads();
    }

    if (n0 == 0){
#pragma unroll
        for (int mt = 0; mt < 4; mt++){
            int row = m0 + wm*64 + mt*16 + (lane >> 2);
#pragma unroll
            for (int nt = 0; nt < 4; nt++){
                int cg = wn*32 + nt*8 + ((lane & 3) << 1);
                bool isQ = (cg < 64);
                float sc = isQ ? SCALE_Q : 1.f;
                int col = isQ ? cg : cg - 64;
#pragma unroll
                for (int hh = 0; hh < 2; hh++){
                    int r = row + hh*8;
                    float v0 = c[mt][nt][hh*2]   * sc;
                    float v1 = c[mt][nt][hh*2+1] * sc;
                    u16 h0,l0,h1,l1; split2(v0,h0,l0); split2(v1,h1,l1);
                    u32 ph = (u32)h0 | ((u32)h1 << 16);
                    u32 pl = (u32)l0 | ((u32)l1 << 16);
                    size_t off = ((size_t)r*DH + col)*2;
                    if (isQ){
                        *reinterpret_cast<u32*>((char*)g_Qh + off) = ph;
                        *reinterpret_cast<u32*>((char*)g_Ql + off) = pl;
                    } else {
                        *reinterpret_cast<u32*>((char*)g_Kh + off) = ph;
                        *reinterpret_cast<u32*>((char*)g_Kl + off) = pl;
                    }
                }
            }
        }
    } else {
        // V: bounce through smem fp32 [128 tok][132], store [feat][tok] split
#pragma unroll
        for (int mt = 0; mt < 4; mt++){
            int rl = wm*64 + mt*16 + (lane >> 2);
#pragma unroll
            for (int nt = 0; nt < 4; nt++){
                int cl = wn*32 + nt*8 + ((lane & 3) << 1);
                *reinterpret_cast<float2*>(&smemT[rl*132 + cl]) =
                    make_float2(c[mt][nt][0], c[mt][nt][1]);
                *reinterpret_cast<float2*>(&smemT[(rl+8)*132 + cl]) =
                    make_float2(c[mt][nt][2], c[mt][nt][3]);
            }
        }
        __syncthreads();
        const int b = m0 >> 11, t0 = m0 & 2047;
#pragma unroll
        for (int fi = 0; fi < 16; fi++){
            int fl = w*16 + fi;
            int gf = (n0 - 128) + fl;
            float v0 = smemT[(lane*4+0)*132 + fl];
            float v1 = smemT[(lane*4+1)*132 + fl];
            float v2 = smemT[(lane*4+2)*132 + fl];
            float v3 = smemT[(lane*4+3)*132 + fl];
            u16 h0,l0,h1,l1,h2,l2,h3,l3;
            split2(v0,h0,l0); split2(v1,h1,l1); split2(v2,h2,l2); split2(v3,h3,l3);
            uint2 H = make_uint2((u32)h0 | ((u32)h1<<16), (u32)h2 | ((u32)h3<<16));
            uint2 L = make_uint2((u32)l0 | ((u32)l1<<16), (u32)l2 | ((u32)l3<<16));
            size_t off = ((size_t)(b*COUT + gf)*SEQ + t0 + lane*4)*2;
            *reinterpret_cast<uint2*>((char*)g_Vth + off) = H;
            *reinterpret_cast<uint2*>((char*)g_Vtl + off) = L;
        }
    }
}

// ---------------------------------------------------------------------------
// attention, 2-stage cp.async pipeline.
// smem: Qh@0 Ql@18432 ; stage s @ 36864+s*55296: Kh@0 Kl@9216 Vh@18432 Vl@36864
// ---------------------------------------------------------------------------
#define A_QH 0
#define A_QL 18432
#define A_ST 36864
#define AST  55296
#define A_SMEM (A_ST + 2*AST)   // 147456

__global__ __launch_bounds__(256) void k_attn(float* __restrict__ out){
    extern __shared__ unsigned char smem[];
    const u32 sb = smem_u32(smem);
    const int tid = threadIdx.x, lane = tid & 31, w = tid >> 5;

    const int bi = blockIdx.x;
    const int qt = 15 - (bi >> 5);        // heavy q-tiles first
    const int sub = bi & 31;
    const int b  = sub >> 2;
    const int h0 = (sub & 3) * 128;
    const int q0 = qt * 128;
    const int nkt = 2*qt + 2;

    auto issue = [&](int kt, int stg){
        const int k0 = kt * 64;
        const u32 SB = sb + A_ST + (u32)stg * AST;
#pragma unroll
        for (int it = 0; it < 2; it++){
            int idx = tid + it*256, r = idx >> 3, cc = idx & 7;
            size_t gk = ((size_t)(b*SEQ + k0 + r)*DH)*2 + cc*16;
            u32 so = (u32)(r*GS + cc*16);
            cpa16(SB +    0 + so, (const char*)g_Kh + gk);
            cpa16(SB + 9216 + so, (const char*)g_Kl + gk);
        }
#pragma unroll
        for (int it = 0; it < 4; it++){
            int idx = tid + it*256, r = idx >> 3, cc = idx & 7;
            size_t gv = ((size_t)(b*COUT + h0 + r)*SEQ + k0)*2 + cc*16;
            u32 so = (u32)(r*GS + cc*16);
            cpa16(SB + 18432 + so, (const char*)g_Vth + gv);
            cpa16(SB + 36864 + so, (const char*)g_Vtl + gv);
        }
        cp_commit();
    };

    issue(0, 0);   // tile 0 in flight before anything else

    // load Q tile (128 rows x 64 d, h/l) into smem
#pragma unroll
    for (int it = 0; it < 4; it++){
        int idx = tid + it*256, r = idx >> 3, cc = idx & 7;
        size_t gq = ((size_t)(b*SEQ + q0 + r)*DH)*2 + cc*16;
        u32 so = (u32)(r*GS + cc*16);
        *reinterpret_cast<uint4*>(smem + A_QH + so) = *reinterpret_cast<const uint4*>((const char*)g_Qh + gq);
        *reinterpret_cast<uint4*>(smem + A_QL + so) = *reinterpret_cast<const uint4*>((const char*)g_Ql + gq);
    }
    __syncthreads();

    u32 qh[4][4], ql[4][4];
#pragma unroll
    for (int kc = 0; kc < 4; kc++){
        u32 ro = (u32)((w*16) * GS + kc*32);
        ldm4(qh[kc], addrA(sb + A_QH + ro, lane, GS));
        ldm4(ql[kc], addrA(sb + A_QL + ro, lane, GS));
    }

    float o[16][4];
#pragma unroll
    for (int nt = 0; nt < 16; nt++)
#pragma unroll
        for (int r = 0; r < 4; r++) o[nt][r] = 0.f;
    float l0 = 0.f, l1 = 0.f;
    const int row0 = q0 + w*16 + (lane >> 2);
    const int row1 = row0 + 8;

    for (int kt = 0; kt < nkt; kt++){
        const int k0 = kt * 64;
        if (kt + 1 < nkt){ issue(kt + 1, (kt + 1) & 1); cp_wait1(); }
        else             { cp_wait0(); }
        __syncthreads();
        const u32 SB = sb + A_ST + (u32)(kt & 1) * AST;

        // ---- S = Q K^T (bf16x3) ----
        float s[8][4];
#pragma unroll
        for (int nt = 0; nt < 8; nt++)
#pragma unroll
            for (int r = 0; r < 4; r++) s[nt][r] = 0.f;

#pragma unroll
        for (int kc = 0; kc < 4; kc++){
#pragma unroll
            for (int np = 0; np < 4; np++){
                u32 ro = (u32)((np*16) * GS + kc*32);
                u32 kh[4], kl[4];
                ldm4(kh, addrB(SB +    0 + ro, lane, GS));
                ldm4(kl, addrB(SB + 9216 + ro, lane, GS));
#pragma unroll
                for (int hh = 0; hh < 2; hh++){
                    int nt = np*2 + hh;
                    mma16816(s[nt], qh[kc], kh[hh*2], kh[hh*2+1]);
                    mma16816(s[nt], ql[kc], kh[hh*2], kh[hh*2+1]);
                    mma16816(s[nt], qh[kc], kl[hh*2], kl[hh*2+1]);
                }
            }
        }

        // ---- exp2 (+mask only on the 2 diagonal tiles) + rowsum ----
        float pv[8][4];
        if (kt < nkt - 2){
#pragma unroll
            for (int nt = 0; nt < 8; nt++){
                pv[nt][0] = exp2f(s[nt][0]); pv[nt][1] = exp2f(s[nt][1]);
                pv[nt][2] = exp2f(s[nt][2]); pv[nt][3] = exp2f(s[nt][3]);
                l0 += pv[nt][0] + pv[nt][1];
                l1 += pv[nt][2] + pv[nt][3];
            }
        } else {
#pragma unroll
            for (int nt = 0; nt < 8; nt++){
                int col = k0 + nt*8 + ((lane & 3) << 1);
                pv[nt][0] = (col     <= row0) ? exp2f(s[nt][0]) : 0.f;
                pv[nt][1] = (col + 1 <= row0) ? exp2f(s[nt][1]) : 0.f;
                pv[nt][2] = (col     <= row1) ? exp2f(s[nt][2]) : 0.f;
                pv[nt][3] = (col + 1 <= row1) ? exp2f(s[nt][3]) : 0.f;
                l0 += pv[nt][0] + pv[nt][1];
                l1 += pv[nt][2] + pv[nt][3];
            }
        }
        u32 pah[4][4], pal[4][4];
#pragma unroll
        for (int kc = 0; kc < 4; kc++){
            const float* e = pv[2*kc];
            const float* f = pv[2*kc+1];
            pah[kc][0] = packbf(bfhi(e[0]), bfhi(e[1]));
            pah[kc][1] = packbf(bfhi(e[2]), bfhi(e[3]));
            pah[kc][2] = packbf(bfhi(f[0]), bfhi(f[1]));
            pah[kc][3] = packbf(bfhi(f[2]), bfhi(f[3]));
            pal[kc][0] = packbf(e[0]-bfhi(e[0]), e[1]-bfhi(e[1]));
            pal[kc][1] = packbf(e[2]-bfhi(e[2]), e[3]-bfhi(e[3]));
            pal[kc][2] = packbf(f[0]-bfhi(f[0]), f[1]-bfhi(f[1]));
            pal[kc][3] = packbf(f[2]-bfhi(f[2]), f[3]-bfhi(f[3]));
        }

        // ---- O += P V (bf16x3) ----
#pragma unroll
        for (int kc = 0; kc < 4; kc++){
#pragma unroll
            for (int np = 0; np < 8; np++){
                u32 ro = (u32)((np*16) * GS + kc*32);
                u32 vh[4], vl[4];
                ldm4(vh, addrB(SB + 18432 + ro, lane, GS));
                ldm4(vl, addrB(SB + 36864 + ro, lane, GS));
#pragma unroll
                for (int hh = 0; hh < 2; hh++){
                    int nt = np*2 + hh;
                    mma16816(o[nt], pah[kc], vh[hh*2], vh[hh*2+1]);
                    mma16816(o[nt], pal[kc], vh[hh*2], vh[hh*2+1]);
                    mma16816(o[nt], pah[kc], vl[hh*2], vl[hh*2+1]);
                }
            }
        }
        __syncthreads();   // all reads of this stage done before it is refilled
    }

    l0 += __shfl_xor_sync(0xffffffffu, l0, 1);
    l0 += __shfl_xor_sync(0xffffffffu, l0, 2);
    l1 += __shfl_xor_sync(0xffffffffu, l1, 1);
    l1 += __shfl_xor_sync(0xffffffffu, l1, 2);
    const float inv0 = 1.f / l0, inv1 = 1.f / l1;

    const size_t ob0 = (size_t)(b*SEQ + row0)*COUT + h0;
    const size_t ob1 = (size_t)(b*SEQ + row1)*COUT + h0;
#pragma unroll
    for (int nt = 0; nt < 16; nt++){
        int cg = nt*8 + ((lane & 3) << 1);
        *reinterpret_cast<float2*>(&out[ob0 + cg]) = make_float2(o[nt][0]*inv0, o[nt][1]*inv0);
        *reinterpret_cast<float2*>(&out[ob1 + cg]) = make_float2(o[nt][2]*inv1, o[nt][3]*inv1);
    }
}

// ---------------------------------------------------------------------------
extern "C" void kernel_launch(void* const* d_in, const int* in_sizes, int n_in,
                              void* d_out, int out_size)
{
    const float* x  = (const float*)d_in[0];
    const float* Wq = (const float*)d_in[1];
    const float* Wk = (const float*)d_in[2];
    const float* Wv = (const float*)d_in[3];
    float* out = (float*)d_out;

    k_split_x<<<(MROWS*CIN/4)/256, 256>>>(x);
    k_split_w<<<(NTOT*CIN)/256, 256>>>(Wq, Wk, Wv);

    cudaFuncSetAttribute(k_gemm, cudaFuncAttributeMaxDynamicSharedMemorySize, G_SMEM);
    k_gemm<<<dim3(128, 5), 256, G_SMEM>>>();

    cudaFuncSetAttribute(k_attn, cudaFuncAttributeMaxDynamicSharedMemorySize, A_SMEM);
    k_attn<<<512, 256, A_SMEM>>>(out);
}

// round 10
// speedup vs baseline: 3.5874x; 1.0765x over previous
#include <cuda_runtime.h>
#include <cuda_bf16.h>
#include <cstdint>

#define BATCH 8
#define SEQ   2048
#define CIN   512
#define DH    64
#define COUT  512
#define MROWS (BATCH*SEQ)   // 16384
#define NTOT  640
#define SCALE_Q 0.18033688011112042f   // (1/8) * log2(e)

typedef unsigned short u16;
typedef uint32_t u32;
typedef uint64_t u64;

// ---- scratch (bf16 halves stored as u16) ----
__device__ __align__(16) u16 g_Xh[(size_t)MROWS*CIN];
__device__ __align__(16) u16 g_Xl[(size_t)MROWS*CIN];
__device__ __align__(16) u16 g_Wth[(size_t)NTOT*CIN];
__device__ __align__(16) u16 g_Wtl[(size_t)NTOT*CIN];
__device__ __align__(16) u16 g_Qh[(size_t)MROWS*DH];
__device__ __align__(16) u16 g_Ql[(size_t)MROWS*DH];
__device__ __align__(16) u16 g_Kh[(size_t)MROWS*DH];
__device__ __align__(16) u16 g_Kl[(size_t)MROWS*DH];
__device__ __align__(16) u16 g_Vth[(size_t)BATCH*COUT*SEQ];  // [b][feat][token]
__device__ __align__(16) u16 g_Vtl[(size_t)BATCH*COUT*SEQ];
__device__ __align__(16) u16 g_Ph[(size_t)MROWS*SEQ];        // P numerators hi
__device__ __align__(16) u16 g_Pl[(size_t)MROWS*SEQ];        // P numerators lo
__device__ float g_lp[(size_t)MROWS*4];                      // per-chunk row sums

// ---- helpers ----
__device__ __forceinline__ u32 smem_u32(const void* p){
    u32 a; asm("{ .reg .u64 t; cvta.to.shared.u64 t, %1; cvt.u32.u64 %0, t; }" : "=r"(a) : "l"(p));
    return a;
}
__device__ __forceinline__ void mma16816(float* c, const u32* a, u32 b0, u32 b1){
    asm volatile("mma.sync.aligned.m16n8k16.row.col.f32.bf16.bf16.f32 "
        "{%0,%1,%2,%3}, {%4,%5,%6,%7}, {%8,%9}, {%0,%1,%2,%3};"
        : "+f"(c[0]), "+f"(c[1]), "+f"(c[2]), "+f"(c[3])
        : "r"(a[0]), "r"(a[1]), "r"(a[2]), "r"(a[3]), "r"(b0), "r"(b1));
}
__device__ __forceinline__ void ldm4(u32* r, u32 addr){
    asm volatile("ldmatrix.sync.aligned.m8n8.x4.shared.b16 {%0,%1,%2,%3}, [%4];"
        : "=r"(r[0]), "=r"(r[1]), "=r"(r[2]), "=r"(r[3]) : "r"(addr));
}
__device__ __forceinline__ u32 packbf(float lo, float hi){
    u32 d; asm("cvt.rn.bf16x2.f32 %0, %1, %2;" : "=r"(d) : "f"(hi), "f"(lo)); return d;
}
__device__ __forceinline__ u16 f2bf(float x){ return __bfloat16_as_ushort(__float2bfloat16(x)); }
__device__ __forceinline__ float bf2f(u16 u){ return __bfloat162float(__ushort_as_bfloat16(u)); }
__device__ __forceinline__ void split2(float x, u16& h, u16& l){
    h = f2bf(x); l = f2bf(x - bf2f(h));
}

__device__ __forceinline__ void cpa16(u32 dst, const void* src){
    asm volatile("cp.async.cg.shared.global [%0], [%1], 16;" :: "r"(dst), "l"(src));
}
__device__ __forceinline__ void cp_commit(){ asm volatile("cp.async.commit_group;" ::: "memory"); }
__device__ __forceinline__ void cp_wait1(){ asm volatile("cp.async.wait_group 1;" ::: "memory"); }
__device__ __forceinline__ void cp_wait0(){ asm volatile("cp.async.wait_group 0;" ::: "memory"); }

// A-operand ldmatrix address (row-major 16x16 tile, row stride S bytes)
__device__ __forceinline__ u32 addrA(u32 base, int lane, int S){
    return base + (u32)((lane & 15) * S + (lane >> 4) * 16);
}
// B-operand ldmatrix address from B^T rows ([n][k] row-major, stride S bytes)
__device__ __forceinline__ u32 addrB(u32 base, int lane, int S){
    int n = ((lane >> 4) << 3) | (lane & 7);
    return base + (u32)(n * S + ((lane >> 3) & 1) * 16);
}

// ---------------------------------------------------------------------------
__global__ __launch_bounds__(256) void k_split_x(const float* __restrict__ X){
    size_t i = (size_t)blockIdx.x * 256 + threadIdx.x;
    float4 v = reinterpret_cast<const float4*>(X)[i];
    u16 h[4], l[4];
    split2(v.x, h[0], l[0]); split2(v.y, h[1], l[1]);
    split2(v.z, h[2], l[2]); split2(v.w, h[3], l[3]);
    uint2 ph, pl;
    ph.x = (u32)h[0] | ((u32)h[1] << 16); ph.y = (u32)h[2] | ((u32)h[3] << 16);
    pl.x = (u32)l[0] | ((u32)l[1] << 16); pl.y = (u32)l[2] | ((u32)l[3] << 16);
    reinterpret_cast<uint2*>(g_Xh)[i] = ph;
    reinterpret_cast<uint2*>(g_Xl)[i] = pl;
}

__global__ __launch_bounds__(256) void k_split_w(const float* __restrict__ Wq,
                                                 const float* __restrict__ Wk,
                                                 const float* __restrict__ Wv){
    int idx = blockIdx.x * 256 + threadIdx.x;
    int n = idx % NTOT, k = idx / NTOT;
    float v;
    if (n < 64)       v = Wq[k*64 + n];
    else if (n < 128) v = Wk[k*64 + (n-64)];
    else              v = Wv[k*512 + (n-128)];
    u16 h, l; split2(v, h, l);
    g_Wth[(size_t)n*CIN + k] = h;
    g_Wtl[(size_t)n*CIN + k] = l;
}

// ---------------------------------------------------------------------------
// projection GEMM, 2-stage cp.async pipeline (unchanged from last passing run)
// ---------------------------------------------------------------------------
#define GS 144
#define GST 73728
#define G_SMEM (2*GST)

__global__ __launch_bounds__(256) void k_gemm(){
    extern __shared__ unsigned char smem[];
    const u32 sb = smem_u32(smem);
    float* smemT = reinterpret_cast<float*>(smem);
    const int tid = threadIdx.x, lane = tid & 31, w = tid >> 5;
    const int wm = w >> 2, wn = w & 3;
    const int m0 = blockIdx.x * 128, n0 = blockIdx.y * 128;

    float c[4][4][4];
#pragma unroll
    for (int i = 0; i < 4; i++)
#pragma unroll
        for (int j = 0; j < 4; j++)
#pragma unroll
            for (int r = 0; r < 4; r++) c[i][j][r] = 0.f;

    auto issue = [&](int s, int stg){
        const u32 SB = sb + (u32)stg * GST;
#pragma unroll
        for (int it = 0; it < 4; it++){
            int idx = tid + it*256, r = idx >> 3, cc = idx & 7;
            size_t ga = ((size_t)(m0 + r)*CIN + s*64)*2 + cc*16;
            size_t gb = ((size_t)(n0 + r)*CIN + s*64)*2 + cc*16;
            u32 so = (u32)(r*GS + cc*16);
            cpa16(SB +     0 + so, (const char*)g_Xh  + ga);
            cpa16(SB + 18432 + so, (const char*)g_Xl  + ga);
            cpa16(SB + 36864 + so, (const char*)g_Wth + gb);
            cpa16(SB + 55296 + so, (const char*)g_Wtl + gb);
        }
        cp_commit();
    };

    issue(0, 0);
    for (int s = 0; s < 8; s++){
        if (s + 1 < 8){ issue(s + 1, (s + 1) & 1); cp_wait1(); }
        else          { cp_wait0(); }
        __syncthreads();
        const u32 SB = sb + (u32)(s & 1) * GST;

#pragma unroll
        for (int kc = 0; kc < 4; kc++){
            u32 ah[4][4], al[4][4];
#pragma unroll
            for (int mt = 0; mt < 4; mt++){
                u32 ro = (u32)((wm*64 + mt*16) * GS + kc*32);
                ldm4(ah[mt], addrA(SB +     0 + ro, lane, GS));
                ldm4(al[mt], addrA(SB + 18432 + ro, lane, GS));
            }
            u32 bh[2][4], bl[2][4];
#pragma unroll
            for (int np = 0; np < 2; np++){
                u32 ro = (u32)((wn*32 + np*16) * GS + kc*32);
                ldm4(bh[np], addrB(SB + 36864 + ro, lane, GS));
                ldm4(bl[np], addrB(SB + 55296 + ro, lane, GS));
            }
#pragma unroll
            for (int mt = 0; mt < 4; mt++)
#pragma unroll
                for (int np = 0; np < 2; np++)
#pragma unroll
                    for (int hh = 0; hh < 2; hh++){
                        int nt = np*2 + hh;
                        mma16816(c[mt][nt], ah[mt], bh[np][hh*2], bh[np][hh*2+1]);
                        mma16816(c[mt][nt], al[mt], bh[np][hh*2], bh[np][hh*2+1]);
                        mma16816(c[mt][nt], ah[mt], bl[np][hh*2], bl[np][hh*2+1]);
                    }
        }
        __syncthreads();
    }

    if (n0 == 0){
#pragma unroll
        for (int mt = 0; mt < 4; mt++){
            int row = m0 + wm*64 + mt*16 + (lane >> 2);
#pragma unroll
            for (int nt = 0; nt < 4; nt++){
                int cg = wn*32 + nt*8 + ((lane & 3) << 1);
                bool isQ = (cg < 64);
                float sc = isQ ? SCALE_Q : 1.f;
                int col = isQ ? cg : cg - 64;
#pragma unroll
                for (int hh = 0; hh < 2; hh++){
                    int r = row + hh*8;
                    float v0 = c[mt][nt][hh*2]   * sc;
                    float v1 = c[mt][nt][hh*2+1] * sc;
                    u16 h0,l0,h1,l1; split2(v0,h0,l0); split2(v1,h1,l1);
                    u32 ph = (u32)h0 | ((u32)h1 << 16);
                    u32 pl = (u32)l0 | ((u32)l1 << 16);
                    size_t off = ((size_t)r*DH + col)*2;
                    if (isQ){
                        *reinterpret_cast<u32*>((char*)g_Qh + off) = ph;
                        *reinterpret_cast<u32*>((char*)g_Ql + off) = pl;
                    } else {
                        *reinterpret_cast<u32*>((char*)g_Kh + off) = ph;
                        *reinterpret_cast<u32*>((char*)g_Kl + off) = pl;
                    }
                }
            }
        }
    } else {
        // V: bounce through smem fp32 [128 tok][132], store [feat][tok] split
#pragma unroll
        for (int mt = 0; mt < 4; mt++){
            int rl = wm*64 + mt*16 + (lane >> 2);
#pragma unroll
            for (int nt = 0; nt < 4; nt++){
                int cl = wn*32 + nt*8 + ((lane & 3) << 1);
                *reinterpret_cast<float2*>(&smemT[rl*132 + cl]) =
                    make_float2(c[mt][nt][0], c[mt][nt][1]);
                *reinterpret_cast<float2*>(&smemT[(rl+8)*132 + cl]) =
                    make_float2(c[mt][nt][2], c[mt][nt][3]);
            }
        }
        __syncthreads();
        const int b = m0 >> 11, t0 = m0 & 2047;
#pragma unroll
        for (int fi = 0; fi < 16; fi++){
            int fl = w*16 + fi;
            int gf = (n0 - 128) + fl;
            float v0 = smemT[(lane*4+0)*132 + fl];
            float v1 = smemT[(lane*4+1)*132 + fl];
            float v2 = smemT[(lane*4+2)*132 + fl];
            float v3 = smemT[(lane*4+3)*132 + fl];
            u16 h0,l0,h1,l1,h2,l2,h3,l3;
            split2(v0,h0,l0); split2(v1,h1,l1); split2(v2,h2,l2); split2(v3,h3,l3);
            uint2 H = make_uint2((u32)h0 | ((u32)h1<<16), (u32)h2 | ((u32)h3<<16));
            uint2 L = make_uint2((u32)l0 | ((u32)l1<<16), (u32)l2 | ((u32)l3<<16));
            size_t off = ((size_t)(b*COUT + gf)*SEQ + t0 + lane*4)*2;
            *reinterpret_cast<uint2*>((char*)g_Vth + off) = H;
            *reinterpret_cast<uint2*>((char*)g_Vtl + off) = L;
        }
    }
}

// ---------------------------------------------------------------------------
// k_qk: S = QK^T (bf16x3) + exp2 + split -> P to global, per-chunk row sums.
// grid 320: (b, qt, 8-tile chunk). 256 thr; warp = 16 q-rows.
// smem: Qh@0 Ql@18432 ; K stages @36864: Kh@0 Kl@9216 per 18432-stage x2
// ---------------------------------------------------------------------------
#define QK_QH 0
#define QK_QL 18432
#define QK_ST 36864
#define QKST  18432
#define QK_SMEM (QK_ST + 2*QKST)   // 73728

__global__ __launch_bounds__(256) void k_qk(){
    extern __shared__ unsigned char smem[];
    const u32 sb = smem_u32(smem);
    const int tid = threadIdx.x, lane = tid & 31, w = tid >> 5;

    // decode (b, qt, chunk); heavy chunks first
    int idx = blockIdx.x;
    const int b = idx / 40;
    int rem = 39 - idx % 40;
    int qt = 0;
    while (rem >= (qt/4 + 1)){ rem -= qt/4 + 1; qt++; }
    const int chunk = rem;
    const int q0 = qt * 128;
    const int nkt = 2*qt + 2;
    const int ktA = chunk * 8;
    const int ktB = (ktA + 8 < nkt) ? ktA + 8 : nkt;

    auto issue = [&](int kt, int stg){
        const int k0 = kt * 64;
        const u32 SB = sb + QK_ST + (u32)stg * QKST;
#pragma unroll
        for (int it = 0; it < 2; it++){
            int i2 = tid + it*256, r = i2 >> 3, cc = i2 & 7;
            size_t gk = ((size_t)(b*SEQ + k0 + r)*DH)*2 + cc*16;
            u32 so = (u32)(r*GS + cc*16);
            cpa16(SB +    0 + so, (const char*)g_Kh + gk);
            cpa16(SB + 9216 + so, (const char*)g_Kl + gk);
        }
        cp_commit();
    };

    issue(ktA, ktA & 1);

    // Q tile (plain loads, once)
#pragma unroll
    for (int it = 0; it < 4; it++){
        int i2 = tid + it*256, r = i2 >> 3, cc = i2 & 7;
        size_t gq = ((size_t)(b*SEQ + q0 + r)*DH)*2 + cc*16;
        u32 so = (u32)(r*GS + cc*16);
        *reinterpret_cast<uint4*>(smem + QK_QH + so) = *reinterpret_cast<const uint4*>((const char*)g_Qh + gq);
        *reinterpret_cast<uint4*>(smem + QK_QL + so) = *reinterpret_cast<const uint4*>((const char*)g_Ql + gq);
    }
    __syncthreads();

    u32 qh[4][4], ql[4][4];
#pragma unroll
    for (int kc = 0; kc < 4; kc++){
        u32 ro = (u32)((w*16) * GS + kc*32);
        ldm4(qh[kc], addrA(sb + QK_QH + ro, lane, GS));
        ldm4(ql[kc], addrA(sb + QK_QL + ro, lane, GS));
    }

    float l0 = 0.f, l1 = 0.f;
    const int row0 = q0 + w*16 + (lane >> 2);
    const int row1 = row0 + 8;
    const size_t pr0 = (size_t)(b*SEQ + row0) * SEQ;
    const size_t pr1 = (size_t)(b*SEQ + row1) * SEQ;

    for (int kt = ktA; kt < ktB; kt++){
        const int k0 = kt * 64;
        if (kt + 1 < ktB){ issue(kt + 1, (kt + 1) & 1); cp_wait1(); }
        else             { cp_wait0(); }
        __syncthreads();
        const u32 SB = sb + QK_ST + (u32)(kt & 1) * QKST;

        float s[8][4];
#pragma unroll
        for (int nt = 0; nt < 8; nt++)
#pragma unroll
            for (int r = 0; r < 4; r++) s[nt][r] = 0.f;

#pragma unroll
        for (int kc = 0; kc < 4; kc++){
#pragma unroll
            for (int np = 0; np < 4; np++){
                u32 ro = (u32)((np*16) * GS + kc*32);
                u32 kh[4], kl[4];
                ldm4(kh, addrB(SB +    0 + ro, lane, GS));
                ldm4(kl, addrB(SB + 9216 + ro, lane, GS));
#pragma unroll
                for (int hh = 0; hh < 2; hh++){
                    int nt = np*2 + hh;
                    mma16816(s[nt], qh[kc], kh[hh*2], kh[hh*2+1]);
                    mma16816(s[nt], ql[kc], kh[hh*2], kh[hh*2+1]);
                    mma16816(s[nt], qh[kc], kl[hh*2], kl[hh*2+1]);
                }
            }
        }

        // exp2 (+mask on diagonal tiles), split and store P
        float pv[8][4];
        if (kt < nkt - 2){
#pragma unroll
            for (int nt = 0; nt < 8; nt++){
                pv[nt][0] = exp2f(s[nt][0]); pv[nt][1] = exp2f(s[nt][1]);
                pv[nt][2] = exp2f(s[nt][2]); pv[nt][3] = exp2f(s[nt][3]);
                l0 += pv[nt][0] + pv[nt][1];
                l1 += pv[nt][2] + pv[nt][3];
            }
        } else {
#pragma unroll
            for (int nt = 0; nt < 8; nt++){
                int col = k0 + nt*8 + ((lane & 3) << 1);
                pv[nt][0] = (col     <= row0) ? exp2f(s[nt][0]) : 0.f;
                pv[nt][1] = (col + 1 <= row0) ? exp2f(s[nt][1]) : 0.f;
                pv[nt][2] = (col     <= row1) ? exp2f(s[nt][2]) : 0.f;
                pv[nt][3] = (col + 1 <= row1) ? exp2f(s[nt][3]) : 0.f;
                l0 += pv[nt][0] + pv[nt][1];
                l1 += pv[nt][2] + pv[nt][3];
            }
        }
#pragma unroll
        for (int nt = 0; nt < 8; nt++){
            int col = k0 + nt*8 + ((lane & 3) << 1);
            u32 h0 = packbf(pv[nt][0], pv[nt][1]);
            u32 h1 = packbf(pv[nt][2], pv[nt][3]);
            float a0 = __uint_as_float(h0 << 16);
            float a1 = __uint_as_float(h0 & 0xffff0000u);
            float c0 = __uint_as_float(h1 << 16);
            float c1 = __uint_as_float(h1 & 0xffff0000u);
            u32 lo0 = packbf(pv[nt][0] - a0, pv[nt][1] - a1);
            u32 lo1 = packbf(pv[nt][2] - c0, pv[nt][3] - c1);
            *reinterpret_cast<u32*>((char*)g_Ph + (pr0 + col)*2) = h0;
            *reinterpret_cast<u32*>((char*)g_Ph + (pr1 + col)*2) = h1;
            *reinterpret_cast<u32*>((char*)g_Pl + (pr0 + col)*2) = lo0;
            *reinterpret_cast<u32*>((char*)g_Pl + (pr1 + col)*2) = lo1;
        }
        __syncthreads();
    }

    l0 += __shfl_xor_sync(0xffffffffu, l0, 1);
    l0 += __shfl_xor_sync(0xffffffffu, l0, 2);
    l1 += __shfl_xor_sync(0xffffffffu, l1, 1);
    l1 += __shfl_xor_sync(0xffffffffu, l1, 2);
    if ((lane & 3) == 0){
        g_lp[(size_t)(b*SEQ + row0)*4 + chunk] = l0;
        g_lp[(size_t)(b*SEQ + row1)*4 + chunk] = l1;
    }
}

// ---------------------------------------------------------------------------
// k_pv: O = P V^T (bf16x3) — pure GEMM, 2-stage cp.async.
// grid 512: (qt heavy-first, b, 128-feat quarter). warp = 16 q-rows.
// stage (73728): Ph@0 Pl@18432 Vh@36864 Vl@55296
// ---------------------------------------------------------------------------
#define PVST 73728
#define PV_SMEM (2*PVST)   // 147456

__global__ __launch_bounds__(256) void k_pv(float* __restrict__ out){
    extern __shared__ unsigned char smem[];
    const u32 sb = smem_u32(smem);
    const int tid = threadIdx.x, lane = tid & 31, w = tid >> 5;

    const int bi = blockIdx.x;
    const int qt = 15 - (bi >> 5);
    const int sub = bi & 31;
    const int b  = sub >> 2;
    const int h0 = (sub & 3) * 128;
    const int q0 = qt * 128;
    const int nkt = 2*qt + 2;

    auto issue = [&](int kt, int stg){
        const int k0 = kt * 64;
        const u32 SB = sb + (u32)stg * PVST;
#pragma unroll
        for (int it = 0; it < 4; it++){
            int i2 = tid + it*256, r = i2 >> 3, cc = i2 & 7;
            size_t gp = ((size_t)(b*SEQ + q0 + r)*SEQ + k0)*2 + cc*16;
            u32 so = (u32)(r*GS + cc*16);
            cpa16(SB +     0 + so, (const char*)g_Ph + gp);
            cpa16(SB + 18432 + so, (const char*)g_Pl + gp);
        }
#pragma unroll
        for (int it = 0; it < 4; it++){
            int i2 = tid + it*256, r = i2 >> 3, cc = i2 & 7;
            size_t gv = ((size_t)(b*COUT + h0 + r)*SEQ + k0)*2 + cc*16;
            u32 so = (u32)(r*GS + cc*16);
            cpa16(SB + 36864 + so, (const char*)g_Vth + gv);
            cpa16(SB + 55296 + so, (const char*)g_Vtl + gv);
        }
        cp_commit();
    };

    issue(0, 0);

    float o[16][4];
#pragma unroll
    for (int nt = 0; nt < 16; nt++)
#pragma unroll
        for (int r = 0; r < 4; r++) o[nt][r] = 0.f;

    const int row0 = q0 + w*16 + (lane >> 2);
    const int row1 = row0 + 8;

    for (int kt = 0; kt < nkt; kt++){
        if (kt + 1 < nkt){ issue(kt + 1, (kt + 1) & 1); cp_wait1(); }
        else             { cp_wait0(); }
        __syncthreads();
        const u32 SB = sb + (u32)(kt & 1) * PVST;

#pragma unroll
        for (int kc = 0; kc < 4; kc++){
            u32 ph[4], pl[4];
            u32 ro_a = (u32)((w*16) * GS + kc*32);
            ldm4(ph, addrA(SB +     0 + ro_a, lane, GS));
            ldm4(pl, addrA(SB + 18432 + ro_a, lane, GS));
#pragma unroll
            for (int np = 0; np < 8; np++){
                u32 ro = (u32)((np*16) * GS + kc*32);
                u32 vh[4], vl[4];
                ldm4(vh, addrB(SB + 36864 + ro, lane, GS));
                ldm4(vl, addrB(SB + 55296 + ro, lane, GS));
#pragma unroll
                for (int hh = 0; hh < 2; hh++){
                    int nt = np*2 + hh;
                    mma16816(o[nt], ph, vh[hh*2], vh[hh*2+1]);
                    mma16816(o[nt], pl, vh[hh*2], vh[hh*2+1]);
                    mma16816(o[nt], ph, vl[hh*2], vl[hh*2+1]);
                }
            }
        }
        __syncthreads();
    }

    // row sums from per-chunk partials (fixed order -> deterministic)
    const int nch = qt/4 + 1;
    float L0 = 0.f, L1 = 0.f;
    for (int c2 = 0; c2 < nch; c2++){
        L0 += g_lp[(size_t)(b*SEQ + row0)*4 + c2];
        L1 += g_lp[(size_t)(b*SEQ + row1)*4 + c2];
    }
    const float inv0 = 1.f / L0, inv1 = 1.f / L1;

    const size_t ob0 = (size_t)(b*SEQ + row0)*COUT + h0;
    const size_t ob1 = (size_t)(b*SEQ + row1)*COUT + h0;
#pragma unroll
    for (int nt = 0; nt < 16; nt++){
        int cg = nt*8 + ((lane & 3) << 1);
        *reinterpret_cast<float2*>(&out[ob0 + cg]) = make_float2(o[nt][0]*inv0, o[nt][1]*inv0);
        *reinterpret_cast<float2*>(&out[ob1 + cg]) = make_float2(o[nt][2]*inv1, o[nt][3]*inv1);
    }
}

// ---------------------------------------------------------------------------
extern "C" void kernel_launch(void* const* d_in, const int* in_sizes, int n_in,
                              void* d_out, int out_size)
{
    const float* x  = (const float*)d_in[0];
    const float* Wq = (const float*)d_in[1];
    const float* Wk = (const float*)d_in[2];
    const float* Wv = (const float*)d_in[3];
    float* out = (float*)d_out;

    k_split_x<<<(MROWS*CIN/4)/256, 256>>>(x);
    k_split_w<<<(NTOT*CIN)/256, 256>>>(Wq, Wk, Wv);

    cudaFuncSetAttribute(k_gemm, cudaFuncAttributeMaxDynamicSharedMemorySize, G_SMEM);
    k_gemm<<<dim3(128, 5), 256, G_SMEM>>>();

    cudaFuncSetAttribute(k_qk, cudaFuncAttributeMaxDynamicSharedMemorySize, QK_SMEM);
    k_qk<<<320, 256, QK_SMEM>>>();

    cudaFuncSetAttribute(k_pv, cudaFuncAttributeMaxDynamicSharedMemorySize, PV_SMEM);
    k_pv<<<512, 256, PV_SMEM>>>(out);
}

// round 11
// speedup vs baseline: 4.2517x; 1.1852x over previous
#include <cuda_runtime.h>
#include <cuda_bf16.h>
#include <cuda_fp16.h>
#include <cstdint>

#define BATCH 8
#define SEQ   2048
#define CIN   512
#define DH    64
#define COUT  512
#define MROWS (BATCH*SEQ)   // 16384
#define NTOT  640
#define SCALE_Q 0.18033688011112042f   // (1/8) * log2(e)

typedef unsigned short u16;
typedef uint32_t u32;
typedef uint64_t u64;

// ---- scratch ----
__device__ __align__(16) u16 g_Xh[(size_t)MROWS*CIN];        // bf16
__device__ __align__(16) u16 g_Xl[(size_t)MROWS*CIN];
__device__ __align__(16) u16 g_Wth[(size_t)NTOT*CIN];
__device__ __align__(16) u16 g_Wtl[(size_t)NTOT*CIN];
__device__ __align__(16) u16 g_Qh[(size_t)MROWS*DH];
__device__ __align__(16) u16 g_Ql[(size_t)MROWS*DH];
__device__ __align__(16) u16 g_Kh[(size_t)MROWS*DH];
__device__ __align__(16) u16 g_Kl[(size_t)MROWS*DH];
__device__ __align__(16) u16 g_Vth[(size_t)BATCH*COUT*SEQ];  // fp16 hi [b][feat][token]
__device__ __align__(16) u16 g_Vtl[(size_t)BATCH*COUT*SEQ];  // fp16 lo
__device__ __align__(16) u16 g_Ph[(size_t)MROWS*SEQ];        // P numerators, fp16 single
__device__ float g_lp[(size_t)MROWS*4];                      // per-chunk row sums

// ---- helpers ----
__device__ __forceinline__ u32 smem_u32(const void* p){
    u32 a; asm("{ .reg .u64 t; cvta.to.shared.u64 t, %1; cvt.u32.u64 %0, t; }" : "=r"(a) : "l"(p));
    return a;
}
__device__ __forceinline__ void mma16816(float* c, const u32* a, u32 b0, u32 b1){
    asm volatile("mma.sync.aligned.m16n8k16.row.col.f32.bf16.bf16.f32 "
        "{%0,%1,%2,%3}, {%4,%5,%6,%7}, {%8,%9}, {%0,%1,%2,%3};"
        : "+f"(c[0]), "+f"(c[1]), "+f"(c[2]), "+f"(c[3])
        : "r"(a[0]), "r"(a[1]), "r"(a[2]), "r"(a[3]), "r"(b0), "r"(b1));
}
__device__ __forceinline__ void mma16816h(float* c, const u32* a, u32 b0, u32 b1){
    asm volatile("mma.sync.aligned.m16n8k16.row.col.f32.f16.f16.f32 "
        "{%0,%1,%2,%3}, {%4,%5,%6,%7}, {%8,%9}, {%0,%1,%2,%3};"
        : "+f"(c[0]), "+f"(c[1]), "+f"(c[2]), "+f"(c[3])
        : "r"(a[0]), "r"(a[1]), "r"(a[2]), "r"(a[3]), "r"(b0), "r"(b1));
}
__device__ __forceinline__ void ldm4(u32* r, u32 addr){
    asm volatile("ldmatrix.sync.aligned.m8n8.x4.shared.b16 {%0,%1,%2,%3}, [%4];"
        : "=r"(r[0]), "=r"(r[1]), "=r"(r[2]), "=r"(r[3]) : "r"(addr));
}
__device__ __forceinline__ u32 packhf(float lo, float hi){
    u32 d; asm("cvt.rn.f16x2.f32 %0, %1, %2;" : "=r"(d) : "f"(hi), "f"(lo)); return d;
}
__device__ __forceinline__ u16 f2bf(float x){ return __bfloat16_as_ushort(__float2bfloat16(x)); }
__device__ __forceinline__ float bf2f(u16 u){ return __bfloat162float(__ushort_as_bfloat16(u)); }
__device__ __forceinline__ void split2(float x, u16& h, u16& l){
    h = f2bf(x); l = f2bf(x - bf2f(h));
}
__device__ __forceinline__ void split2h(float x, u16& h, u16& l){
    __half hh = __float2half_rn(x);
    h = __half_as_ushort(hh);
    l = __half_as_ushort(__float2half_rn(x - __half2float(hh)));
}

__device__ __forceinline__ void cpa16(u32 dst, const void* src){
    asm volatile("cp.async.cg.shared.global [%0], [%1], 16;" :: "r"(dst), "l"(src));
}
__device__ __forceinline__ void cp_commit(){ asm volatile("cp.async.commit_group;" ::: "memory"); }
__device__ __forceinline__ void cp_wait1(){ asm volatile("cp.async.wait_group 1;" ::: "memory"); }
__device__ __forceinline__ void cp_wait0(){ asm volatile("cp.async.wait_group 0;" ::: "memory"); }

// A-operand ldmatrix address (row-major 16x16 tile, row stride S bytes)
__device__ __forceinline__ u32 addrA(u32 base, int lane, int S){
    return base + (u32)((lane & 15) * S + (lane >> 4) * 16);
}
// B-operand ldmatrix address from B^T rows ([n][k] row-major, stride S bytes)
__device__ __forceinline__ u32 addrB(u32 base, int lane, int S){
    int n = ((lane >> 4) << 3) | (lane & 7);
    return base + (u32)(n * S + ((lane >> 3) & 1) * 16);
}

// ---------------------------------------------------------------------------
__global__ __launch_bounds__(256) void k_split_x(const float* __restrict__ X){
    size_t i = (size_t)blockIdx.x * 256 + threadIdx.x;
    float4 v = reinterpret_cast<const float4*>(X)[i];
    u16 h[4], l[4];
    split2(v.x, h[0], l[0]); split2(v.y, h[1], l[1]);
    split2(v.z, h[2], l[2]); split2(v.w, h[3], l[3]);
    uint2 ph, pl;
    ph.x = (u32)h[0] | ((u32)h[1] << 16); ph.y = (u32)h[2] | ((u32)h[3] << 16);
    pl.x = (u32)l[0] | ((u32)l[1] << 16); pl.y = (u32)l[2] | ((u32)l[3] << 16);
    reinterpret_cast<uint2*>(g_Xh)[i] = ph;
    reinterpret_cast<uint2*>(g_Xl)[i] = pl;
}

__global__ __launch_bounds__(256) void k_split_w(const float* __restrict__ Wq,
                                                 const float* __restrict__ Wk,
                                                 const float* __restrict__ Wv){
    int idx = blockIdx.x * 256 + threadIdx.x;
    int n = idx % NTOT, k = idx / NTOT;
    float v;
    if (n < 64)       v = Wq[k*64 + n];
    else if (n < 128) v = Wk[k*64 + (n-64)];
    else              v = Wv[k*512 + (n-128)];
    u16 h, l; split2(v, h, l);
    g_Wth[(size_t)n*CIN + k] = h;
    g_Wtl[(size_t)n*CIN + k] = l;
}

// ---------------------------------------------------------------------------
// projection GEMM, 2-stage cp.async pipeline (bf16x3)
// ---------------------------------------------------------------------------
#define GS 144
#define GST 73728
#define G_SMEM (2*GST)

__global__ __launch_bounds__(256) void k_gemm(){
    extern __shared__ unsigned char smem[];
    const u32 sb = smem_u32(smem);
    float* smemT = reinterpret_cast<float*>(smem);
    const int tid = threadIdx.x, lane = tid & 31, w = tid >> 5;
    const int wm = w >> 2, wn = w & 3;
    const int m0 = blockIdx.x * 128, n0 = blockIdx.y * 128;

    float c[4][4][4];
#pragma unroll
    for (int i = 0; i < 4; i++)
#pragma unroll
        for (int j = 0; j < 4; j++)
#pragma unroll
            for (int r = 0; r < 4; r++) c[i][j][r] = 0.f;

    auto issue = [&](int s, int stg){
        const u32 SB = sb + (u32)stg * GST;
#pragma unroll
        for (int it = 0; it < 4; it++){
            int idx = tid + it*256, r = idx >> 3, cc = idx & 7;
            size_t ga = ((size_t)(m0 + r)*CIN + s*64)*2 + cc*16;
            size_t gb = ((size_t)(n0 + r)*CIN + s*64)*2 + cc*16;
            u32 so = (u32)(r*GS + cc*16);
            cpa16(SB +     0 + so, (const char*)g_Xh  + ga);
            cpa16(SB + 18432 + so, (const char*)g_Xl  + ga);
            cpa16(SB + 36864 + so, (const char*)g_Wth + gb);
            cpa16(SB + 55296 + so, (const char*)g_Wtl + gb);
        }
        cp_commit();
    };

    issue(0, 0);
    for (int s = 0; s < 8; s++){
        if (s + 1 < 8){ issue(s + 1, (s + 1) & 1); cp_wait1(); }
        else          { cp_wait0(); }
        __syncthreads();
        const u32 SB = sb + (u32)(s & 1) * GST;

#pragma unroll
        for (int kc = 0; kc < 4; kc++){
            u32 ah[4][4], al[4][4];
#pragma unroll
            for (int mt = 0; mt < 4; mt++){
                u32 ro = (u32)((wm*64 + mt*16) * GS + kc*32);
                ldm4(ah[mt], addrA(SB +     0 + ro, lane, GS));
                ldm4(al[mt], addrA(SB + 18432 + ro, lane, GS));
            }
            u32 bh[2][4], bl[2][4];
#pragma unroll
            for (int np = 0; np < 2; np++){
                u32 ro = (u32)((wn*32 + np*16) * GS + kc*32);
                ldm4(bh[np], addrB(SB + 36864 + ro, lane, GS));
                ldm4(bl[np], addrB(SB + 55296 + ro, lane, GS));
            }
#pragma unroll
            for (int mt = 0; mt < 4; mt++)
#pragma unroll
                for (int np = 0; np < 2; np++)
#pragma unroll
                    for (int hh = 0; hh < 2; hh++){
                        int nt = np*2 + hh;
                        mma16816(c[mt][nt], ah[mt], bh[np][hh*2], bh[np][hh*2+1]);
                        mma16816(c[mt][nt], al[mt], bh[np][hh*2], bh[np][hh*2+1]);
                        mma16816(c[mt][nt], ah[mt], bl[np][hh*2], bl[np][hh*2+1]);
                    }
        }
        __syncthreads();
    }

    if (n0 == 0){
        // Q (scaled) and K: bf16 hi/lo register stores
#pragma unroll
        for (int mt = 0; mt < 4; mt++){
            int row = m0 + wm*64 + mt*16 + (lane >> 2);
#pragma unroll
            for (int nt = 0; nt < 4; nt++){
                int cg = wn*32 + nt*8 + ((lane & 3) << 1);
                bool isQ = (cg < 64);
                float sc = isQ ? SCALE_Q : 1.f;
                int col = isQ ? cg : cg - 64;
#pragma unroll
                for (int hh = 0; hh < 2; hh++){
                    int r = row + hh*8;
                    float v0 = c[mt][nt][hh*2]   * sc;
                    float v1 = c[mt][nt][hh*2+1] * sc;
                    u16 h0,l0,h1,l1; split2(v0,h0,l0); split2(v1,h1,l1);
                    u32 ph = (u32)h0 | ((u32)h1 << 16);
                    u32 pl = (u32)l0 | ((u32)l1 << 16);
                    size_t off = ((size_t)r*DH + col)*2;
                    if (isQ){
                        *reinterpret_cast<u32*>((char*)g_Qh + off) = ph;
                        *reinterpret_cast<u32*>((char*)g_Ql + off) = pl;
                    } else {
                        *reinterpret_cast<u32*>((char*)g_Kh + off) = ph;
                        *reinterpret_cast<u32*>((char*)g_Kl + off) = pl;
                    }
                }
            }
        }
    } else {
        // V: bounce through smem fp32, store [feat][tok] fp16 hi/lo
#pragma unroll
        for (int mt = 0; mt < 4; mt++){
            int rl = wm*64 + mt*16 + (lane >> 2);
#pragma unroll
            for (int nt = 0; nt < 4; nt++){
                int cl = wn*32 + nt*8 + ((lane & 3) << 1);
                *reinterpret_cast<float2*>(&smemT[rl*132 + cl]) =
                    make_float2(c[mt][nt][0], c[mt][nt][1]);
                *reinterpret_cast<float2*>(&smemT[(rl+8)*132 + cl]) =
                    make_float2(c[mt][nt][2], c[mt][nt][3]);
            }
        }
        __syncthreads();
        const int b = m0 >> 11, t0 = m0 & 2047;
#pragma unroll
        for (int fi = 0; fi < 16; fi++){
            int fl = w*16 + fi;
            int gf = (n0 - 128) + fl;
            float v0 = smemT[(lane*4+0)*132 + fl];
            float v1 = smemT[(lane*4+1)*132 + fl];
            float v2 = smemT[(lane*4+2)*132 + fl];
            float v3 = smemT[(lane*4+3)*132 + fl];
            u16 h0,l0,h1,l1,h2,l2,h3,l3;
            split2h(v0,h0,l0); split2h(v1,h1,l1); split2h(v2,h2,l2); split2h(v3,h3,l3);
            uint2 H = make_uint2((u32)h0 | ((u32)h1<<16), (u32)h2 | ((u32)h3<<16));
            uint2 L = make_uint2((u32)l0 | ((u32)l1<<16), (u32)l2 | ((u32)l3<<16));
            size_t off = ((size_t)(b*COUT + gf)*SEQ + t0 + lane*4)*2;
            *reinterpret_cast<uint2*>((char*)g_Vth + off) = H;
            *reinterpret_cast<uint2*>((char*)g_Vtl + off) = L;
        }
    }
}

// ---------------------------------------------------------------------------
// k_qk: S = QK^T (bf16x3) + exp2 -> P (fp16 single) to global, chunk row sums.
// ---------------------------------------------------------------------------
#define QK_QH 0
#define QK_QL 18432
#define QK_ST 36864
#define QKST  18432
#define QK_SMEM (QK_ST + 2*QKST)   // 73728

__global__ __launch_bounds__(256) void k_qk(){
    extern __shared__ unsigned char smem[];
    const u32 sb = smem_u32(smem);
    const int tid = threadIdx.x, lane = tid & 31, w = tid >> 5;

    // decode (b, qt, chunk); heavy chunks first
    int idx = blockIdx.x;
    const int b = idx / 40;
    int rem = 39 - idx % 40;
    int qt = 0;
    while (rem >= (qt/4 + 1)){ rem -= qt/4 + 1; qt++; }
    const int chunk = rem;
    const int q0 = qt * 128;
    const int nkt = 2*qt + 2;
    const int ktA = chunk * 8;
    const int ktB = (ktA + 8 < nkt) ? ktA + 8 : nkt;

    auto issue = [&](int kt, int stg){
        const int k0 = kt * 64;
        const u32 SB = sb + QK_ST + (u32)stg * QKST;
#pragma unroll
        for (int it = 0; it < 2; it++){
            int i2 = tid + it*256, r = i2 >> 3, cc = i2 & 7;
            size_t gk = ((size_t)(b*SEQ + k0 + r)*DH)*2 + cc*16;
            u32 so = (u32)(r*GS + cc*16);
            cpa16(SB +    0 + so, (const char*)g_Kh + gk);
            cpa16(SB + 9216 + so, (const char*)g_Kl + gk);
        }
        cp_commit();
    };

    issue(ktA, ktA & 1);

#pragma unroll
    for (int it = 0; it < 4; it++){
        int i2 = tid + it*256, r = i2 >> 3, cc = i2 & 7;
        size_t gq = ((size_t)(b*SEQ + q0 + r)*DH)*2 + cc*16;
        u32 so = (u32)(r*GS + cc*16);
        *reinterpret_cast<uint4*>(smem + QK_QH + so) = *reinterpret_cast<const uint4*>((const char*)g_Qh + gq);
        *reinterpret_cast<uint4*>(smem + QK_QL + so) = *reinterpret_cast<const uint4*>((const char*)g_Ql + gq);
    }
    __syncthreads();

    u32 qh[4][4], ql[4][4];
#pragma unroll
    for (int kc = 0; kc < 4; kc++){
        u32 ro = (u32)((w*16) * GS + kc*32);
        ldm4(qh[kc], addrA(sb + QK_QH + ro, lane, GS));
        ldm4(ql[kc], addrA(sb + QK_QL + ro, lane, GS));
    }

    float l0 = 0.f, l1 = 0.f;
    const int row0 = q0 + w*16 + (lane >> 2);
    const int row1 = row0 + 8;
    const size_t pr0 = (size_t)(b*SEQ + row0) * SEQ;
    const size_t pr1 = (size_t)(b*SEQ + row1) * SEQ;

    for (int kt = ktA; kt < ktB; kt++){
        const int k0 = kt * 64;
        if (kt + 1 < ktB){ issue(kt + 1, (kt + 1) & 1); cp_wait1(); }
        else             { cp_wait0(); }
        __syncthreads();
        const u32 SB = sb + QK_ST + (u32)(kt & 1) * QKST;

        float s[8][4];
#pragma unroll
        for (int nt = 0; nt < 8; nt++)
#pragma unroll
            for (int r = 0; r < 4; r++) s[nt][r] = 0.f;

#pragma unroll
        for (int kc = 0; kc < 4; kc++){
#pragma unroll
            for (int np = 0; np < 4; np++){
                u32 ro = (u32)((np*16) * GS + kc*32);
                u32 kh[4], kl[4];
                ldm4(kh, addrB(SB +    0 + ro, lane, GS));
                ldm4(kl, addrB(SB + 9216 + ro, lane, GS));
#pragma unroll
                for (int hh = 0; hh < 2; hh++){
                    int nt = np*2 + hh;
                    mma16816(s[nt], qh[kc], kh[hh*2], kh[hh*2+1]);
                    mma16816(s[nt], ql[kc], kh[hh*2], kh[hh*2+1]);
                    mma16816(s[nt], qh[kc], kl[hh*2], kl[hh*2+1]);
                }
            }
        }

        // exp2 (+mask on diagonal tiles), store P fp16
        float pv[8][4];
        if (kt < nkt - 2){
#pragma unroll
            for (int nt = 0; nt < 8; nt++){
                pv[nt][0] = exp2f(s[nt][0]); pv[nt][1] = exp2f(s[nt][1]);
                pv[nt][2] = exp2f(s[nt][2]); pv[nt][3] = exp2f(s[nt][3]);
                l0 += pv[nt][0] + pv[nt][1];
                l1 += pv[nt][2] + pv[nt][3];
            }
        } else {
#pragma unroll
            for (int nt = 0; nt < 8; nt++){
                int col = k0 + nt*8 + ((lane & 3) << 1);
                pv[nt][0] = (col     <= row0) ? exp2f(s[nt][0]) : 0.f;
                pv[nt][1] = (col + 1 <= row0) ? exp2f(s[nt][1]) : 0.f;
                pv[nt][2] = (col     <= row1) ? exp2f(s[nt][2]) : 0.f;
                pv[nt][3] = (col + 1 <= row1) ? exp2f(s[nt][3]) : 0.f;
                l0 += pv[nt][0] + pv[nt][1];
                l1 += pv[nt][2] + pv[nt][3];
            }
        }
#pragma unroll
        for (int nt = 0; nt < 8; nt++){
            int col = k0 + nt*8 + ((lane & 3) << 1);
            u32 p0 = packhf(pv[nt][0], pv[nt][1]);
            u32 p1 = packhf(pv[nt][2], pv[nt][3]);
            *reinterpret_cast<u32*>((char*)g_Ph + (pr0 + col)*2) = p0;
            *reinterpret_cast<u32*>((char*)g_Ph + (pr1 + col)*2) = p1;
        }
        __syncthreads();
    }

    l0 += __shfl_xor_sync(0xffffffffu, l0, 1);
    l0 += __shfl_xor_sync(0xffffffffu, l0, 2);
    l1 += __shfl_xor_sync(0xffffffffu, l1, 1);
    l1 += __shfl_xor_sync(0xffffffffu, l1, 2);
    if ((lane & 3) == 0){
        g_lp[(size_t)(b*SEQ + row0)*4 + chunk] = l0;
        g_lp[(size_t)(b*SEQ + row1)*4 + chunk] = l1;
    }
}

// ---------------------------------------------------------------------------
// k_pv: O = P V^T (fp16, 2 products) — pure GEMM, 2-stage cp.async.
// stage (55296): Ph@0 Vh@18432 Vl@36864
// ---------------------------------------------------------------------------
#define PVST 55296
#define PV_SMEM (2*PVST)   // 110592

__global__ __launch_bounds__(256) void k_pv(float* __restrict__ out){
    extern __shared__ unsigned char smem[];
    const u32 sb = smem_u32(smem);
    const int tid = threadIdx.x, lane = tid & 31, w = tid >> 5;

    const int bi = blockIdx.x;
    const int qt = 15 - (bi >> 5);
    const int sub = bi & 31;
    const int b  = sub >> 2;
    const int h0 = (sub & 3) * 128;
    const int q0 = qt * 128;
    const int nkt = 2*qt + 2;

    auto issue = [&](int kt, int stg){
        const int k0 = kt * 64;
        const u32 SB = sb + (u32)stg * PVST;
#pragma unroll
        for (int it = 0; it < 4; it++){
            int i2 = tid + it*256, r = i2 >> 3, cc = i2 & 7;
            size_t gp = ((size_t)(b*SEQ + q0 + r)*SEQ + k0)*2 + cc*16;
            u32 so = (u32)(r*GS + cc*16);
            cpa16(SB + so, (const char*)g_Ph + gp);
        }
#pragma unroll
        for (int it = 0; it < 4; it++){
            int i2 = tid + it*256, r = i2 >> 3, cc = i2 & 7;
            size_t gv = ((size_t)(b*COUT + h0 + r)*SEQ + k0)*2 + cc*16;
            u32 so = (u32)(r*GS + cc*16);
            cpa16(SB + 18432 + so, (const char*)g_Vth + gv);
            cpa16(SB + 36864 + so, (const char*)g_Vtl + gv);
        }
        cp_commit();
    };

    issue(0, 0);

    float o[16][4];
#pragma unroll
    for (int nt = 0; nt < 16; nt++)
#pragma unroll
        for (int r = 0; r < 4; r++) o[nt][r] = 0.f;

    const int row0 = q0 + w*16 + (lane >> 2);
    const int row1 = row0 + 8;

    for (int kt = 0; kt < nkt; kt++){
        if (kt + 1 < nkt){ issue(kt + 1, (kt + 1) & 1); cp_wait1(); }
        else             { cp_wait0(); }
        __syncthreads();
        const u32 SB = sb + (u32)(kt & 1) * PVST;

#pragma unroll
        for (int kc = 0; kc < 4; kc++){
            u32 p[4];
            u32 ro_a = (u32)((w*16) * GS + kc*32);
            ldm4(p, addrA(SB + ro_a, lane, GS));
#pragma unroll
            for (int np = 0; np < 8; np++){
                u32 ro = (u32)((np*16) * GS + kc*32);
                u32 vh[4], vl[4];
                ldm4(vh, addrB(SB + 18432 + ro, lane, GS));
                ldm4(vl, addrB(SB + 36864 + ro, lane, GS));
#pragma unroll
                for (int hh = 0; hh < 2; hh++){
                    int nt = np*2 + hh;
                    mma16816h(o[nt], p, vh[hh*2], vh[hh*2+1]);
                    mma16816h(o[nt], p, vl[hh*2], vl[hh*2+1]);
                }
            }
        }
        __syncthreads();
    }

    const int nch = qt/4 + 1;
    float L0 = 0.f, L1 = 0.f;
    for (int c2 = 0; c2 < nch; c2++){
        L0 += g_lp[(size_t)(b*SEQ + row0)*4 + c2];
        L1 += g_lp[(size_t)(b*SEQ + row1)*4 + c2];
    }
    const float inv0 = 1.f / L0, inv1 = 1.f / L1;

    const size_t ob0 = (size_t)(b*SEQ + row0)*COUT + h0;
    const size_t ob1 = (size_t)(b*SEQ + row1)*COUT + h0;
#pragma unroll
    for (int nt = 0; nt < 16; nt++){
        int cg = nt*8 + ((lane & 3) << 1);
        *reinterpret_cast<float2*>(&out[ob0 + cg]) = make_float2(o[nt][0]*inv0, o[nt][1]*inv0);
        *reinterpret_cast<float2*>(&out[ob1 + cg]) = make_float2(o[nt][2]*inv1, o[nt][3]*inv1);
    }
}

// ---------------------------------------------------------------------------
extern "C" void kernel_launch(void* const* d_in, const int* in_sizes, int n_in,
                              void* d_out, int out_size)
{
    const float* x  = (const float*)d_in[0];
    const float* Wq = (const float*)d_in[1];
    const float* Wk = (const float*)d_in[2];
    const float* Wv = (const float*)d_in[3];
    float* out = (float*)d_out;

    k_split_x<<<(MROWS*CIN/4)/256, 256>>>(x);
    k_split_w<<<(NTOT*CIN)/256, 256>>>(Wq, Wk, Wv);

    cudaFuncSetAttribute(k_gemm, cudaFuncAttributeMaxDynamicSharedMemorySize, G_SMEM);
    k_gemm<<<dim3(128, 5), 256, G_SMEM>>>();

    cudaFuncSetAttribute(k_qk, cudaFuncAttributeMaxDynamicSharedMemorySize, QK_SMEM);
    k_qk<<<320, 256, QK_SMEM>>>();

    cudaFuncSetAttribute(k_pv, cudaFuncAttributeMaxDynamicSharedMemorySize, PV_SMEM);
    k_pv<<<512, 256, PV_SMEM>>>(out);
}

// round 12
// speedup vs baseline: 5.0607x; 1.1903x over previous
#include <cuda_runtime.h>
#include <cuda_bf16.h>
#include <cuda_fp16.h>
#include <cstdint>

#define BATCH 8
#define SEQ   2048
#define CIN   512
#define DH    64
#define COUT  512
#define MROWS (BATCH*SEQ)   // 16384
#define NTOT  640
#define SCALE_Q 0.18033688011112042f   // (1/8) * log2(e)

typedef unsigned short u16;
typedef uint32_t u32;
typedef uint64_t u64;

// ---- scratch ----
__device__ __align__(16) u16 g_Xh[(size_t)MROWS*CIN];        // bf16
__device__ __align__(16) u16 g_Xl[(size_t)MROWS*CIN];
__device__ __align__(16) u16 g_Wth[(size_t)NTOT*CIN];
__device__ __align__(16) u16 g_Wtl[(size_t)NTOT*CIN];
__device__ __align__(16) u16 g_Qh[(size_t)MROWS*DH];
__device__ __align__(16) u16 g_Ql[(size_t)MROWS*DH];
__device__ __align__(16) u16 g_Kh[(size_t)MROWS*DH];
__device__ __align__(16) u16 g_Kl[(size_t)MROWS*DH];
__device__ __align__(16) u16 g_Vt[(size_t)BATCH*COUT*SEQ];   // fp16 single [b][feat][token]
__device__ __align__(16) u16 g_Ph[(size_t)MROWS*SEQ];        // P numerators, fp16 single
__device__ float g_lp[(size_t)MROWS*4];                      // per-chunk row sums

// ---- helpers ----
__device__ __forceinline__ u32 smem_u32(const void* p){
    u32 a; asm("{ .reg .u64 t; cvta.to.shared.u64 t, %1; cvt.u32.u64 %0, t; }" : "=r"(a) : "l"(p));
    return a;
}
__device__ __forceinline__ void mma16816(float* c, const u32* a, u32 b0, u32 b1){
    asm volatile("mma.sync.aligned.m16n8k16.row.col.f32.bf16.bf16.f32 "
        "{%0,%1,%2,%3}, {%4,%5,%6,%7}, {%8,%9}, {%0,%1,%2,%3};"
        : "+f"(c[0]), "+f"(c[1]), "+f"(c[2]), "+f"(c[3])
        : "r"(a[0]), "r"(a[1]), "r"(a[2]), "r"(a[3]), "r"(b0), "r"(b1));
}
__device__ __forceinline__ void mma16816h(float* c, const u32* a, u32 b0, u32 b1){
    asm volatile("mma.sync.aligned.m16n8k16.row.col.f32.f16.f16.f32 "
        "{%0,%1,%2,%3}, {%4,%5,%6,%7}, {%8,%9}, {%0,%1,%2,%3};"
        : "+f"(c[0]), "+f"(c[1]), "+f"(c[2]), "+f"(c[3])
        : "r"(a[0]), "r"(a[1]), "r"(a[2]), "r"(a[3]), "r"(b0), "r"(b1));
}
__device__ __forceinline__ void ldm4(u32* r, u32 addr){
    asm volatile("ldmatrix.sync.aligned.m8n8.x4.shared.b16 {%0,%1,%2,%3}, [%4];"
        : "=r"(r[0]), "=r"(r[1]), "=r"(r[2]), "=r"(r[3]) : "r"(addr));
}
__device__ __forceinline__ u32 packhf(float lo, float hi){
    u32 d; asm("cvt.rn.f16x2.f32 %0, %1, %2;" : "=r"(d) : "f"(hi), "f"(lo)); return d;
}
__device__ __forceinline__ u16 f2bf(float x){ return __bfloat16_as_ushort(__float2bfloat16(x)); }
__device__ __forceinline__ float bf2f(u16 u){ return __bfloat162float(__ushort_as_bfloat16(u)); }
__device__ __forceinline__ void split2(float x, u16& h, u16& l){
    h = f2bf(x); l = f2bf(x - bf2f(h));
}

__device__ __forceinline__ void cpa16(u32 dst, const void* src){
    asm volatile("cp.async.cg.shared.global [%0], [%1], 16;" :: "r"(dst), "l"(src));
}
__device__ __forceinline__ void cp_commit(){ asm volatile("cp.async.commit_group;" ::: "memory"); }
__device__ __forceinline__ void cp_wait1(){ asm volatile("cp.async.wait_group 1;" ::: "memory"); }
__device__ __forceinline__ void cp_wait0(){ asm volatile("cp.async.wait_group 0;" ::: "memory"); }

// A-operand ldmatrix address (row-major 16x16 tile, row stride S bytes)
__device__ __forceinline__ u32 addrA(u32 base, int lane, int S){
    return base + (u32)((lane & 15) * S + (lane >> 4) * 16);
}
// B-operand ldmatrix address from B^T rows ([n][k] row-major, stride S bytes)
__device__ __forceinline__ u32 addrB(u32 base, int lane, int S){
    int n = ((lane >> 4) << 3) | (lane & 7);
    return base + (u32)(n * S + ((lane >> 3) & 1) * 16);
}

// ---------------------------------------------------------------------------
__global__ __launch_bounds__(256) void k_split_x(const float* __restrict__ X){
    size_t i = (size_t)blockIdx.x * 256 + threadIdx.x;
    float4 v = reinterpret_cast<const float4*>(X)[i];
    u16 h[4], l[4];
    split2(v.x, h[0], l[0]); split2(v.y, h[1], l[1]);
    split2(v.z, h[2], l[2]); split2(v.w, h[3], l[3]);
    uint2 ph, pl;
    ph.x = (u32)h[0] | ((u32)h[1] << 16); ph.y = (u32)h[2] | ((u32)h[3] << 16);
    pl.x = (u32)l[0] | ((u32)l[1] << 16); pl.y = (u32)l[2] | ((u32)l[3] << 16);
    reinterpret_cast<uint2*>(g_Xh)[i] = ph;
    reinterpret_cast<uint2*>(g_Xl)[i] = pl;
}

__global__ __launch_bounds__(256) void k_split_w(const float* __restrict__ Wq,
                                                 const float* __restrict__ Wk,
                                                 const float* __restrict__ Wv){
    int idx = blockIdx.x * 256 + threadIdx.x;
    int n = idx % NTOT, k = idx / NTOT;
    float v;
    if (n < 64)       v = Wq[k*64 + n];
    else if (n < 128) v = Wk[k*64 + (n-64)];
    else              v = Wv[k*512 + (n-128)];
    u16 h, l; split2(v, h, l);
    g_Wth[(size_t)n*CIN + k] = h;
    g_Wtl[(size_t)n*CIN + k] = l;
}

// ---------------------------------------------------------------------------
// projection GEMM, 2-stage cp.async pipeline (bf16x3)
// ---------------------------------------------------------------------------
#define GS 144
#define GST 73728
#define G_SMEM (2*GST)

__global__ __launch_bounds__(256) void k_gemm(){
    extern __shared__ unsigned char smem[];
    const u32 sb = smem_u32(smem);
    float* smemT = reinterpret_cast<float*>(smem);
    const int tid = threadIdx.x, lane = tid & 31, w = tid >> 5;
    const int wm = w >> 2, wn = w & 3;
    const int m0 = blockIdx.x * 128, n0 = blockIdx.y * 128;

    float c[4][4][4];
#pragma unroll
    for (int i = 0; i < 4; i++)
#pragma unroll
        for (int j = 0; j < 4; j++)
#pragma unroll
            for (int r = 0; r < 4; r++) c[i][j][r] = 0.f;

    auto issue = [&](int s, int stg){
        const u32 SB = sb + (u32)stg * GST;
#pragma unroll
        for (int it = 0; it < 4; it++){
            int idx = tid + it*256, r = idx >> 3, cc = idx & 7;
            size_t ga = ((size_t)(m0 + r)*CIN + s*64)*2 + cc*16;
            size_t gb = ((size_t)(n0 + r)*CIN + s*64)*2 + cc*16;
            u32 so = (u32)(r*GS + cc*16);
            cpa16(SB +     0 + so, (const char*)g_Xh  + ga);
            cpa16(SB + 18432 + so, (const char*)g_Xl  + ga);
            cpa16(SB + 36864 + so, (const char*)g_Wth + gb);
            cpa16(SB + 55296 + so, (const char*)g_Wtl + gb);
        }
        cp_commit();
    };

    issue(0, 0);
    for (int s = 0; s < 8; s++){
        if (s + 1 < 8){ issue(s + 1, (s + 1) & 1); cp_wait1(); }
        else          { cp_wait0(); }
        __syncthreads();
        const u32 SB = sb + (u32)(s & 1) * GST;

#pragma unroll
        for (int kc = 0; kc < 4; kc++){
            u32 ah[4][4], al[4][4];
#pragma unroll
            for (int mt = 0; mt < 4; mt++){
                u32 ro = (u32)((wm*64 + mt*16) * GS + kc*32);
                ldm4(ah[mt], addrA(SB +     0 + ro, lane, GS));
                ldm4(al[mt], addrA(SB + 18432 + ro, lane, GS));
            }
            u32 bh[2][4], bl[2][4];
#pragma unroll
            for (int np = 0; np < 2; np++){
                u32 ro = (u32)((wn*32 + np*16) * GS + kc*32);
                ldm4(bh[np], addrB(SB + 36864 + ro, lane, GS));
                ldm4(bl[np], addrB(SB + 55296 + ro, lane, GS));
            }
#pragma unroll
            for (int mt = 0; mt < 4; mt++)
#pragma unroll
                for (int np = 0; np < 2; np++)
#pragma unroll
                    for (int hh = 0; hh < 2; hh++){
                        int nt = np*2 + hh;
                        mma16816(c[mt][nt], ah[mt], bh[np][hh*2], bh[np][hh*2+1]);
                        mma16816(c[mt][nt], al[mt], bh[np][hh*2], bh[np][hh*2+1]);
                        mma16816(c[mt][nt], ah[mt], bl[np][hh*2], bl[np][hh*2+1]);
                    }
        }
        __syncthreads();
    }

    if (n0 == 0){
        // Q (scaled) and K: bf16 hi/lo register stores
#pragma unroll
        for (int mt = 0; mt < 4; mt++){
            int row = m0 + wm*64 + mt*16 + (lane >> 2);
#pragma unroll
            for (int nt = 0; nt < 4; nt++){
                int cg = wn*32 + nt*8 + ((lane & 3) << 1);
                bool isQ = (cg < 64);
                float sc = isQ ? SCALE_Q : 1.f;
                int col = isQ ? cg : cg - 64;
#pragma unroll
                for (int hh = 0; hh < 2; hh++){
                    int r = row + hh*8;
                    float v0 = c[mt][nt][hh*2]   * sc;
                    float v1 = c[mt][nt][hh*2+1] * sc;
                    u16 h0,l0,h1,l1; split2(v0,h0,l0); split2(v1,h1,l1);
                    u32 ph = (u32)h0 | ((u32)h1 << 16);
                    u32 pl = (u32)l0 | ((u32)l1 << 16);
                    size_t off = ((size_t)r*DH + col)*2;
                    if (isQ){
                        *reinterpret_cast<u32*>((char*)g_Qh + off) = ph;
                        *reinterpret_cast<u32*>((char*)g_Ql + off) = pl;
                    } else {
                        *reinterpret_cast<u32*>((char*)g_Kh + off) = ph;
                        *reinterpret_cast<u32*>((char*)g_Kl + off) = pl;
                    }
                }
            }
        }
    } else {
        // V: bounce through smem fp32, store [feat][tok] fp16 single
#pragma unroll
        for (int mt = 0; mt < 4; mt++){
            int rl = wm*64 + mt*16 + (lane >> 2);
#pragma unroll
            for (int nt = 0; nt < 4; nt++){
                int cl = wn*32 + nt*8 + ((lane & 3) << 1);
                *reinterpret_cast<float2*>(&smemT[rl*132 + cl]) =
                    make_float2(c[mt][nt][0], c[mt][nt][1]);
                *reinterpret_cast<float2*>(&smemT[(rl+8)*132 + cl]) =
                    make_float2(c[mt][nt][2], c[mt][nt][3]);
            }
        }
        __syncthreads();
        const int b = m0 >> 11, t0 = m0 & 2047;
#pragma unroll
        for (int fi = 0; fi < 16; fi++){
            int fl = w*16 + fi;
            int gf = (n0 - 128) + fl;
            u32 p0 = packhf(smemT[(lane*4+0)*132 + fl], smemT[(lane*4+1)*132 + fl]);
            u32 p1 = packhf(smemT[(lane*4+2)*132 + fl], smemT[(lane*4+3)*132 + fl]);
            size_t off = ((size_t)(b*COUT + gf)*SEQ + t0 + lane*4)*2;
            *reinterpret_cast<uint2*>((char*)g_Vt + off) = make_uint2(p0, p1);
        }
    }
}

// ---------------------------------------------------------------------------
// k_qk: S = QK^T (bf16x3) + exp2 -> P (fp16 single) to global, chunk row sums.
// ---------------------------------------------------------------------------
#define QK_QH 0
#define QK_QL 18432
#define QK_ST 36864
#define QKST  18432
#define QK_SMEM (QK_ST + 2*QKST)   // 73728

__global__ __launch_bounds__(256) void k_qk(){
    extern __shared__ unsigned char smem[];
    const u32 sb = smem_u32(smem);
    const int tid = threadIdx.x, lane = tid & 31, w = tid >> 5;

    // decode (b, qt, chunk); heavy chunks first
    int idx = blockIdx.x;
    const int b = idx / 40;
    int rem = 39 - idx % 40;
    int qt = 0;
    while (rem >= (qt/4 + 1)){ rem -= qt/4 + 1; qt++; }
    const int chunk = rem;
    const int q0 = qt * 128;
    const int nkt = 2*qt + 2;
    const int ktA = chunk * 8;
    const int ktB = (ktA + 8 < nkt) ? ktA + 8 : nkt;

    auto issue = [&](int kt, int stg){
        const int k0 = kt * 64;
        const u32 SB = sb + QK_ST + (u32)stg * QKST;
#pragma unroll
        for (int it = 0; it < 2; it++){
            int i2 = tid + it*256, r = i2 >> 3, cc = i2 & 7;
            size_t gk = ((size_t)(b*SEQ + k0 + r)*DH)*2 + cc*16;
            u32 so = (u32)(r*GS + cc*16);
            cpa16(SB +    0 + so, (const char*)g_Kh + gk);
            cpa16(SB + 9216 + so, (const char*)g_Kl + gk);
        }
        cp_commit();
    };

    issue(ktA, ktA & 1);

#pragma unroll
    for (int it = 0; it < 4; it++){
        int i2 = tid + it*256, r = i2 >> 3, cc = i2 & 7;
        size_t gq = ((size_t)(b*SEQ + q0 + r)*DH)*2 + cc*16;
        u32 so = (u32)(r*GS + cc*16);
        *reinterpret_cast<uint4*>(smem + QK_QH + so) = *reinterpret_cast<const uint4*>((const char*)g_Qh + gq);
        *reinterpret_cast<uint4*>(smem + QK_QL + so) = *reinterpret_cast<const uint4*>((const char*)g_Ql + gq);
    }
    __syncthreads();

    u32 qh[4][4], ql[4][4];
#pragma unroll
    for (int kc = 0; kc < 4; kc++){
        u32 ro = (u32)((w*16) * GS + kc*32);
        ldm4(qh[kc], addrA(sb + QK_QH + ro, lane, GS));
        ldm4(ql[kc], addrA(sb + QK_QL + ro, lane, GS));
    }

    float l0 = 0.f, l1 = 0.f;
    const int row0 = q0 + w*16 + (lane >> 2);
    const int row1 = row0 + 8;
    const size_t pr0 = (size_t)(b*SEQ + row0) * SEQ;
    const size_t pr1 = (size_t)(b*SEQ + row1) * SEQ;

    for (int kt = ktA; kt < ktB; kt++){
        const int k0 = kt * 64;
        if (kt + 1 < ktB){ issue(kt + 1, (kt + 1) & 1); cp_wait1(); }
        else             { cp_wait0(); }
        __syncthreads();
        const u32 SB = sb + QK_ST + (u32)(kt & 1) * QKST;

        float s[8][4];
#pragma unroll
        for (int nt = 0; nt < 8; nt++)
#pragma unroll
            for (int r = 0; r < 4; r++) s[nt][r] = 0.f;

#pragma unroll
        for (int kc = 0; kc < 4; kc++){
#pragma unroll
            for (int np = 0; np < 4; np++){
                u32 ro = (u32)((np*16) * GS + kc*32);
                u32 kh[4], kl[4];
                ldm4(kh, addrB(SB +    0 + ro, lane, GS));
                ldm4(kl, addrB(SB + 9216 + ro, lane, GS));
#pragma unroll
                for (int hh = 0; hh < 2; hh++){
                    int nt = np*2 + hh;
                    mma16816(s[nt], qh[kc], kh[hh*2], kh[hh*2+1]);
                    mma16816(s[nt], ql[kc], kh[hh*2], kh[hh*2+1]);
                    mma16816(s[nt], qh[kc], kl[hh*2], kl[hh*2+1]);
                }
            }
        }

        // exp2 (+mask on diagonal tiles), store P fp16
        float pv[8][4];
        if (kt < nkt - 2){
#pragma unroll
            for (int nt = 0; nt < 8; nt++){
                pv[nt][0] = exp2f(s[nt][0]); pv[nt][1] = exp2f(s[nt][1]);
                pv[nt][2] = exp2f(s[nt][2]); pv[nt][3] = exp2f(s[nt][3]);
                l0 += pv[nt][0] + pv[nt][1];
                l1 += pv[nt][2] + pv[nt][3];
            }
        } else {
#pragma unroll
            for (int nt = 0; nt < 8; nt++){
                int col = k0 + nt*8 + ((lane & 3) << 1);
                pv[nt][0] = (col     <= row0) ? exp2f(s[nt][0]) : 0.f;
                pv[nt][1] = (col + 1 <= row0) ? exp2f(s[nt][1]) : 0.f;
                pv[nt][2] = (col     <= row1) ? exp2f(s[nt][2]) : 0.f;
                pv[nt][3] = (col + 1 <= row1) ? exp2f(s[nt][3]) : 0.f;
                l0 += pv[nt][0] + pv[nt][1];
                l1 += pv[nt][2] + pv[nt][3];
            }
        }
#pragma unroll
        for (int nt = 0; nt < 8; nt++){
            int col = k0 + nt*8 + ((lane & 3) << 1);
            u32 p0 = packhf(pv[nt][0], pv[nt][1]);
            u32 p1 = packhf(pv[nt][2], pv[nt][3]);
            *reinterpret_cast<u32*>((char*)g_Ph + (pr0 + col)*2) = p0;
            *reinterpret_cast<u32*>((char*)g_Ph + (pr1 + col)*2) = p1;
        }
        __syncthreads();
    }

    l0 += __shfl_xor_sync(0xffffffffu, l0, 1);
    l0 += __shfl_xor_sync(0xffffffffu, l0, 2);
    l1 += __shfl_xor_sync(0xffffffffu, l1, 1);
    l1 += __shfl_xor_sync(0xffffffffu, l1, 2);
    if ((lane & 3) == 0){
        g_lp[(size_t)(b*SEQ + row0)*4 + chunk] = l0;
        g_lp[(size_t)(b*SEQ + row1)*4 + chunk] = l1;
    }
}

// ---------------------------------------------------------------------------
// k_pv: O = P V^T (fp16 single product) — pure GEMM, 2-stage cp.async,
// 2 CTAs/SM. stage (36864): Ph@0 Vt@18432
// ---------------------------------------------------------------------------
#define PVST 36864
#define PV_SMEM (2*PVST)   // 73728

__global__ __launch_bounds__(256, 2) void k_pv(float* __restrict__ out){
    extern __shared__ unsigned char smem[];
    const u32 sb = smem_u32(smem);
    const int tid = threadIdx.x, lane = tid & 31, w = tid >> 5;

    const int bi = blockIdx.x;
    const int qt = 15 - (bi >> 5);
    const int sub = bi & 31;
    const int b  = sub >> 2;
    const int h0 = (sub & 3) * 128;
    const int q0 = qt * 128;
    const int nkt = 2*qt + 2;

    auto issue = [&](int kt, int stg){
        const int k0 = kt * 64;
        const u32 SB = sb + (u32)stg * PVST;
#pragma unroll
        for (int it = 0; it < 4; it++){
            int i2 = tid + it*256, r = i2 >> 3, cc = i2 & 7;
            size_t gp = ((size_t)(b*SEQ + q0 + r)*SEQ + k0)*2 + cc*16;
            u32 so = (u32)(r*GS + cc*16);
            cpa16(SB + so, (const char*)g_Ph + gp);
        }
#pragma unroll
        for (int it = 0; it < 4; it++){
            int i2 = tid + it*256, r = i2 >> 3, cc = i2 & 7;
            size_t gv = ((size_t)(b*COUT + h0 + r)*SEQ + k0)*2 + cc*16;
            u32 so = (u32)(r*GS + cc*16);
            cpa16(SB + 18432 + so, (const char*)g_Vt + gv);
        }
        cp_commit();
    };

    issue(0, 0);

    float o[16][4];
#pragma unroll
    for (int nt = 0; nt < 16; nt++)
#pragma unroll
        for (int r = 0; r < 4; r++) o[nt][r] = 0.f;

    const int row0 = q0 + w*16 + (lane >> 2);
    const int row1 = row0 + 8;

    for (int kt = 0; kt < nkt; kt++){
        if (kt + 1 < nkt){ issue(kt + 1, (kt + 1) & 1); cp_wait1(); }
        else             { cp_wait0(); }
        __syncthreads();
        const u32 SB = sb + (u32)(kt & 1) * PVST;

#pragma unroll
        for (int kc = 0; kc < 4; kc++){
            u32 p[4];
            u32 ro_a = (u32)((w*16) * GS + kc*32);
            ldm4(p, addrA(SB + ro_a, lane, GS));
#pragma unroll
            for (int np = 0; np < 8; np++){
                u32 ro = (u32)((np*16) * GS + kc*32);
                u32 v[4];
                ldm4(v, addrB(SB + 18432 + ro, lane, GS));
                mma16816h(o[np*2],   p, v[0], v[1]);
                mma16816h(o[np*2+1], p, v[2], v[3]);
            }
        }
        __syncthreads();
    }

    const int nch = qt/4 + 1;
    float L0 = 0.f, L1 = 0.f;
    for (int c2 = 0; c2 < nch; c2++){
        L0 += g_lp[(size_t)(b*SEQ + row0)*4 + c2];
        L1 += g_lp[(size_t)(b*SEQ + row1)*4 + c2];
    }
    const float inv0 = 1.f / L0, inv1 = 1.f / L1;

    const size_t ob0 = (size_t)(b*SEQ + row0)*COUT + h0;
    const size_t ob1 = (size_t)(b*SEQ + row1)*COUT + h0;
#pragma unroll
    for (int nt = 0; nt < 16; nt++){
        int cg = nt*8 + ((lane & 3) << 1);
        *reinterpret_cast<float2*>(&out[ob0 + cg]) = make_float2(o[nt][0]*inv0, o[nt][1]*inv0);
        *reinterpret_cast<float2*>(&out[ob1 + cg]) = make_float2(o[nt][2]*inv1, o[nt][3]*inv1);
    }
}

// ---------------------------------------------------------------------------
extern "C" void kernel_launch(void* const* d_in, const int* in_sizes, int n_in,
                              void* d_out, int out_size)
{
    const float* x  = (const float*)d_in[0];
    const float* Wq = (const float*)d_in[1];
    const float* Wk = (const float*)d_in[2];
    const float* Wv = (const float*)d_in[3];
    float* out = (float*)d_out;

    k_split_x<<<(MROWS*CIN/4)/256, 256>>>(x);
    k_split_w<<<(NTOT*CIN)/256, 256>>>(Wq, Wk, Wv);

    cudaFuncSetAttribute(k_gemm, cudaFuncAttributeMaxDynamicSharedMemorySize, G_SMEM);
    k_gemm<<<dim3(128, 5), 256, G_SMEM>>>();

    cudaFuncSetAttribute(k_qk, cudaFuncAttributeMaxDynamicSharedMemorySize, QK_SMEM);
    k_qk<<<320, 256, QK_SMEM>>>();

    cudaFuncSetAttribute(k_pv, cudaFuncAttributeMaxDynamicSharedMemorySize, PV_SMEM);
    k_pv<<<512, 256, PV_SMEM>>>(out);
}

// round 13
// speedup vs baseline: 5.2691x; 1.0412x over previous
#include <cuda_runtime.h>
#include <cuda_bf16.h>
#include <cuda_fp16.h>
#include <cstdint>

#define BATCH 8
#define SEQ   2048
#define CIN   512
#define DH    64
#define COUT  512
#define MROWS (BATCH*SEQ)   // 16384
#define NTOT  640
#define SCALE_Q 0.18033688011112042f   // (1/8) * log2(e)

typedef unsigned short u16;
typedef uint32_t u32;
typedef uint64_t u64;

// ---- scratch ----
__device__ __align__(16) u16 g_Xh[(size_t)MROWS*CIN];        // bf16
__device__ __align__(16) u16 g_Xl[(size_t)MROWS*CIN];
__device__ __align__(16) u16 g_Wth[(size_t)NTOT*CIN];
__device__ __align__(16) u16 g_Wtl[(size_t)NTOT*CIN];
__device__ __align__(16) u16 g_Qh[(size_t)MROWS*DH];
__device__ __align__(16) u16 g_Ql[(size_t)MROWS*DH];
__device__ __align__(16) u16 g_Kh[(size_t)MROWS*DH];
__device__ __align__(16) u16 g_Kl[(size_t)MROWS*DH];
__device__ __align__(16) u16 g_Vt[(size_t)BATCH*COUT*SEQ];   // fp16 single [b][feat][token]
__device__ __align__(16) u16 g_Ph[(size_t)MROWS*SEQ];        // P numerators, fp16 single
__device__ float g_lp[(size_t)MROWS*4];                      // per-chunk row sums

// ---- helpers ----
__device__ __forceinline__ u32 smem_u32(const void* p){
    u32 a; asm("{ .reg .u64 t; cvta.to.shared.u64 t, %1; cvt.u32.u64 %0, t; }" : "=r"(a) : "l"(p));
    return a;
}
__device__ __forceinline__ void mma16816(float* c, const u32* a, u32 b0, u32 b1){
    asm volatile("mma.sync.aligned.m16n8k16.row.col.f32.bf16.bf16.f32 "
        "{%0,%1,%2,%3}, {%4,%5,%6,%7}, {%8,%9}, {%0,%1,%2,%3};"
        : "+f"(c[0]), "+f"(c[1]), "+f"(c[2]), "+f"(c[3])
        : "r"(a[0]), "r"(a[1]), "r"(a[2]), "r"(a[3]), "r"(b0), "r"(b1));
}
__device__ __forceinline__ void mma16816h(float* c, const u32* a, u32 b0, u32 b1){
    asm volatile("mma.sync.aligned.m16n8k16.row.col.f32.f16.f16.f32 "
        "{%0,%1,%2,%3}, {%4,%5,%6,%7}, {%8,%9}, {%0,%1,%2,%3};"
        : "+f"(c[0]), "+f"(c[1]), "+f"(c[2]), "+f"(c[3])
        : "r"(a[0]), "r"(a[1]), "r"(a[2]), "r"(a[3]), "r"(b0), "r"(b1));
}
__device__ __forceinline__ void ldm4(u32* r, u32 addr){
    asm volatile("ldmatrix.sync.aligned.m8n8.x4.shared.b16 {%0,%1,%2,%3}, [%4];"
        : "=r"(r[0]), "=r"(r[1]), "=r"(r[2]), "=r"(r[3]) : "r"(addr));
}
__device__ __forceinline__ u32 packhf(float lo, float hi){
    u32 d; asm("cvt.rn.f16x2.f32 %0, %1, %2;" : "=r"(d) : "f"(hi), "f"(lo)); return d;
}
__device__ __forceinline__ u16 f2bf(float x){ return __bfloat16_as_ushort(__float2bfloat16(x)); }
__device__ __forceinline__ float bf2f(u16 u){ return __bfloat162float(__ushort_as_bfloat16(u)); }
__device__ __forceinline__ void split2(float x, u16& h, u16& l){
    h = f2bf(x); l = f2bf(x - bf2f(h));
}

__device__ __forceinline__ void cpa16(u32 dst, const void* src){
    asm volatile("cp.async.cg.shared.global [%0], [%1], 16;" :: "r"(dst), "l"(src));
}
__device__ __forceinline__ void cp_commit(){ asm volatile("cp.async.commit_group;" ::: "memory"); }
__device__ __forceinline__ void cp_wait1(){ asm volatile("cp.async.wait_group 1;" ::: "memory"); }
__device__ __forceinline__ void cp_wait0(){ asm volatile("cp.async.wait_group 0;" ::: "memory"); }

// A-operand ldmatrix address (row-major 16x16 tile, row stride S bytes)
__device__ __forceinline__ u32 addrA(u32 base, int lane, int S){
    return base + (u32)((lane & 15) * S + (lane >> 4) * 16);
}
// B-operand ldmatrix address from B^T rows ([n][k] row-major, stride S bytes)
__device__ __forceinline__ u32 addrB(u32 base, int lane, int S){
    int n = ((lane >> 4) << 3) | (lane & 7);
    return base + (u32)(n * S + ((lane >> 3) & 1) * 16);
}

// ---------------------------------------------------------------------------
__global__ __launch_bounds__(256) void k_split_x(const float* __restrict__ X){
    size_t i = (size_t)blockIdx.x * 256 + threadIdx.x;
    float4 v = reinterpret_cast<const float4*>(X)[i];
    u16 h[4], l[4];
    split2(v.x, h[0], l[0]); split2(v.y, h[1], l[1]);
    split2(v.z, h[2], l[2]); split2(v.w, h[3], l[3]);
    uint2 ph, pl;
    ph.x = (u32)h[0] | ((u32)h[1] << 16); ph.y = (u32)h[2] | ((u32)h[3] << 16);
    pl.x = (u32)l[0] | ((u32)l[1] << 16); pl.y = (u32)l[2] | ((u32)l[3] << 16);
    reinterpret_cast<uint2*>(g_Xh)[i] = ph;
    reinterpret_cast<uint2*>(g_Xl)[i] = pl;
}

__global__ __launch_bounds__(256) void k_split_w(const float* __restrict__ Wq,
                                                 const float* __restrict__ Wk,
                                                 const float* __restrict__ Wv){
    int idx = blockIdx.x * 256 + threadIdx.x;
    int n = idx % NTOT, k = idx / NTOT;
    float v;
    if (n < 64)       v = Wq[k*64 + n];
    else if (n < 128) v = Wk[k*64 + (n-64)];
    else              v = Wv[k*512 + (n-128)];
    u16 h, l; split2(v, h, l);
    g_Wth[(size_t)n*CIN + k] = h;
    g_Wtl[(size_t)n*CIN + k] = l;
}

// ---------------------------------------------------------------------------
// projection GEMM, 2-stage cp.async pipeline (bf16x3)
// ---------------------------------------------------------------------------
#define GS 144
#define GST 73728
#define G_SMEM (2*GST)

__global__ __launch_bounds__(256) void k_gemm(){
    extern __shared__ unsigned char smem[];
    const u32 sb = smem_u32(smem);
    float* smemT = reinterpret_cast<float*>(smem);
    const int tid = threadIdx.x, lane = tid & 31, w = tid >> 5;
    const int wm = w >> 2, wn = w & 3;
    const int m0 = blockIdx.x * 128, n0 = blockIdx.y * 128;

    float c[4][4][4];
#pragma unroll
    for (int i = 0; i < 4; i++)
#pragma unroll
        for (int j = 0; j < 4; j++)
#pragma unroll
            for (int r = 0; r < 4; r++) c[i][j][r] = 0.f;

    auto issue = [&](int s, int stg){
        const u32 SB = sb + (u32)stg * GST;
#pragma unroll
        for (int it = 0; it < 4; it++){
            int idx = tid + it*256, r = idx >> 3, cc = idx & 7;
            size_t ga = ((size_t)(m0 + r)*CIN + s*64)*2 + cc*16;
            size_t gb = ((size_t)(n0 + r)*CIN + s*64)*2 + cc*16;
            u32 so = (u32)(r*GS + cc*16);
            cpa16(SB +     0 + so, (const char*)g_Xh  + ga);
            cpa16(SB + 18432 + so, (const char*)g_Xl  + ga);
            cpa16(SB + 36864 + so, (const char*)g_Wth + gb);
            cpa16(SB + 55296 + so, (const char*)g_Wtl + gb);
        }
        cp_commit();
    };

    issue(0, 0);
    for (int s = 0; s < 8; s++){
        if (s + 1 < 8){ issue(s + 1, (s + 1) & 1); cp_wait1(); }
        else          { cp_wait0(); }
        __syncthreads();
        const u32 SB = sb + (u32)(s & 1) * GST;

#pragma unroll
        for (int kc = 0; kc < 4; kc++){
            u32 ah[4][4], al[4][4];
#pragma unroll
            for (int mt = 0; mt < 4; mt++){
                u32 ro = (u32)((wm*64 + mt*16) * GS + kc*32);
                ldm4(ah[mt], addrA(SB +     0 + ro, lane, GS));
                ldm4(al[mt], addrA(SB + 18432 + ro, lane, GS));
            }
            u32 bh[2][4], bl[2][4];
#pragma unroll
            for (int np = 0; np < 2; np++){
                u32 ro = (u32)((wn*32 + np*16) * GS + kc*32);
                ldm4(bh[np], addrB(SB + 36864 + ro, lane, GS));
                ldm4(bl[np], addrB(SB + 55296 + ro, lane, GS));
            }
#pragma unroll
            for (int mt = 0; mt < 4; mt++)
#pragma unroll
                for (int np = 0; np < 2; np++)
#pragma unroll
                    for (int hh = 0; hh < 2; hh++){
                        int nt = np*2 + hh;
                        mma16816(c[mt][nt], ah[mt], bh[np][hh*2], bh[np][hh*2+1]);
                        mma16816(c[mt][nt], al[mt], bh[np][hh*2], bh[np][hh*2+1]);
                        mma16816(c[mt][nt], ah[mt], bl[np][hh*2], bl[np][hh*2+1]);
                    }
        }
        __syncthreads();
    }

    if (n0 == 0){
        // Q (scaled) and K: bf16 hi/lo register stores
#pragma unroll
        for (int mt = 0; mt < 4; mt++){
            int row = m0 + wm*64 + mt*16 + (lane >> 2);
#pragma unroll
            for (int nt = 0; nt < 4; nt++){
                int cg = wn*32 + nt*8 + ((lane & 3) << 1);
                bool isQ = (cg < 64);
                float sc = isQ ? SCALE_Q : 1.f;
                int col = isQ ? cg : cg - 64;
#pragma unroll
                for (int hh = 0; hh < 2; hh++){
                    int r = row + hh*8;
                    float v0 = c[mt][nt][hh*2]   * sc;
                    float v1 = c[mt][nt][hh*2+1] * sc;
                    u16 h0,l0,h1,l1; split2(v0,h0,l0); split2(v1,h1,l1);
                    u32 ph = (u32)h0 | ((u32)h1 << 16);
                    u32 pl = (u32)l0 | ((u32)l1 << 16);
                    size_t off = ((size_t)r*DH + col)*2;
                    if (isQ){
                        *reinterpret_cast<u32*>((char*)g_Qh + off) = ph;
                        *reinterpret_cast<u32*>((char*)g_Ql + off) = pl;
                    } else {
                        *reinterpret_cast<u32*>((char*)g_Kh + off) = ph;
                        *reinterpret_cast<u32*>((char*)g_Kl + off) = pl;
                    }
                }
            }
        }
    } else {
        // V: bounce through smem fp32, store [feat][tok] fp16 single
#pragma unroll
        for (int mt = 0; mt < 4; mt++){
            int rl = wm*64 + mt*16 + (lane >> 2);
#pragma unroll
            for (int nt = 0; nt < 4; nt++){
                int cl = wn*32 + nt*8 + ((lane & 3) << 1);
                *reinterpret_cast<float2*>(&smemT[rl*132 + cl]) =
                    make_float2(c[mt][nt][0], c[mt][nt][1]);
                *reinterpret_cast<float2*>(&smemT[(rl+8)*132 + cl]) =
                    make_float2(c[mt][nt][2], c[mt][nt][3]);
            }
        }
        __syncthreads();
        const int b = m0 >> 11, t0 = m0 & 2047;
#pragma unroll
        for (int fi = 0; fi < 16; fi++){
            int fl = w*16 + fi;
            int gf = (n0 - 128) + fl;
            u32 p0 = packhf(smemT[(lane*4+0)*132 + fl], smemT[(lane*4+1)*132 + fl]);
            u32 p1 = packhf(smemT[(lane*4+2)*132 + fl], smemT[(lane*4+3)*132 + fl]);
            size_t off = ((size_t)(b*COUT + gf)*SEQ + t0 + lane*4)*2;
            *reinterpret_cast<uint2*>((char*)g_Vt + off) = make_uint2(p0, p1);
        }
    }
}

// ---------------------------------------------------------------------------
// k_qk: S = QK^T (bf16x3) + exp2 -> P (fp16 single) to global, chunk row sums.
// 2 CTAs/SM.
// ---------------------------------------------------------------------------
#define QK_QH 0
#define QK_QL 18432
#define QK_ST 36864
#define QKST  18432
#define QK_SMEM (QK_ST + 2*QKST)   // 73728

__global__ __launch_bounds__(256, 2) void k_qk(){
    extern __shared__ unsigned char smem[];
    const u32 sb = smem_u32(smem);
    const int tid = threadIdx.x, lane = tid & 31, w = tid >> 5;

    // decode (b, qt, chunk); heavy chunks first
    int idx = blockIdx.x;
    const int b = idx / 40;
    int rem = 39 - idx % 40;
    int qt = 0;
    while (rem >= (qt/4 + 1)){ rem -= qt/4 + 1; qt++; }
    const int chunk = rem;
    const int q0 = qt * 128;
    const int nkt = 2*qt + 2;
    const int ktA = chunk * 8;
    const int ktB = (ktA + 8 < nkt) ? ktA + 8 : nkt;

    auto issue = [&](int kt, int stg){
        const int k0 = kt * 64;
        const u32 SB = sb + QK_ST + (u32)stg * QKST;
#pragma unroll
        for (int it = 0; it < 2; it++){
            int i2 = tid + it*256, r = i2 >> 3, cc = i2 & 7;
            size_t gk = ((size_t)(b*SEQ + k0 + r)*DH)*2 + cc*16;
            u32 so = (u32)(r*GS + cc*16);
            cpa16(SB +    0 + so, (const char*)g_Kh + gk);
            cpa16(SB + 9216 + so, (const char*)g_Kl + gk);
        }
        cp_commit();
    };

    issue(ktA, ktA & 1);

#pragma unroll
    for (int it = 0; it < 4; it++){
        int i2 = tid + it*256, r = i2 >> 3, cc = i2 & 7;
        size_t gq = ((size_t)(b*SEQ + q0 + r)*DH)*2 + cc*16;
        u32 so = (u32)(r*GS + cc*16);
        *reinterpret_cast<uint4*>(smem + QK_QH + so) = *reinterpret_cast<const uint4*>((const char*)g_Qh + gq);
        *reinterpret_cast<uint4*>(smem + QK_QL + so) = *reinterpret_cast<const uint4*>((const char*)g_Ql + gq);
    }
    __syncthreads();

    u32 qh[4][4], ql[4][4];
#pragma unroll
    for (int kc = 0; kc < 4; kc++){
        u32 ro = (u32)((w*16) * GS + kc*32);
        ldm4(qh[kc], addrA(sb + QK_QH + ro, lane, GS));
        ldm4(ql[kc], addrA(sb + QK_QL + ro, lane, GS));
    }

    float l0 = 0.f, l1 = 0.f;
    const int row0 = q0 + w*16 + (lane >> 2);
    const int row1 = row0 + 8;
    const size_t pr0 = (size_t)(b*SEQ + row0) * SEQ;
    const size_t pr1 = (size_t)(b*SEQ + row1) * SEQ;

    for (int kt = ktA; kt < ktB; kt++){
        const int k0 = kt * 64;
        if (kt + 1 < ktB){ issue(kt + 1, (kt + 1) & 1); cp_wait1(); }
        else             { cp_wait0(); }
        __syncthreads();
        const u32 SB = sb + QK_ST + (u32)(kt & 1) * QKST;

        float s[8][4];
#pragma unroll
        for (int nt = 0; nt < 8; nt++)
#pragma unroll
            for (int r = 0; r < 4; r++) s[nt][r] = 0.f;

#pragma unroll
        for (int kc = 0; kc < 4; kc++){
#pragma unroll
            for (int np = 0; np < 4; np++){
                u32 ro = (u32)((np*16) * GS + kc*32);
                u32 kh[4], kl[4];
                ldm4(kh, addrB(SB +    0 + ro, lane, GS));
                ldm4(kl, addrB(SB + 9216 + ro, lane, GS));
#pragma unroll
                for (int hh = 0; hh < 2; hh++){
                    int nt = np*2 + hh;
                    mma16816(s[nt], qh[kc], kh[hh*2], kh[hh*2+1]);
                    mma16816(s[nt], ql[kc], kh[hh*2], kh[hh*2+1]);
                    mma16816(s[nt], qh[kc], kl[hh*2], kl[hh*2+1]);
                }
            }
        }

        // exp2 (+mask on diagonal tiles), store P fp16
        float pv[8][4];
        if (kt < nkt - 2){
#pragma unroll
            for (int nt = 0; nt < 8; nt++){
                pv[nt][0] = exp2f(s[nt][0]); pv[nt][1] = exp2f(s[nt][1]);
                pv[nt][2] = exp2f(s[nt][2]); pv[nt][3] = exp2f(s[nt][3]);
                l0 += pv[nt][0] + pv[nt][1];
                l1 += pv[nt][2] + pv[nt][3];
            }
        } else {
#pragma unroll
            for (int nt = 0; nt < 8; nt++){
                int col = k0 + nt*8 + ((lane & 3) << 1);
                pv[nt][0] = (col     <= row0) ? exp2f(s[nt][0]) : 0.f;
                pv[nt][1] = (col + 1 <= row0) ? exp2f(s[nt][1]) : 0.f;
                pv[nt][2] = (col     <= row1) ? exp2f(s[nt][2]) : 0.f;
                pv[nt][3] = (col + 1 <= row1) ? exp2f(s[nt][3]) : 0.f;
                l0 += pv[nt][0] + pv[nt][1];
                l1 += pv[nt][2] + pv[nt][3];
            }
        }
#pragma unroll
        for (int nt = 0; nt < 8; nt++){
            int col = k0 + nt*8 + ((lane & 3) << 1);
            u32 p0 = packhf(pv[nt][0], pv[nt][1]);
            u32 p1 = packhf(pv[nt][2], pv[nt][3]);
            *reinterpret_cast<u32*>((char*)g_Ph + (pr0 + col)*2) = p0;
            *reinterpret_cast<u32*>((char*)g_Ph + (pr1 + col)*2) = p1;
        }
        __syncthreads();
    }

    l0 += __shfl_xor_sync(0xffffffffu, l0, 1);
    l0 += __shfl_xor_sync(0xffffffffu, l0, 2);
    l1 += __shfl_xor_sync(0xffffffffu, l1, 1);
    l1 += __shfl_xor_sync(0xffffffffu, l1, 2);
    if ((lane & 3) == 0){
        g_lp[(size_t)(b*SEQ + row0)*4 + chunk] = l0;
        g_lp[(size_t)(b*SEQ + row1)*4 + chunk] = l1;
    }
}

// ---------------------------------------------------------------------------
// k_pv: O = P V^T (fp16) — pure GEMM, 2-stage cp.async, 2 CTAs/SM.
// Warp grid 4(m)x2(n): warp tile 32 q-rows x 64 feats (V smem reads 8x -> 2x).
// stage (36864): Ph@0 Vt@18432
// ---------------------------------------------------------------------------
#define PVST 36864
#define PV_SMEM (2*PVST)   // 73728

__global__ __launch_bounds__(256, 2) void k_pv(float* __restrict__ out){
    extern __shared__ unsigned char smem[];
    const u32 sb = smem_u32(smem);
    const int tid = threadIdx.x, lane = tid & 31, w = tid >> 5;
    const int wm = w >> 1, wn = w & 1;

    const int bi = blockIdx.x;
    const int qt = 15 - (bi >> 5);
    const int sub = bi & 31;
    const int b  = sub >> 2;
    const int h0 = (sub & 3) * 128;
    const int q0 = qt * 128;
    const int nkt = 2*qt + 2;

    auto issue = [&](int kt, int stg){
        const int k0 = kt * 64;
        const u32 SB = sb + (u32)stg * PVST;
#pragma unroll
        for (int it = 0; it < 4; it++){
            int i2 = tid + it*256, r = i2 >> 3, cc = i2 & 7;
            size_t gp = ((size_t)(b*SEQ + q0 + r)*SEQ + k0)*2 + cc*16;
            u32 so = (u32)(r*GS + cc*16);
            cpa16(SB + so, (const char*)g_Ph + gp);
        }
#pragma unroll
        for (int it = 0; it < 4; it++){
            int i2 = tid + it*256, r = i2 >> 3, cc = i2 & 7;
            size_t gv = ((size_t)(b*COUT + h0 + r)*SEQ + k0)*2 + cc*16;
            u32 so = (u32)(r*GS + cc*16);
            cpa16(SB + 18432 + so, (const char*)g_Vt + gv);
        }
        cp_commit();
    };

    issue(0, 0);

    float o[2][8][4];
#pragma unroll
    for (int mt = 0; mt < 2; mt++)
#pragma unroll
        for (int nt = 0; nt < 8; nt++)
#pragma unroll
            for (int r = 0; r < 4; r++) o[mt][nt][r] = 0.f;

    for (int kt = 0; kt < nkt; kt++){
        if (kt + 1 < nkt){ issue(kt + 1, (kt + 1) & 1); cp_wait1(); }
        else             { cp_wait0(); }
        __syncthreads();
        const u32 SB = sb + (u32)(kt & 1) * PVST;

#pragma unroll
        for (int kc = 0; kc < 4; kc++){
            u32 p0[4], p1[4];
            ldm4(p0, addrA(SB + (u32)((wm*32     ) * GS + kc*32), lane, GS));
            ldm4(p1, addrA(SB + (u32)((wm*32 + 16) * GS + kc*32), lane, GS));
#pragma unroll
            for (int np = 0; np < 4; np++){
                u32 ro = (u32)((wn*64 + np*16) * GS + kc*32);
                u32 v[4];
                ldm4(v, addrB(SB + 18432 + ro, lane, GS));
                mma16816h(o[0][np*2],   p0, v[0], v[1]);
                mma16816h(o[0][np*2+1], p0, v[2], v[3]);
                mma16816h(o[1][np*2],   p1, v[0], v[1]);
                mma16816h(o[1][np*2+1], p1, v[2], v[3]);
            }
        }
        __syncthreads();
    }

    const int nch = qt/4 + 1;
#pragma unroll
    for (int mt = 0; mt < 2; mt++){
        const int row0 = q0 + wm*32 + mt*16 + (lane >> 2);
        const int row1 = row0 + 8;
        float L0 = 0.f, L1 = 0.f;
        for (int c2 = 0; c2 < nch; c2++){
            L0 += g_lp[(size_t)(b*SEQ + row0)*4 + c2];
            L1 += g_lp[(size_t)(b*SEQ + row1)*4 + c2];
        }
        const float inv0 = 1.f / L0, inv1 = 1.f / L1;
        const size_t ob0 = (size_t)(b*SEQ + row0)*COUT + h0 + wn*64;
        const size_t ob1 = (size_t)(b*SEQ + row1)*COUT + h0 + wn*64;
#pragma unroll
        for (int nt = 0; nt < 8; nt++){
            int cg = nt*8 + ((lane & 3) << 1);
            *reinterpret_cast<float2*>(&out[ob0 + cg]) =
                make_float2(o[mt][nt][0]*inv0, o[mt][nt][1]*inv0);
            *reinterpret_cast<float2*>(&out[ob1 + cg]) =
                make_float2(o[mt][nt][2]*inv1, o[mt][nt][3]*inv1);
        }
    }
}

// ---------------------------------------------------------------------------
extern "C" void kernel_launch(void* const* d_in, const int* in_sizes, int n_in,
                              void* d_out, int out_size)
{
    const float* x  = (const float*)d_in[0];
    const float* Wq = (const float*)d_in[1];
    const float* Wk = (const float*)d_in[2];
    const float* Wv = (const float*)d_in[3];
    float* out = (float*)d_out;

    k_split_x<<<(MROWS*CIN/4)/256, 256>>>(x);
    k_split_w<<<(NTOT*CIN)/256, 256>>>(Wq, Wk, Wv);

    cudaFuncSetAttribute(k_gemm, cudaFuncAttributeMaxDynamicSharedMemorySize, G_SMEM);
    k_gemm<<<dim3(128, 5), 256, G_SMEM>>>();

    cudaFuncSetAttribute(k_qk, cudaFuncAttributeMaxDynamicSharedMemorySize, QK_SMEM);
    k_qk<<<320, 256, QK_SMEM>>>();

    cudaFuncSetAttribute(k_pv, cudaFuncAttributeMaxDynamicSharedMemorySize, PV_SMEM);
    k_pv<<<512, 256, PV_SMEM>>>(out);
}

// round 14
// speedup vs baseline: 5.3093x; 1.0076x over previous
#include <cuda_runtime.h>
#include <cuda_bf16.h>
#include <cuda_fp16.h>
#include <cstdint>

#define BATCH 8
#define SEQ   2048
#define CIN   512
#define DH    64
#define COUT  512
#define MROWS (BATCH*SEQ)   // 16384
#define NTOT  640
#define SCALE_Q 0.18033688011112042f   // (1/8) * log2(e)

typedef unsigned short u16;
typedef uint32_t u32;
typedef uint64_t u64;

// ---- scratch ----
__device__ __align__(16) u16 g_Xh[(size_t)MROWS*CIN];        // bf16
__device__ __align__(16) u16 g_Xl[(size_t)MROWS*CIN];
__device__ __align__(16) u16 g_Wth[(size_t)NTOT*CIN];
__device__ __align__(16) u16 g_Wtl[(size_t)NTOT*CIN];
__device__ __align__(16) u16 g_Qh[(size_t)MROWS*DH];
__device__ __align__(16) u16 g_Ql[(size_t)MROWS*DH];
__device__ __align__(16) u16 g_Kh[(size_t)MROWS*DH];
__device__ __align__(16) u16 g_Kl[(size_t)MROWS*DH];
__device__ __align__(16) u16 g_Vt[(size_t)BATCH*COUT*SEQ];   // fp16 single [b][feat][token]
__device__ __align__(16) u16 g_Ph[(size_t)MROWS*SEQ];        // P numerators, fp16 single
__device__ float g_lp[(size_t)MROWS*4];                      // per-chunk row sums

// ---- helpers ----
__device__ __forceinline__ u32 smem_u32(const void* p){
    u32 a; asm("{ .reg .u64 t; cvta.to.shared.u64 t, %1; cvt.u32.u64 %0, t; }" : "=r"(a) : "l"(p));
    return a;
}
__device__ __forceinline__ void mma16816(float* c, const u32* a, u32 b0, u32 b1){
    asm volatile("mma.sync.aligned.m16n8k16.row.col.f32.bf16.bf16.f32 "
        "{%0,%1,%2,%3}, {%4,%5,%6,%7}, {%8,%9}, {%0,%1,%2,%3};"
        : "+f"(c[0]), "+f"(c[1]), "+f"(c[2]), "+f"(c[3])
        : "r"(a[0]), "r"(a[1]), "r"(a[2]), "r"(a[3]), "r"(b0), "r"(b1));
}
__device__ __forceinline__ void mma16816h(float* c, const u32* a, u32 b0, u32 b1){
    asm volatile("mma.sync.aligned.m16n8k16.row.col.f32.f16.f16.f32 "
        "{%0,%1,%2,%3}, {%4,%5,%6,%7}, {%8,%9}, {%0,%1,%2,%3};"
        : "+f"(c[0]), "+f"(c[1]), "+f"(c[2]), "+f"(c[3])
        : "r"(a[0]), "r"(a[1]), "r"(a[2]), "r"(a[3]), "r"(b0), "r"(b1));
}
__device__ __forceinline__ void ldm4(u32* r, u32 addr){
    asm volatile("ldmatrix.sync.aligned.m8n8.x4.shared.b16 {%0,%1,%2,%3}, [%4];"
        : "=r"(r[0]), "=r"(r[1]), "=r"(r[2]), "=r"(r[3]) : "r"(addr));
}
__device__ __forceinline__ u32 packhf(float lo, float hi){
    u32 d; asm("cvt.rn.f16x2.f32 %0, %1, %2;" : "=r"(d) : "f"(hi), "f"(lo)); return d;
}
__device__ __forceinline__ u16 f2bf(float x){ return __bfloat16_as_ushort(__float2bfloat16(x)); }
__device__ __forceinline__ float bf2f(u16 u){ return __bfloat162float(__ushort_as_bfloat16(u)); }
__device__ __forceinline__ void split2(float x, u16& h, u16& l){
    h = f2bf(x); l = f2bf(x - bf2f(h));
}

__device__ __forceinline__ void cpa16(u32 dst, const void* src){
    asm volatile("cp.async.cg.shared.global [%0], [%1], 16;" :: "r"(dst), "l"(src));
}
__device__ __forceinline__ void cp_commit(){ asm volatile("cp.async.commit_group;" ::: "memory"); }
__device__ __forceinline__ void cp_wait1(){ asm volatile("cp.async.wait_group 1;" ::: "memory"); }
__device__ __forceinline__ void cp_wait0(){ asm volatile("cp.async.wait_group 0;" ::: "memory"); }

// A-operand ldmatrix address (row-major 16x16 tile, row stride S bytes)
__device__ __forceinline__ u32 addrA(u32 base, int lane, int S){
    return base + (u32)((lane & 15) * S + (lane >> 4) * 16);
}
// B-operand ldmatrix address from B^T rows ([n][k] row-major, stride S bytes)
__device__ __forceinline__ u32 addrB(u32 base, int lane, int S){
    int n = ((lane >> 4) << 3) | (lane & 7);
    return base + (u32)(n * S + ((lane >> 3) & 1) * 16);
}

// ---------------------------------------------------------------------------
__global__ __launch_bounds__(256) void k_split_x(const float* __restrict__ X){
    size_t i = (size_t)blockIdx.x * 256 + threadIdx.x;
    float4 v = reinterpret_cast<const float4*>(X)[i];
    u16 h[4], l[4];
    split2(v.x, h[0], l[0]); split2(v.y, h[1], l[1]);
    split2(v.z, h[2], l[2]); split2(v.w, h[3], l[3]);
    uint2 ph, pl;
    ph.x = (u32)h[0] | ((u32)h[1] << 16); ph.y = (u32)h[2] | ((u32)h[3] << 16);
    pl.x = (u32)l[0] | ((u32)l[1] << 16); pl.y = (u32)l[2] | ((u32)l[3] << 16);
    reinterpret_cast<uint2*>(g_Xh)[i] = ph;
    reinterpret_cast<uint2*>(g_Xl)[i] = pl;
}

__global__ __launch_bounds__(256) void k_split_w(const float* __restrict__ Wq,
                                                 const float* __restrict__ Wk,
                                                 const float* __restrict__ Wv){
    int idx = blockIdx.x * 256 + threadIdx.x;
    int n = idx % NTOT, k = idx / NTOT;
    float v;
    if (n < 64)       v = Wq[k*64 + n];
    else if (n < 128) v = Wk[k*64 + (n-64)];
    else              v = Wv[k*512 + (n-128)];
    u16 h, l; split2(v, h, l);
    g_Wth[(size_t)n*CIN + k] = h;
    g_Wtl[(size_t)n*CIN + k] = l;
}

// ---------------------------------------------------------------------------
// projection GEMM (bf16x3), K-step 32, 2-stage cp.async, 2 CTAs/SM.
// stage (40960): Ah@0 Al@10240 Bh@20480 Bl@30720 ; rows stride 80B
// ---------------------------------------------------------------------------
#define GS  144       // stride for k_qk / k_pv tiles (64 tok * 2B + pad)
#define GS2 80        // stride for k_gemm K32 tiles (32 bf16 + 16B pad)
#define GBUF 10240
#define GST 40960
#define G_SMEM (2*GST)   // 81920

__global__ __launch_bounds__(256, 2) void k_gemm(){
    extern __shared__ unsigned char smem[];
    const u32 sb = smem_u32(smem);
    float* smemT = reinterpret_cast<float*>(smem);
    const int tid = threadIdx.x, lane = tid & 31, w = tid >> 5;
    const int wm = w >> 2, wn = w & 3;
    const int m0 = blockIdx.x * 128, n0 = blockIdx.y * 128;

    float c[4][4][4];
#pragma unroll
    for (int i = 0; i < 4; i++)
#pragma unroll
        for (int j = 0; j < 4; j++)
#pragma unroll
            for (int r = 0; r < 4; r++) c[i][j][r] = 0.f;

    auto issue = [&](int s, int stg){
        const u32 SB = sb + (u32)stg * GST;
#pragma unroll
        for (int it = 0; it < 2; it++){
            int i2 = tid + it*256;          // 0..511
            int r  = i2 >> 2, cc = i2 & 3;  // row, 16B chunk
            size_t ga = ((size_t)(m0 + r)*CIN + s*32)*2 + cc*16;
            size_t gb = ((size_t)(n0 + r)*CIN + s*32)*2 + cc*16;
            u32 so = (u32)(r*GS2 + cc*16);
            cpa16(SB +       0 + so, (const char*)g_Xh  + ga);
            cpa16(SB +   GBUF + so, (const char*)g_Xl  + ga);
            cpa16(SB + 2*GBUF + so, (const char*)g_Wth + gb);
            cpa16(SB + 3*GBUF + so, (const char*)g_Wtl + gb);
        }
        cp_commit();
    };

    issue(0, 0);
    for (int s = 0; s < 16; s++){
        if (s + 1 < 16){ issue(s + 1, (s + 1) & 1); cp_wait1(); }
        else           { cp_wait0(); }
        __syncthreads();
        const u32 SB = sb + (u32)(s & 1) * GST;

#pragma unroll
        for (int kc = 0; kc < 2; kc++){
            u32 ah[4][4], al[4][4];
#pragma unroll
            for (int mt = 0; mt < 4; mt++){
                u32 ro = (u32)((wm*64 + mt*16) * GS2 + kc*32);
                ldm4(ah[mt], addrA(SB +    0 + ro, lane, GS2));
                ldm4(al[mt], addrA(SB + GBUF + ro, lane, GS2));
            }
            u32 bh[2][4], bl[2][4];
#pragma unroll
            for (int np = 0; np < 2; np++){
                u32 ro = (u32)((wn*32 + np*16) * GS2 + kc*32);
                ldm4(bh[np], addrB(SB + 2*GBUF + ro, lane, GS2));
                ldm4(bl[np], addrB(SB + 3*GBUF + ro, lane, GS2));
            }
#pragma unroll
            for (int mt = 0; mt < 4; mt++)
#pragma unroll
                for (int np = 0; np < 2; np++)
#pragma unroll
                    for (int hh = 0; hh < 2; hh++){
                        int nt = np*2 + hh;
                        mma16816(c[mt][nt], ah[mt], bh[np][hh*2], bh[np][hh*2+1]);
                        mma16816(c[mt][nt], al[mt], bh[np][hh*2], bh[np][hh*2+1]);
                        mma16816(c[mt][nt], ah[mt], bl[np][hh*2], bl[np][hh*2+1]);
                    }
        }
        __syncthreads();
    }

    if (n0 == 0){
        // Q (scaled) and K: bf16 hi/lo register stores
#pragma unroll
        for (int mt = 0; mt < 4; mt++){
            int row = m0 + wm*64 + mt*16 + (lane >> 2);
#pragma unroll
            for (int nt = 0; nt < 4; nt++){
                int cg = wn*32 + nt*8 + ((lane & 3) << 1);
                bool isQ = (cg < 64);
                float sc = isQ ? SCALE_Q : 1.f;
                int col = isQ ? cg : cg - 64;
#pragma unroll
                for (int hh = 0; hh < 2; hh++){
                    int r = row + hh*8;
                    float v0 = c[mt][nt][hh*2]   * sc;
                    float v1 = c[mt][nt][hh*2+1] * sc;
                    u16 h0,l0,h1,l1; split2(v0,h0,l0); split2(v1,h1,l1);
                    u32 ph = (u32)h0 | ((u32)h1 << 16);
                    u32 pl = (u32)l0 | ((u32)l1 << 16);
                    size_t off = ((size_t)r*DH + col)*2;
                    if (isQ){
                        *reinterpret_cast<u32*>((char*)g_Qh + off) = ph;
                        *reinterpret_cast<u32*>((char*)g_Ql + off) = pl;
                    } else {
                        *reinterpret_cast<u32*>((char*)g_Kh + off) = ph;
                        *reinterpret_cast<u32*>((char*)g_Kl + off) = pl;
                    }
                }
            }
        }
    } else {
        // V: bounce through smem fp32, store [feat][tok] fp16 single
        __syncthreads();
#pragma unroll
        for (int mt = 0; mt < 4; mt++){
            int rl = wm*64 + mt*16 + (lane >> 2);
#pragma unroll
            for (int nt = 0; nt < 4; nt++){
                int cl = wn*32 + nt*8 + ((lane & 3) << 1);
                *reinterpret_cast<float2*>(&smemT[rl*132 + cl]) =
                    make_float2(c[mt][nt][0], c[mt][nt][1]);
                *reinterpret_cast<float2*>(&smemT[(rl+8)*132 + cl]) =
                    make_float2(c[mt][nt][2], c[mt][nt][3]);
            }
        }
        __syncthreads();
        const int b = m0 >> 11, t0 = m0 & 2047;
#pragma unroll
        for (int fi = 0; fi < 16; fi++){
            int fl = w*16 + fi;
            int gf = (n0 - 128) + fl;
            u32 p0 = packhf(smemT[(lane*4+0)*132 + fl], smemT[(lane*4+1)*132 + fl]);
            u32 p1 = packhf(smemT[(lane*4+2)*132 + fl], smemT[(lane*4+3)*132 + fl]);
            size_t off = ((size_t)(b*COUT + gf)*SEQ + t0 + lane*4)*2;
            *reinterpret_cast<uint2*>((char*)g_Vt + off) = make_uint2(p0, p1);
        }
    }
}

// ---------------------------------------------------------------------------
// k_qk: S = QK^T (bf16x3) + exp2 -> P (fp16 single) to global, chunk row sums.
// 2 CTAs/SM.
// ---------------------------------------------------------------------------
#define QK_QH 0
#define QK_QL 18432
#define QK_ST 36864
#define QKST  18432
#define QK_SMEM (QK_ST + 2*QKST)   // 73728

__global__ __launch_bounds__(256, 2) void k_qk(){
    extern __shared__ unsigned char smem[];
    const u32 sb = smem_u32(smem);
    const int tid = threadIdx.x, lane = tid & 31, w = tid >> 5;

    // decode (b, qt, chunk); heavy chunks first
    int idx = blockIdx.x;
    const int b = idx / 40;
    int rem = 39 - idx % 40;
    int qt = 0;
    while (rem >= (qt/4 + 1)){ rem -= qt/4 + 1; qt++; }
    const int chunk = rem;
    const int q0 = qt * 128;
    const int nkt = 2*qt + 2;
    const int ktA = chunk * 8;
    const int ktB = (ktA + 8 < nkt) ? ktA + 8 : nkt;

    auto issue = [&](int kt, int stg){
        const int k0 = kt * 64;
        const u32 SB = sb + QK_ST + (u32)stg * QKST;
#pragma unroll
        for (int it = 0; it < 2; it++){
            int i2 = tid + it*256, r = i2 >> 3, cc = i2 & 7;
            size_t gk = ((size_t)(b*SEQ + k0 + r)*DH)*2 + cc*16;
            u32 so = (u32)(r*GS + cc*16);
            cpa16(SB +    0 + so, (const char*)g_Kh + gk);
            cpa16(SB + 9216 + so, (const char*)g_Kl + gk);
        }
        cp_commit();
    };

    issue(ktA, ktA & 1);

#pragma unroll
    for (int it = 0; it < 4; it++){
        int i2 = tid + it*256, r = i2 >> 3, cc = i2 & 7;
        size_t gq = ((size_t)(b*SEQ + q0 + r)*DH)*2 + cc*16;
        u32 so = (u32)(r*GS + cc*16);
        *reinterpret_cast<uint4*>(smem + QK_QH + so) = *reinterpret_cast<const uint4*>((const char*)g_Qh + gq);
        *reinterpret_cast<uint4*>(smem + QK_QL + so) = *reinterpret_cast<const uint4*>((const char*)g_Ql + gq);
    }
    __syncthreads();

    u32 qh[4][4], ql[4][4];
#pragma unroll
    for (int kc = 0; kc < 4; kc++){
        u32 ro = (u32)((w*16) * GS + kc*32);
        ldm4(qh[kc], addrA(sb + QK_QH + ro, lane, GS));
        ldm4(ql[kc], addrA(sb + QK_QL + ro, lane, GS));
    }

    float l0 = 0.f, l1 = 0.f;
    const int row0 = q0 + w*16 + (lane >> 2);
    const int row1 = row0 + 8;
    const size_t pr0 = (size_t)(b*SEQ + row0) * SEQ;
    const size_t pr1 = (size_t)(b*SEQ + row1) * SEQ;

    for (int kt = ktA; kt < ktB; kt++){
        const int k0 = kt * 64;
        if (kt + 1 < ktB){ issue(kt + 1, (kt + 1) & 1); cp_wait1(); }
        else             { cp_wait0(); }
        __syncthreads();
        const u32 SB = sb + QK_ST + (u32)(kt & 1) * QKST;

        float s[8][4];
#pragma unroll
        for (int nt = 0; nt < 8; nt++)
#pragma unroll
            for (int r = 0; r < 4; r++) s[nt][r] = 0.f;

#pragma unroll
        for (int kc = 0; kc < 4; kc++){
#pragma unroll
            for (int np = 0; np < 4; np++){
                u32 ro = (u32)((np*16) * GS + kc*32);
                u32 kh[4], kl[4];
                ldm4(kh, addrB(SB +    0 + ro, lane, GS));
                ldm4(kl, addrB(SB + 9216 + ro, lane, GS));
#pragma unroll
                for (int hh = 0; hh < 2; hh++){
                    int nt = np*2 + hh;
                    mma16816(s[nt], qh[kc], kh[hh*2], kh[hh*2+1]);
                    mma16816(s[nt], ql[kc], kh[hh*2], kh[hh*2+1]);
                    mma16816(s[nt], qh[kc], kl[hh*2], kl[hh*2+1]);
                }
            }
        }

        // exp2 (+mask on diagonal tiles), store P fp16
        float pv[8][4];
        if (kt < nkt - 2){
#pragma unroll
            for (int nt = 0; nt < 8; nt++){
                pv[nt][0] = exp2f(s[nt][0]); pv[nt][1] = exp2f(s[nt][1]);
                pv[nt][2] = exp2f(s[nt][2]); pv[nt][3] = exp2f(s[nt][3]);
                l0 += pv[nt][0] + pv[nt][1];
                l1 += pv[nt][2] + pv[nt][3];
            }
        } else {
#pragma unroll
            for (int nt = 0; nt < 8; nt++){
                int col = k0 + nt*8 + ((lane & 3) << 1);
                pv[nt][0] = (col     <= row0) ? exp2f(s[nt][0]) : 0.f;
                pv[nt][1] = (col + 1 <= row0) ? exp2f(s[nt][1]) : 0.f;
                pv[nt][2] = (col     <= row1) ? exp2f(s[nt][2]) : 0.f;
                pv[nt][3] = (col + 1 <= row1) ? exp2f(s[nt][3]) : 0.f;
                l0 += pv[nt][0] + pv[nt][1];
                l1 += pv[nt][2] + pv[nt][3];
            }
        }
#pragma unroll
        for (int nt = 0; nt < 8; nt++){
            int col = k0 + nt*8 + ((lane & 3) << 1);
            u32 p0 = packhf(pv[nt][0], pv[nt][1]);
            u32 p1 = packhf(pv[nt][2], pv[nt][3]);
            *reinterpret_cast<u32*>((char*)g_Ph + (pr0 + col)*2) = p0;
            *reinterpret_cast<u32*>((char*)g_Ph + (pr1 + col)*2) = p1;
        }
        __syncthreads();
    }

    l0 += __shfl_xor_sync(0xffffffffu, l0, 1);
    l0 += __shfl_xor_sync(0xffffffffu, l0, 2);
    l1 += __shfl_xor_sync(0xffffffffu, l1, 1);
    l1 += __shfl_xor_sync(0xffffffffu, l1, 2);
    if ((lane & 3) == 0){
        g_lp[(size_t)(b*SEQ + row0)*4 + chunk] = l0;
        g_lp[(size_t)(b*SEQ + row1)*4 + chunk] = l1;
    }
}

// ---------------------------------------------------------------------------
// k_pv: O = P V^T (fp16) — pure GEMM, 2-stage cp.async, 2 CTAs/SM.
// Warp grid 4(m)x2(n): warp tile 32 q-rows x 64 feats.
// stage (36864): Ph@0 Vt@18432
// ---------------------------------------------------------------------------
#define PVST 36864
#define PV_SMEM (2*PVST)   // 73728

__global__ __launch_bounds__(256, 2) void k_pv(float* __restrict__ out){
    extern __shared__ unsigned char smem[];
    const u32 sb = smem_u32(smem);
    const int tid = threadIdx.x, lane = tid & 31, w = tid >> 5;
    const int wm = w >> 1, wn = w & 1;

    const int bi = blockIdx.x;
    const int qt = 15 - (bi >> 5);
    const int sub = bi & 31;
    const int b  = sub >> 2;
    const int h0 = (sub & 3) * 128;
    const int q0 = qt * 128;
    const int nkt = 2*qt + 2;

    auto issue = [&](int kt, int stg){
        const int k0 = kt * 64;
        const u32 SB = sb + (u32)stg * PVST;
#pragma unroll
        for (int it = 0; it < 4; it++){
            int i2 = tid + it*256, r = i2 >> 3, cc = i2 & 7;
            size_t gp = ((size_t)(b*SEQ + q0 + r)*SEQ + k0)*2 + cc*16;
            u32 so = (u32)(r*GS + cc*16);
            cpa16(SB + so, (const char*)g_Ph + gp);
        }
#pragma unroll
        for (int it = 0; it < 4; it++){
            int i2 = tid + it*256, r = i2 >> 3, cc = i2 & 7;
            size_t gv = ((size_t)(b*COUT + h0 + r)*SEQ + k0)*2 + cc*16;
            u32 so = (u32)(r*GS + cc*16);
            cpa16(SB + 18432 + so, (const char*)g_Vt + gv);
        }
        cp_commit();
    };

    issue(0, 0);

    float o[2][8][4];
#pragma unroll
    for (int mt = 0; mt < 2; mt++)
#pragma unroll
        for (int nt = 0; nt < 8; nt++)
#pragma unroll
            for (int r = 0; r < 4; r++) o[mt][nt][r] = 0.f;

    for (int kt = 0; kt < nkt; kt++){
        if (kt + 1 < nkt){ issue(kt + 1, (kt + 1) & 1); cp_wait1(); }
        else             { cp_wait0(); }
        __syncthreads();
        const u32 SB = sb + (u32)(kt & 1) * PVST;

#pragma unroll
        for (int kc = 0; kc < 4; kc++){
            u32 p0[4], p1[4];
            ldm4(p0, addrA(SB + (u32)((wm*32     ) * GS + kc*32), lane, GS));
            ldm4(p1, addrA(SB + (u32)((wm*32 + 16) * GS + kc*32), lane, GS));
#pragma unroll
            for (int np = 0; np < 4; np++){
                u32 ro = (u32)((wn*64 + np*16) * GS + kc*32);
                u32 v[4];
                ldm4(v, addrB(SB + 18432 + ro, lane, GS));
                mma16816h(o[0][np*2],   p0, v[0], v[1]);
                mma16816h(o[0][np*2+1], p0, v[2], v[3]);
                mma16816h(o[1][np*2],   p1, v[0], v[1]);
                mma16816h(o[1][np*2+1], p1, v[2], v[3]);
            }
        }
        __syncthreads();
    }

    const int nch = qt/4 + 1;
#pragma unroll
    for (int mt = 0; mt < 2; mt++){
        const int row0 = q0 + wm*32 + mt*16 + (lane >> 2);
        const int row1 = row0 + 8;
        float L0 = 0.f, L1 = 0.f;
        for (int c2 = 0; c2 < nch; c2++){
            L0 += g_lp[(size_t)(b*SEQ + row0)*4 + c2];
            L1 += g_lp[(size_t)(b*SEQ + row1)*4 + c2];
        }
        const float inv0 = 1.f / L0, inv1 = 1.f / L1;
        const size_t ob0 = (size_t)(b*SEQ + row0)*COUT + h0 + wn*64;
        const size_t ob1 = (size_t)(b*SEQ + row1)*COUT + h0 + wn*64;
#pragma unroll
        for (int nt = 0; nt < 8; nt++){
            int cg = nt*8 + ((lane & 3) << 1);
            *reinterpret_cast<float2*>(&out[ob0 + cg]) =
                make_float2(o[mt][nt][0]*inv0, o[mt][nt][1]*inv0);
            *reinterpret_cast<float2*>(&out[ob1 + cg]) =
                make_float2(o[mt][nt][2]*inv1, o[mt][nt][3]*inv1);
        }
    }
}

// ---------------------------------------------------------------------------
extern "C" void kernel_launch(void* const* d_in, const int* in_sizes, int n_in,
                              void* d_out, int out_size)
{
    const float* x  = (const float*)d_in[0];
    const float* Wq = (const float*)d_in[1];
    const float* Wk = (const float*)d_in[2];
    const float* Wv = (const float*)d_in[3];
    float* out = (float*)d_out;

    k_split_x<<<(MROWS*CIN/4)/256, 256>>>(x);
    k_split_w<<<(NTOT*CIN)/256, 256>>>(Wq, Wk, Wv);

    cudaFuncSetAttribute(k_gemm, cudaFuncAttributeMaxDynamicSharedMemorySize, G_SMEM);
    k_gemm<<<dim3(128, 5), 256, G_SMEM>>>();

    cudaFuncSetAttribute(k_qk, cudaFuncAttributeMaxDynamicSharedMemorySize, QK_SMEM);
    k_qk<<<320, 256, QK_SMEM>>>();

    cudaFuncSetAttribute(k_pv, cudaFuncAttributeMaxDynamicSharedMemorySize, PV_SMEM);
    k_pv<<<512, 256, PV_SMEM>>>(out);
}

// round 15
// speedup vs baseline: 5.6231x; 1.0591x over previous
#include <cuda_runtime.h>
#include <cuda_bf16.h>
#include <cuda_fp16.h>
#include <cstdint>

#define BATCH 8
#define SEQ   2048
#define CIN   512
#define DH    64
#define COUT  512
#define MROWS (BATCH*SEQ)   // 16384
#define NTOT  640
#define SCALE_Q 0.18033688011112042f   // (1/8) * log2(e)

typedef unsigned short u16;
typedef uint32_t u32;
typedef uint64_t u64;

// ---- scratch ----
__device__ __align__(16) u16 g_Xh[(size_t)MROWS*CIN];        // bf16
__device__ __align__(16) u16 g_Xl[(size_t)MROWS*CIN];
__device__ __align__(16) u16 g_Wth[(size_t)NTOT*CIN];
__device__ __align__(16) u16 g_Wtl[(size_t)NTOT*CIN];
__device__ __align__(16) u16 g_Q[(size_t)MROWS*DH];          // fp16 single
__device__ __align__(16) u16 g_K[(size_t)MROWS*DH];          // fp16 single
__device__ __align__(16) u16 g_Vt[(size_t)BATCH*COUT*SEQ];   // fp16 single [b][feat][token]
__device__ __align__(16) u16 g_Ph[(size_t)MROWS*SEQ];        // P numerators, fp16 single
__device__ float g_lp[(size_t)MROWS*4];                      // per-chunk row sums

// ---- helpers ----
__device__ __forceinline__ u32 smem_u32(const void* p){
    u32 a; asm("{ .reg .u64 t; cvta.to.shared.u64 t, %1; cvt.u32.u64 %0, t; }" : "=r"(a) : "l"(p));
    return a;
}
__device__ __forceinline__ void mma16816(float* c, const u32* a, u32 b0, u32 b1){
    asm volatile("mma.sync.aligned.m16n8k16.row.col.f32.bf16.bf16.f32 "
        "{%0,%1,%2,%3}, {%4,%5,%6,%7}, {%8,%9}, {%0,%1,%2,%3};"
        : "+f"(c[0]), "+f"(c[1]), "+f"(c[2]), "+f"(c[3])
        : "r"(a[0]), "r"(a[1]), "r"(a[2]), "r"(a[3]), "r"(b0), "r"(b1));
}
__device__ __forceinline__ void mma16816h(float* c, const u32* a, u32 b0, u32 b1){
    asm volatile("mma.sync.aligned.m16n8k16.row.col.f32.f16.f16.f32 "
        "{%0,%1,%2,%3}, {%4,%5,%6,%7}, {%8,%9}, {%0,%1,%2,%3};"
        : "+f"(c[0]), "+f"(c[1]), "+f"(c[2]), "+f"(c[3])
        : "r"(a[0]), "r"(a[1]), "r"(a[2]), "r"(a[3]), "r"(b0), "r"(b1));
}
__device__ __forceinline__ void ldm4(u32* r, u32 addr){
    asm volatile("ldmatrix.sync.aligned.m8n8.x4.shared.b16 {%0,%1,%2,%3}, [%4];"
        : "=r"(r[0]), "=r"(r[1]), "=r"(r[2]), "=r"(r[3]) : "r"(addr));
}
__device__ __forceinline__ u32 packhf(float lo, float hi){
    u32 d; asm("cvt.rn.f16x2.f32 %0, %1, %2;" : "=r"(d) : "f"(hi), "f"(lo)); return d;
}
__device__ __forceinline__ u16 f2bf(float x){ return __bfloat16_as_ushort(__float2bfloat16(x)); }
__device__ __forceinline__ float bf2f(u16 u){ return __bfloat162float(__ushort_as_bfloat16(u)); }
__device__ __forceinline__ void split2(float x, u16& h, u16& l){
    h = f2bf(x); l = f2bf(x - bf2f(h));
}

__device__ __forceinline__ void cpa16(u32 dst, const void* src){
    asm volatile("cp.async.cg.shared.global [%0], [%1], 16;" :: "r"(dst), "l"(src));
}
__device__ __forceinline__ void cp_commit(){ asm volatile("cp.async.commit_group;" ::: "memory"); }
__device__ __forceinline__ void cp_wait1(){ asm volatile("cp.async.wait_group 1;" ::: "memory"); }
__device__ __forceinline__ void cp_wait0(){ asm volatile("cp.async.wait_group 0;" ::: "memory"); }

// A-operand ldmatrix address (row-major 16x16 tile, row stride S bytes)
__device__ __forceinline__ u32 addrA(u32 base, int lane, int S){
    return base + (u32)((lane & 15) * S + (lane >> 4) * 16);
}
// B-operand ldmatrix address from B^T rows ([n][k] row-major, stride S bytes)
__device__ __forceinline__ u32 addrB(u32 base, int lane, int S){
    int n = ((lane >> 4) << 3) | (lane & 7);
    return base + (u32)(n * S + ((lane >> 3) & 1) * 16);
}

// ---------------------------------------------------------------------------
__global__ __launch_bounds__(256) void k_split_x(const float* __restrict__ X){
    size_t i = (size_t)blockIdx.x * 256 + threadIdx.x;
    float4 v = reinterpret_cast<const float4*>(X)[i];
    u16 h[4], l[4];
    split2(v.x, h[0], l[0]); split2(v.y, h[1], l[1]);
    split2(v.z, h[2], l[2]); split2(v.w, h[3], l[3]);
    uint2 ph, pl;
    ph.x = (u32)h[0] | ((u32)h[1] << 16); ph.y = (u32)h[2] | ((u32)h[3] << 16);
    pl.x = (u32)l[0] | ((u32)l[1] << 16); pl.y = (u32)l[2] | ((u32)l[3] << 16);
    reinterpret_cast<uint2*>(g_Xh)[i] = ph;
    reinterpret_cast<uint2*>(g_Xl)[i] = pl;
}

__global__ __launch_bounds__(256) void k_split_w(const float* __restrict__ Wq,
                                                 const float* __restrict__ Wk,
                                                 const float* __restrict__ Wv){
    int idx = blockIdx.x * 256 + threadIdx.x;
    int n = idx % NTOT, k = idx / NTOT;
    float v;
    if (n < 64)       v = Wq[k*64 + n];
    else if (n < 128) v = Wk[k*64 + (n-64)];
    else              v = Wv[k*512 + (n-128)];
    u16 h, l; split2(v, h, l);
    g_Wth[(size_t)n*CIN + k] = h;
    g_Wtl[(size_t)n*CIN + k] = l;
}

// ---------------------------------------------------------------------------
// projection GEMM (bf16x3), K-step 32, 2-stage cp.async, 2 CTAs/SM.
// stage (40960): Ah@0 Al@10240 Bh@20480 Bl@30720 ; rows stride 80B
// ---------------------------------------------------------------------------
#define GS  144       // stride for k_qk / k_pv tiles (64 tok * 2B + pad)
#define GS2 80        // stride for k_gemm K32 tiles (32 bf16 + 16B pad)
#define GBUF 10240
#define GST 40960
#define G_SMEM (2*GST)   // 81920

__global__ __launch_bounds__(256, 2) void k_gemm(){
    extern __shared__ unsigned char smem[];
    const u32 sb = smem_u32(smem);
    float* smemT = reinterpret_cast<float*>(smem);
    const int tid = threadIdx.x, lane = tid & 31, w = tid >> 5;
    const int wm = w >> 2, wn = w & 3;
    const int m0 = blockIdx.x * 128, n0 = blockIdx.y * 128;

    float c[4][4][4];
#pragma unroll
    for (int i = 0; i < 4; i++)
#pragma unroll
        for (int j = 0; j < 4; j++)
#pragma unroll
            for (int r = 0; r < 4; r++) c[i][j][r] = 0.f;

    auto issue = [&](int s, int stg){
        const u32 SB = sb + (u32)stg * GST;
#pragma unroll
        for (int it = 0; it < 2; it++){
            int i2 = tid + it*256;          // 0..511
            int r  = i2 >> 2, cc = i2 & 3;  // row, 16B chunk
            size_t ga = ((size_t)(m0 + r)*CIN + s*32)*2 + cc*16;
            size_t gb = ((size_t)(n0 + r)*CIN + s*32)*2 + cc*16;
            u32 so = (u32)(r*GS2 + cc*16);
            cpa16(SB +       0 + so, (const char*)g_Xh  + ga);
            cpa16(SB +   GBUF + so, (const char*)g_Xl  + ga);
            cpa16(SB + 2*GBUF + so, (const char*)g_Wth + gb);
            cpa16(SB + 3*GBUF + so, (const char*)g_Wtl + gb);
        }
        cp_commit();
    };

    issue(0, 0);
    for (int s = 0; s < 16; s++){
        if (s + 1 < 16){ issue(s + 1, (s + 1) & 1); cp_wait1(); }
        else           { cp_wait0(); }
        __syncthreads();
        const u32 SB = sb + (u32)(s & 1) * GST;

#pragma unroll
        for (int kc = 0; kc < 2; kc++){
            u32 ah[4][4], al[4][4];
#pragma unroll
            for (int mt = 0; mt < 4; mt++){
                u32 ro = (u32)((wm*64 + mt*16) * GS2 + kc*32);
                ldm4(ah[mt], addrA(SB +    0 + ro, lane, GS2));
                ldm4(al[mt], addrA(SB + GBUF + ro, lane, GS2));
            }
            u32 bh[2][4], bl[2][4];
#pragma unroll
            for (int np = 0; np < 2; np++){
                u32 ro = (u32)((wn*32 + np*16) * GS2 + kc*32);
                ldm4(bh[np], addrB(SB + 2*GBUF + ro, lane, GS2));
                ldm4(bl[np], addrB(SB + 3*GBUF + ro, lane, GS2));
            }
#pragma unroll
            for (int mt = 0; mt < 4; mt++)
#pragma unroll
                for (int np = 0; np < 2; np++)
#pragma unroll
                    for (int hh = 0; hh < 2; hh++){
                        int nt = np*2 + hh;
                        mma16816(c[mt][nt], ah[mt], bh[np][hh*2], bh[np][hh*2+1]);
                        mma16816(c[mt][nt], al[mt], bh[np][hh*2], bh[np][hh*2+1]);
                        mma16816(c[mt][nt], ah[mt], bl[np][hh*2], bl[np][hh*2+1]);
                    }
        }
        __syncthreads();
    }

    if (n0 == 0){
        // Q (scaled) and K: fp16-single packed stores
#pragma unroll
        for (int mt = 0; mt < 4; mt++){
            int row = m0 + wm*64 + mt*16 + (lane >> 2);
#pragma unroll
            for (int nt = 0; nt < 4; nt++){
                int cg = wn*32 + nt*8 + ((lane & 3) << 1);
                bool isQ = (cg < 64);
                float sc = isQ ? SCALE_Q : 1.f;
                int col = isQ ? cg : cg - 64;
#pragma unroll
                for (int hh = 0; hh < 2; hh++){
                    int r = row + hh*8;
                    u32 p = packhf(c[mt][nt][hh*2] * sc, c[mt][nt][hh*2+1] * sc);
                    size_t off = ((size_t)r*DH + col)*2;
                    if (isQ) *reinterpret_cast<u32*>((char*)g_Q + off) = p;
                    else     *reinterpret_cast<u32*>((char*)g_K + off) = p;
                }
            }
        }
    } else {
        // V: bounce through smem fp32, store [feat][tok] fp16 single
        __syncthreads();
#pragma unroll
        for (int mt = 0; mt < 4; mt++){
            int rl = wm*64 + mt*16 + (lane >> 2);
#pragma unroll
            for (int nt = 0; nt < 4; nt++){
                int cl = wn*32 + nt*8 + ((lane & 3) << 1);
                *reinterpret_cast<float2*>(&smemT[rl*132 + cl]) =
                    make_float2(c[mt][nt][0], c[mt][nt][1]);
                *reinterpret_cast<float2*>(&smemT[(rl+8)*132 + cl]) =
                    make_float2(c[mt][nt][2], c[mt][nt][3]);
            }
        }
        __syncthreads();
        const int b = m0 >> 11, t0 = m0 & 2047;
#pragma unroll
        for (int fi = 0; fi < 16; fi++){
            int fl = w*16 + fi;
            int gf = (n0 - 128) + fl;
            u32 p0 = packhf(smemT[(lane*4+0)*132 + fl], smemT[(lane*4+1)*132 + fl]);
            u32 p1 = packhf(smemT[(lane*4+2)*132 + fl], smemT[(lane*4+3)*132 + fl]);
            size_t off = ((size_t)(b*COUT + gf)*SEQ + t0 + lane*4)*2;
            *reinterpret_cast<uint2*>((char*)g_Vt + off) = make_uint2(p0, p1);
        }
    }
}

// ---------------------------------------------------------------------------
// k_qk: S = QK^T (fp16 single) + exp2 -> P (fp16) to global, chunk row sums.
// 2 CTAs/SM. smem: Q@0 (18432) ; K stages @18432: 2 x 9216
// ---------------------------------------------------------------------------
#define QK_Q  0
#define QK_ST 18432
#define QKST  9216
#define QK_SMEM (QK_ST + 2*QKST)   // 36864

__global__ __launch_bounds__(256, 2) void k_qk(){
    extern __shared__ unsigned char smem[];
    const u32 sb = smem_u32(smem);
    const int tid = threadIdx.x, lane = tid & 31, w = tid >> 5;

    // decode (b, qt, chunk); heavy chunks first
    int idx = blockIdx.x;
    const int b = idx / 40;
    int rem = 39 - idx % 40;
    int qt = 0;
    while (rem >= (qt/4 + 1)){ rem -= qt/4 + 1; qt++; }
    const int chunk = rem;
    const int q0 = qt * 128;
    const int nkt = 2*qt + 2;
    const int ktA = chunk * 8;
    const int ktB = (ktA + 8 < nkt) ? ktA + 8 : nkt;

    auto issue = [&](int kt, int stg){
        const int k0 = kt * 64;
        const u32 SB = sb + QK_ST + (u32)stg * QKST;
#pragma unroll
        for (int it = 0; it < 2; it++){
            int i2 = tid + it*256, r = i2 >> 3, cc = i2 & 7;
            size_t gk = ((size_t)(b*SEQ + k0 + r)*DH)*2 + cc*16;
            u32 so = (u32)(r*GS + cc*16);
            cpa16(SB + so, (const char*)g_K + gk);
        }
        cp_commit();
    };

    issue(ktA, ktA & 1);

    // Q tile (plain loads, once)
#pragma unroll
    for (int it = 0; it < 4; it++){
        int i2 = tid + it*256, r = i2 >> 3, cc = i2 & 7;
        size_t gq = ((size_t)(b*SEQ + q0 + r)*DH)*2 + cc*16;
        u32 so = (u32)(r*GS + cc*16);
        *reinterpret_cast<uint4*>(smem + QK_Q + so) =
            *reinterpret_cast<const uint4*>((const char*)g_Q + gq);
    }
    __syncthreads();

    u32 qf[4][4];
#pragma unroll
    for (int kc = 0; kc < 4; kc++){
        u32 ro = (u32)((w*16) * GS + kc*32);
        ldm4(qf[kc], addrA(sb + QK_Q + ro, lane, GS));
    }

    float l0 = 0.f, l1 = 0.f;
    const int row0 = q0 + w*16 + (lane >> 2);
    const int row1 = row0 + 8;
    const size_t pr0 = (size_t)(b*SEQ + row0) * SEQ;
    const size_t pr1 = (size_t)(b*SEQ + row1) * SEQ;

    for (int kt = ktA; kt < ktB; kt++){
        const int k0 = kt * 64;
        if (kt + 1 < ktB){ issue(kt + 1, (kt + 1) & 1); cp_wait1(); }
        else             { cp_wait0(); }
        __syncthreads();
        const u32 SB = sb + QK_ST + (u32)(kt & 1) * QKST;

        float s[8][4];
#pragma unroll
        for (int nt = 0; nt < 8; nt++)
#pragma unroll
            for (int r = 0; r < 4; r++) s[nt][r] = 0.f;

#pragma unroll
        for (int kc = 0; kc < 4; kc++){
#pragma unroll
            for (int np = 0; np < 4; np++){
                u32 ro = (u32)((np*16) * GS + kc*32);
                u32 kk[4];
                ldm4(kk, addrB(SB + ro, lane, GS));
                mma16816h(s[np*2],   qf[kc], kk[0], kk[1]);
                mma16816h(s[np*2+1], qf[kc], kk[2], kk[3]);
            }
        }

        // exp2 (+mask on diagonal tiles), store P fp16
        float pv[8][4];
        if (kt < nkt - 2){
#pragma unroll
            for (int nt = 0; nt < 8; nt++){
                pv[nt][0] = exp2f(s[nt][0]); pv[nt][1] = exp2f(s[nt][1]);
                pv[nt][2] = exp2f(s[nt][2]); pv[nt][3] = exp2f(s[nt][3]);
                l0 += pv[nt][0] + pv[nt][1];
                l1 += pv[nt][2] + pv[nt][3];
            }
        } else {
#pragma unroll
            for (int nt = 0; nt < 8; nt++){
                int col = k0 + nt*8 + ((lane & 3) << 1);
                pv[nt][0] = (col     <= row0) ? exp2f(s[nt][0]) : 0.f;
                pv[nt][1] = (col + 1 <= row0) ? exp2f(s[nt][1]) : 0.f;
                pv[nt][2] = (col     <= row1) ? exp2f(s[nt][2]) : 0.f;
                pv[nt][3] = (col + 1 <= row1) ? exp2f(s[nt][3]) : 0.f;
                l0 += pv[nt][0] + pv[nt][1];
                l1 += pv[nt][2] + pv[nt][3];
            }
        }
#pragma unroll
        for (int nt = 0; nt < 8; nt++){
            int col = k0 + nt*8 + ((lane & 3) << 1);
            u32 p0 = packhf(pv[nt][0], pv[nt][1]);
            u32 p1 = packhf(pv[nt][2], pv[nt][3]);
            *reinterpret_cast<u32*>((char*)g_Ph + (pr0 + col)*2) = p0;
            *reinterpret_cast<u32*>((char*)g_Ph + (pr1 + col)*2) = p1;
        }
        __syncthreads();
    }

    l0 += __shfl_xor_sync(0xffffffffu, l0, 1);
    l0 += __shfl_xor_sync(0xffffffffu, l0, 2);
    l1 += __shfl_xor_sync(0xffffffffu, l1, 1);
    l1 += __shfl_xor_sync(0xffffffffu, l1, 2);
    if ((lane & 3) == 0){
        g_lp[(size_t)(b*SEQ + row0)*4 + chunk] = l0;
        g_lp[(size_t)(b*SEQ + row1)*4 + chunk] = l1;
    }
}

// ---------------------------------------------------------------------------
// k_pv: O = P V^T (fp16) — pure GEMM, 2-stage cp.async, 2 CTAs/SM.
// Warp grid 4(m)x2(n): warp tile 32 q-rows x 64 feats.
// stage (36864): Ph@0 Vt@18432
// ---------------------------------------------------------------------------
#define PVST 36864
#define PV_SMEM (2*PVST)   // 73728

__global__ __launch_bounds__(256, 2) void k_pv(float* __restrict__ out){
    extern __shared__ unsigned char smem[];
    const u32 sb = smem_u32(smem);
    const int tid = threadIdx.x, lane = tid & 31, w = tid >> 5;
    const int wm = w >> 1, wn = w & 1;

    const int bi = blockIdx.x;
    const int qt = 15 - (bi >> 5);
    const int sub = bi & 31;
    const int b  = sub >> 2;
    const int h0 = (sub & 3) * 128;
    const int q0 = qt * 128;
    const int nkt = 2*qt + 2;

    auto issue = [&](int kt, int stg){
        const int k0 = kt * 64;
        const u32 SB = sb + (u32)stg * PVST;
#pragma unroll
        for (int it = 0; it < 4; it++){
            int i2 = tid + it*256, r = i2 >> 3, cc = i2 & 7;
            size_t gp = ((size_t)(b*SEQ + q0 + r)*SEQ + k0)*2 + cc*16;
            u32 so = (u32)(r*GS + cc*16);
            cpa16(SB + so, (const char*)g_Ph + gp);
        }
#pragma unroll
        for (int it = 0; it < 4; it++){
            int i2 = tid + it*256, r = i2 >> 3, cc = i2 & 7;
            size_t gv = ((size_t)(b*COUT + h0 + r)*SEQ + k0)*2 + cc*16;
            u32 so = (u32)(r*GS + cc*16);
            cpa16(SB + 18432 + so, (const char*)g_Vt + gv);
        }
        cp_commit();
    };

    issue(0, 0);

    float o[2][8][4];
#pragma unroll
    for (int mt = 0; mt < 2; mt++)
#pragma unroll
        for (int nt = 0; nt < 8; nt++)
#pragma unroll
            for (int r = 0; r < 4; r++) o[mt][nt][r] = 0.f;

    for (int kt = 0; kt < nkt; kt++){
        if (kt + 1 < nkt){ issue(kt + 1, (kt + 1) & 1); cp_wait1(); }
        else             { cp_wait0(); }
        __syncthreads();
        const u32 SB = sb + (u32)(kt & 1) * PVST;

#pragma unroll
        for (int kc = 0; kc < 4; kc++){
            u32 p0[4], p1[4];
            ldm4(p0, addrA(SB + (u32)((wm*32     ) * GS + kc*32), lane, GS));
            ldm4(p1, addrA(SB + (u32)((wm*32 + 16) * GS + kc*32), lane, GS));
#pragma unroll
            for (int np = 0; np < 4; np++){
                u32 ro = (u32)((wn*64 + np*16) * GS + kc*32);
                u32 v[4];
                ldm4(v, addrB(SB + 18432 + ro, lane, GS));
                mma16816h(o[0][np*2],   p0, v[0], v[1]);
                mma16816h(o[0][np*2+1], p0, v[2], v[3]);
                mma16816h(o[1][np*2],   p1, v[0], v[1]);
                mma16816h(o[1][np*2+1], p1, v[2], v[3]);
            }
        }
        __syncthreads();
    }

    const int nch = qt/4 + 1;
#pragma unroll
    for (int mt = 0; mt < 2; mt++){
        const int row0 = q0 + wm*32 + mt*16 + (lane >> 2);
        const int row1 = row0 + 8;
        float L0 = 0.f, L1 = 0.f;
        for (int c2 = 0; c2 < nch; c2++){
            L0 += g_lp[(size_t)(b*SEQ + row0)*4 + c2];
            L1 += g_lp[(size_t)(b*SEQ + row1)*4 + c2];
        }
        const float inv0 = 1.f / L0, inv1 = 1.f / L1;
        const size_t ob0 = (size_t)(b*SEQ + row0)*COUT + h0 + wn*64;
        const size_t ob1 = (size_t)(b*SEQ + row1)*COUT + h0 + wn*64;
#pragma unroll
        for (int nt = 0; nt < 8; nt++){
            int cg = nt*8 + ((lane & 3) << 1);
            *reinterpret_cast<float2*>(&out[ob0 + cg]) =
                make_float2(o[mt][nt][0]*inv0, o[mt][nt][1]*inv0);
            *reinterpret_cast<float2*>(&out[ob1 + cg]) =
                make_float2(o[mt][nt][2]*inv1, o[mt][nt][3]*inv1);
        }
    }
}

// ---------------------------------------------------------------------------
extern "C" void kernel_launch(void* const* d_in, const int* in_sizes, int n_in,
                              void* d_out, int out_size)
{
    const float* x  = (const float*)d_in[0];
    const float* Wq = (const float*)d_in[1];
    const float* Wk = (const float*)d_in[2];
    const float* Wv = (const float*)d_in[3];
    float* out = (float*)d_out;

    k_split_x<<<(MROWS*CIN/4)/256, 256>>>(x);
    k_split_w<<<(NTOT*CIN)/256, 256>>>(Wq, Wk, Wv);

    cudaFuncSetAttribute(k_gemm, cudaFuncAttributeMaxDynamicSharedMemorySize, G_SMEM);
    k_gemm<<<dim3(128, 5), 256, G_SMEM>>>();

    cudaFuncSetAttribute(k_qk, cudaFuncAttributeMaxDynamicSharedMemorySize, QK_SMEM);
    k_qk<<<320, 256, QK_SMEM>>>();

    cudaFuncSetAttribute(k_pv, cudaFuncAttributeMaxDynamicSharedMemorySize, PV_SMEM);
    k_pv<<<512, 256, PV_SMEM>>>(out);
}